// round 1
// baseline (speedup 1.0000x reference)
#include <cuda_runtime.h>

#define DN 128
#define NN 20000
#define EE 640000
#define ETILE 64
#define CATP 272   // 264 used + pad, 16B-aligned rows
#define H1P 260    // 256 used + pad (bank spread)

// ---- scratch (static device globals: no runtime allocation) ----
__device__ float g_x[NN * DN];        // x = h @ lin_w^T + lin_b
__device__ float g_out[NN * DN];      // segment-sum accumulator
__device__ float g_w1T[264 * 256];    // att_w1 transposed [k][o], K padded to 264
__device__ float g_w2T[256 * 128];    // att_w2 transposed [k][o]
__device__ int g_e64;                 // 1 if edges buffer is int64, 0 if int32

__device__ __forceinline__ float sigm(float v) { return 1.0f / (1.0f + __expf(-v)); }
__device__ __forceinline__ float silu_(float v) { return v * sigm(v); }

// ---------------------------------------------------------------------------
// Prep: transpose att weights into [k][o] layout (coalesced GEMM staging),
// detect edges dtype (jax w/o x64 downcasts int64->int32 silently).
// ---------------------------------------------------------------------------
__global__ void k_prep(const float* __restrict__ w1, const float* __restrict__ w2,
                       const void* __restrict__ edges) {
    int idx = blockIdx.x * 256 + threadIdx.x;
    if (idx < 264 * 256) {
        int k = idx / 256, o = idx % 256;
        g_w1T[idx] = (k < 257) ? w1[o * 257 + k] : 0.0f;
    } else {
        int j = idx - 264 * 256;   // < 256*128 by grid construction
        int k = j / 128, o = j % 128;
        g_w2T[j] = w2[o * 256 + k];
    }
    if (idx == 0) {
        // int64 little-endian: high words of small nonneg ids are all zero.
        const int* e32 = (const int*)edges;
        int nz = 0;
        for (int i = 0; i < 16; i++) nz |= e32[2 * i + 1];
        g_e64 = (nz == 0) ? 1 : 0;
    }
}

__global__ void k_zero() {
    int i = blockIdx.x * 256 + threadIdx.x;
    if (i < NN * DN) g_out[i] = 0.0f;
}

// ---------------------------------------------------------------------------
// x = h @ lin_w^T + lin_b       (32 nodes per CTA, weights in smem)
// ---------------------------------------------------------------------------
__global__ __launch_bounds__(256, 1) void k_lin(const float* __restrict__ h,
                                                const float* __restrict__ w,
                                                const float* __restrict__ b) {
    extern __shared__ float sm[];
    float* wT = sm;               // [128][132]
    float* ins = sm + 128 * 132;  // [32][132]
    float* bs = ins + 32 * 132;   // [128]
    int tid = threadIdx.x, lane = tid & 31, warp = tid >> 5;
    int n0 = blockIdx.x * 32;

    for (int idx = tid; idx < 128 * 128; idx += 256) {
        int o = idx >> 7, k = idx & 127;
        wT[k * 132 + o] = w[idx];
    }
    if (tid < 128) bs[tid] = b[tid];
#pragma unroll
    for (int i = 0; i < 4; i++) {
        int nl = warp * 4 + i;
        float4 v = *(const float4*)&h[(size_t)(n0 + nl) * DN + lane * 4];
        *(float4*)&ins[nl * 132 + lane * 4] = v;
    }
    __syncthreads();

    float acc[4][4] = {};
    const float* inw = ins + warp * 4 * 132;
    for (int k = 0; k < 128; k++) {
        float a[4], wv[4];
#pragma unroll
        for (int i = 0; i < 4; i++) a[i] = inw[i * 132 + k];
#pragma unroll
        for (int j = 0; j < 4; j++) wv[j] = wT[k * 132 + lane + 32 * j];
#pragma unroll
        for (int i = 0; i < 4; i++)
#pragma unroll
            for (int j = 0; j < 4; j++) acc[i][j] += a[i] * wv[j];
    }
#pragma unroll
    for (int i = 0; i < 4; i++) {
        int nl = warp * 4 + i;
#pragma unroll
        for (int j = 0; j < 4; j++) {
            int o = lane + 32 * j;
            g_x[(size_t)(n0 + nl) * DN + o] = acc[i][j] + bs[o];
        }
    }
}

// ---------------------------------------------------------------------------
// Fused edge kernel: gather -> GEMM1(silu) -> GEMM2(silu) -> dot w3 ->
// sigmoid*mask -> atomic scatter-add of x_col*att into g_out.
// 64 edges/CTA, 256 threads, per-thread 8x8 / 8x4 register tiles.
// ---------------------------------------------------------------------------
__global__ __launch_bounds__(256, 1) void k_edge(
    const float* __restrict__ dist, const float* __restrict__ emask,
    const float* __restrict__ b1, const float* __restrict__ b2,
    const float* __restrict__ w3, const float* __restrict__ b3,
    const void* __restrict__ edges) {
    extern __shared__ float sm[];
    float* cat = sm;                       // [64][272], k: 0..127 x_row, 128..255 x_col, 256 d, 257..263 zero
    float* h1s = cat + ETILE * CATP;       // [64][260]
    float* wt = h1s + ETILE * H1P;         // [8][256] weight k-tile
    float* b1s = wt + 2048;                // 256
    float* b2s = b1s + 256;                // 128
    float* w3s = b2s + 128;                // 128
    float* ems = w3s + 128;                // 64
    int* rows = (int*)(ems + 64);          // 64
    int* cols = rows + 64;                 // 64

    int tid = threadIdx.x, lane = tid & 31, warp = tid >> 5;
    int e0 = blockIdx.x * ETILE;

    b1s[tid] = b1[tid];
    if (tid < 128) { b2s[tid] = b2[tid]; w3s[tid] = w3[tid]; }
    if (tid < 64) {
        int e = e0 + tid;
        if (g_e64) {
            const long long* e64 = (const long long*)edges;
            rows[tid] = (int)e64[e];
            cols[tid] = (int)e64[EE + e];
        } else {
            const int* e32 = (const int*)edges;
            rows[tid] = e32[e];
            cols[tid] = e32[EE + e];
        }
        float em = emask[e];
        ems[tid] = em;
        cat[tid * CATP + 256] = dist[e] * em;
#pragma unroll
        for (int p = 257; p < 264; p++) cat[tid * CATP + p] = 0.0f;
    }
    __syncthreads();

    // gather x_row / x_col (coalesced 512B per edge, L2-resident x)
#pragma unroll
    for (int i = 0; i < 8; i++) {
        int el = warp * 8 + i;
        const float* xr = &g_x[(size_t)rows[el] * DN];
        const float* xc = &g_x[(size_t)cols[el] * DN];
        *(float4*)&cat[el * CATP + lane * 4] = *(const float4*)&xr[lane * 4];
        *(float4*)&cat[el * CATP + 128 + lane * 4] = *(const float4*)&xc[lane * 4];
    }
    __syncthreads();

    // ---- GEMM1: [64e x 256o], K=264 (padded). out o = lane + 32j ----
    float acc[8][8] = {};
    {
        int t8 = tid * 8;
        float4 pa = *(const float4*)&g_w1T[t8];
        float4 pb = *(const float4*)&g_w1T[t8 + 4];
        const float* catw = cat + warp * 8 * CATP;
        for (int t = 0; t < 33; t++) {
            *(float4*)&wt[t8] = pa;
            *(float4*)&wt[t8 + 4] = pb;
            __syncthreads();
            if (t < 32) {  // register prefetch of next k-tile overlaps compute
                const float* src = &g_w1T[(t + 1) * 2048];
                pa = *(const float4*)&src[t8];
                pb = *(const float4*)&src[t8 + 4];
            }
#pragma unroll
            for (int kk = 0; kk < 8; kk++) {
                int k = t * 8 + kk;
                float a[8], wv[8];
#pragma unroll
                for (int i = 0; i < 8; i++) a[i] = catw[i * CATP + k];   // warp-uniform broadcast
#pragma unroll
                for (int j = 0; j < 8; j++) wv[j] = wt[kk * 256 + lane + 32 * j];  // conflict-free
#pragma unroll
                for (int i = 0; i < 8; i++)
#pragma unroll
                    for (int j = 0; j < 8; j++) acc[i][j] += a[i] * wv[j];
            }
            __syncthreads();
        }
    }
    // epilogue: bias + silu -> h1s (warp-private rows, no sync needed)
#pragma unroll
    for (int i = 0; i < 8; i++) {
        int el = warp * 8 + i;
#pragma unroll
        for (int j = 0; j < 8; j++) {
            int o = lane + 32 * j;
            h1s[el * H1P + o] = silu_(acc[i][j] + b1s[o]);
        }
    }

    // ---- GEMM2: [64e x 128o], K=256 ----
    float acc2[8][4] = {};
    {
        int t8 = tid * 8;
        float4 pa = make_float4(0.f, 0.f, 0.f, 0.f), pb = pa;
        if (tid < 128) {
            pa = *(const float4*)&g_w2T[t8];
            pb = *(const float4*)&g_w2T[t8 + 4];
        }
        const float* h1w = h1s + warp * 8 * H1P;
        for (int t = 0; t < 32; t++) {
            if (tid < 128) {
                *(float4*)&wt[t8] = pa;
                *(float4*)&wt[t8 + 4] = pb;
            }
            __syncthreads();
            if (tid < 128 && t < 31) {
                const float* src = &g_w2T[(t + 1) * 1024];
                pa = *(const float4*)&src[t8];
                pb = *(const float4*)&src[t8 + 4];
            }
#pragma unroll
            for (int kk = 0; kk < 8; kk++) {
                int k = t * 8 + kk;
                float a[8], wv[4];
#pragma unroll
                for (int i = 0; i < 8; i++) a[i] = h1w[i * H1P + k];
#pragma unroll
                for (int j = 0; j < 4; j++) wv[j] = wt[kk * 128 + lane + 32 * j];
#pragma unroll
                for (int i = 0; i < 8; i++)
#pragma unroll
                    for (int j = 0; j < 4; j++) acc2[i][j] += a[i] * wv[j];
            }
            __syncthreads();
        }
    }

    // ---- att = sigmoid(silu(h2) . w3 + b3) * mask ----
    float part[8];
#pragma unroll
    for (int i = 0; i < 8; i++) part[i] = 0.0f;
#pragma unroll
    for (int i = 0; i < 8; i++)
#pragma unroll
        for (int j = 0; j < 4; j++) {
            int o = lane + 32 * j;
            part[i] += silu_(acc2[i][j] + b2s[o]) * w3s[o];
        }
#pragma unroll
    for (int off = 16; off > 0; off >>= 1)
#pragma unroll
        for (int i = 0; i < 8; i++)
            part[i] += __shfl_xor_sync(0xffffffffu, part[i], off);

    float b3v = b3[0];
    float attv[8];
#pragma unroll
    for (int i = 0; i < 8; i++) attv[i] = sigm(part[i] + b3v) * ems[warp * 8 + i];

    // ---- scatter: g_out[row] += x_col * att ----
#pragma unroll
    for (int i = 0; i < 8; i++) {
        int el = warp * 8 + i;
        float a = attv[i];
        float* dst = &g_out[(size_t)rows[el] * DN + lane * 4];
        const float4 v = *(const float4*)&cat[el * CATP + 128 + lane * 4];
        atomicAdd(dst + 0, v.x * a);
        atomicAdd(dst + 1, v.y * a);
        atomicAdd(dst + 2, v.z * a);
        atomicAdd(dst + 3, v.w * a);
    }
}

// ---------------------------------------------------------------------------
// node_mlp + residual + final LN + silu.   32 nodes/CTA.
// ---------------------------------------------------------------------------
__global__ __launch_bounds__(256, 1) void k_node(
    const float* __restrict__ w1, const float* __restrict__ b1,
    const float* __restrict__ g1, const float* __restrict__ bb1,
    const float* __restrict__ w2, const float* __restrict__ b2,
    const float* __restrict__ g2, const float* __restrict__ bb2,
    float* __restrict__ out) {
    extern __shared__ float sm[];
    float* w1T = sm;              // [128][132]
    float* w2T = w1T + 16896;     // [128][132]
    float* ins = w2T + 16896;     // [32][132]
    float* mids = ins + 4224;     // [32][132]
    float* b1s = mids + 4224;     // 128
    float* b2s = b1s + 128;       // 128
    int tid = threadIdx.x, lane = tid & 31, warp = tid >> 5;
    int n0 = blockIdx.x * 32;

    for (int idx = tid; idx < 128 * 128; idx += 256) {
        int o = idx >> 7, k = idx & 127;
        w1T[k * 132 + o] = w1[idx];
        w2T[k * 132 + o] = w2[idx];
    }
    if (tid < 128) { b1s[tid] = b1[tid]; b2s[tid] = b2[tid]; }
#pragma unroll
    for (int i = 0; i < 4; i++) {
        int nl = warp * 4 + i;
        float4 v = *(const float4*)&g_out[(size_t)(n0 + nl) * DN + lane * 4];
        v.x *= 0.01f; v.y *= 0.01f; v.z *= 0.01f; v.w *= 0.01f;  // / NORM_FACTOR
        *(float4*)&ins[nl * 132 + lane * 4] = v;
    }
    __syncthreads();

    // GEMM1
    float acc[4][4] = {};
    {
        const float* inw = ins + warp * 4 * 132;
        for (int k = 0; k < 128; k++) {
            float a[4], wv[4];
#pragma unroll
            for (int i = 0; i < 4; i++) a[i] = inw[i * 132 + k];
#pragma unroll
            for (int j = 0; j < 4; j++) wv[j] = w1T[k * 132 + lane + 32 * j];
#pragma unroll
            for (int i = 0; i < 4; i++)
#pragma unroll
                for (int j = 0; j < 4; j++) acc[i][j] += a[i] * wv[j];
        }
    }
    // LN1 + silu
    float lg1[4], lb1[4];
#pragma unroll
    for (int j = 0; j < 4; j++) { int o = lane + 32 * j; lg1[j] = g1[o]; lb1[j] = bb1[o]; }
#pragma unroll
    for (int i = 0; i < 4; i++) {
        float v[4], s1 = 0.f, s2 = 0.f;
#pragma unroll
        for (int j = 0; j < 4; j++) {
            v[j] = acc[i][j] + b1s[lane + 32 * j];
            s1 += v[j]; s2 += v[j] * v[j];
        }
#pragma unroll
        for (int off = 16; off > 0; off >>= 1) {
            s1 += __shfl_xor_sync(0xffffffffu, s1, off);
            s2 += __shfl_xor_sync(0xffffffffu, s2, off);
        }
        float mean = s1 * (1.0f / 128.0f);
        float var = s2 * (1.0f / 128.0f) - mean * mean;
        float inv = rsqrtf(var + 1e-5f);
        int nl = warp * 4 + i;
#pragma unroll
        for (int j = 0; j < 4; j++) {
            float y = (v[j] - mean) * inv * lg1[j] + lb1[j];
            mids[nl * 132 + lane + 32 * j] = silu_(y);
        }
    }
    __syncthreads();

    // GEMM2
    float acc2[4][4] = {};
    {
        const float* mw = mids + warp * 4 * 132;
        for (int k = 0; k < 128; k++) {
            float a[4], wv[4];
#pragma unroll
            for (int i = 0; i < 4; i++) a[i] = mw[i * 132 + k];
#pragma unroll
            for (int j = 0; j < 4; j++) wv[j] = w2T[k * 132 + lane + 32 * j];
#pragma unroll
            for (int i = 0; i < 4; i++)
#pragma unroll
                for (int j = 0; j < 4; j++) acc2[i][j] += a[i] * wv[j];
        }
    }
    // + residual, LN2, silu, store
    float lg2[4], lb2[4];
#pragma unroll
    for (int j = 0; j < 4; j++) { int o = lane + 32 * j; lg2[j] = g2[o]; lb2[j] = bb2[o]; }
#pragma unroll
    for (int i = 0; i < 4; i++) {
        int nl = warp * 4 + i;
        float v[4], s1 = 0.f, s2 = 0.f;
#pragma unroll
        for (int j = 0; j < 4; j++) {
            int o = lane + 32 * j;
            v[j] = acc2[i][j] + b2s[o] + g_x[(size_t)(n0 + nl) * DN + o];
            s1 += v[j]; s2 += v[j] * v[j];
        }
#pragma unroll
        for (int off = 16; off > 0; off >>= 1) {
            s1 += __shfl_xor_sync(0xffffffffu, s1, off);
            s2 += __shfl_xor_sync(0xffffffffu, s2, off);
        }
        float mean = s1 * (1.0f / 128.0f);
        float var = s2 * (1.0f / 128.0f) - mean * mean;
        float inv = rsqrtf(var + 1e-5f);
#pragma unroll
        for (int j = 0; j < 4; j++) {
            int o = lane + 32 * j;
            float y = (v[j] - mean) * inv * lg2[j] + lb2[j];
            out[(size_t)(n0 + nl) * DN + o] = silu_(y);
        }
    }
}

// ---------------------------------------------------------------------------
extern "C" void kernel_launch(void* const* d_in, const int* in_sizes, int n_in,
                              void* d_out, int out_size) {
    const float* h = (const float*)d_in[0];
    const float* distances = (const float*)d_in[1];
    // d_in[2] = node_mask (unused by reference)
    const float* edge_mask = (const float*)d_in[3];
    const float* lin_w = (const float*)d_in[4];
    const float* lin_b = (const float*)d_in[5];
    const float* att_w1 = (const float*)d_in[6];
    const float* att_b1 = (const float*)d_in[7];
    const float* att_w2 = (const float*)d_in[8];
    const float* att_b2 = (const float*)d_in[9];
    const float* att_w3 = (const float*)d_in[10];
    const float* att_b3 = (const float*)d_in[11];
    const float* nm_w1 = (const float*)d_in[12];
    const float* nm_b1 = (const float*)d_in[13];
    const float* nm_ln_g = (const float*)d_in[14];
    const float* nm_ln_b = (const float*)d_in[15];
    const float* nm_w2 = (const float*)d_in[16];
    const float* nm_b2 = (const float*)d_in[17];
    const float* ln_g = (const float*)d_in[18];
    const float* ln_b = (const float*)d_in[19];
    const void* edges = d_in[20];

    cudaFuncSetAttribute(k_lin, cudaFuncAttributeMaxDynamicSharedMemorySize, 84992);
    cudaFuncSetAttribute(k_edge, cudaFuncAttributeMaxDynamicSharedMemorySize, 147200);
    cudaFuncSetAttribute(k_node, cudaFuncAttributeMaxDynamicSharedMemorySize, 169984);

    k_prep<<<392, 256>>>(att_w1, att_w2, edges);
    k_zero<<<(NN * DN + 255) / 256, 256>>>();
    k_lin<<<625, 256, 84992>>>(h, lin_w, lin_b);
    k_edge<<<EE / ETILE, 256, 147200>>>(distances, edge_mask, att_b1, att_b2,
                                        att_w3, att_b3, edges);
    k_node<<<625, 256, 169984>>>(nm_w1, nm_b1, nm_ln_g, nm_ln_b,
                                 nm_w2, nm_b2, ln_g, ln_b, (float*)d_out);
}

// round 2
// speedup vs baseline: 1.1574x; 1.1574x over previous
#include <cuda_runtime.h>

#define DN 128
#define NN 20000
#define EE 640000
#define ETILE 64
#define CATP 272   // 264 used + pad, 16B-aligned rows
#define H1P 260    // 256 used + pad (bank spread)

// ---- scratch (static device globals: no runtime allocation) ----
__device__ float g_x[NN * DN];        // x = h @ lin_w^T + lin_b
__device__ float g_out[NN * DN];      // segment-sum accumulator
__device__ float g_w1T[264 * 256];    // att_w1 transposed [k][o], K padded to 264
__device__ float g_w2T[256 * 128];    // att_w2 transposed [k][o]
__device__ int g_e64;                 // 1 if edges buffer is int64, 0 if int32

__device__ __forceinline__ float sigm(float v) { return 1.0f / (1.0f + __expf(-v)); }
__device__ __forceinline__ float silu_(float v) { return v * sigm(v); }

// ---- packed fp32x2 helpers (fma.rn.f32x2 — FFMA2, 2x fp32 per instruction) ----
typedef unsigned long long u64t;
__device__ __forceinline__ u64t dup2(float a) {
    u64t r; asm("mov.b64 %0, {%1, %1};" : "=l"(r) : "f"(a)); return r;
}
__device__ __forceinline__ u64t fma2(u64t a, u64t b, u64t c) {
    u64t d; asm("fma.rn.f32x2 %0, %1, %2, %3;" : "=l"(d) : "l"(a), "l"(b), "l"(c)); return d;
}
__device__ __forceinline__ void unpack2(u64t v, float& lo, float& hi) {
    asm("mov.b64 {%0, %1}, %2;" : "=f"(lo), "=f"(hi) : "l"(v));
}

// ---------------------------------------------------------------------------
// Prep: transpose att weights into [k][o] layout, detect edges dtype.
// ---------------------------------------------------------------------------
__global__ void k_prep(const float* __restrict__ w1, const float* __restrict__ w2,
                       const void* __restrict__ edges) {
    int idx = blockIdx.x * 256 + threadIdx.x;
    if (idx < 264 * 256) {
        int k = idx / 256, o = idx % 256;
        g_w1T[idx] = (k < 257) ? w1[o * 257 + k] : 0.0f;
    } else {
        int j = idx - 264 * 256;   // < 256*128 by grid construction
        int k = j / 128, o = j % 128;
        g_w2T[j] = w2[o * 256 + k];
    }
    if (idx == 0) {
        const int* e32 = (const int*)edges;
        int nz = 0;
        for (int i = 0; i < 16; i++) nz |= e32[2 * i + 1];
        g_e64 = (nz == 0) ? 1 : 0;
    }
}

__global__ void k_zero() {
    int i = blockIdx.x * 256 + threadIdx.x;
    if (i < NN * DN) g_out[i] = 0.0f;
}

// ---------------------------------------------------------------------------
// x = h @ lin_w^T + lin_b       (32 nodes per CTA, weights in smem)
// ---------------------------------------------------------------------------
__global__ __launch_bounds__(256, 1) void k_lin(const float* __restrict__ h,
                                                const float* __restrict__ w,
                                                const float* __restrict__ b) {
    extern __shared__ float sm[];
    float* wT = sm;               // [128][132]
    float* ins = sm + 128 * 132;  // [32][132]
    float* bs = ins + 32 * 132;   // [128]
    int tid = threadIdx.x, lane = tid & 31, warp = tid >> 5;
    int n0 = blockIdx.x * 32;

    for (int idx = tid; idx < 128 * 128; idx += 256) {
        int o = idx >> 7, k = idx & 127;
        wT[k * 132 + o] = w[idx];
    }
    if (tid < 128) bs[tid] = b[tid];
#pragma unroll
    for (int i = 0; i < 4; i++) {
        int nl = warp * 4 + i;
        float4 v = *(const float4*)&h[(size_t)(n0 + nl) * DN + lane * 4];
        *(float4*)&ins[nl * 132 + lane * 4] = v;
    }
    __syncthreads();

    float acc[4][4] = {};
    const float* inw = ins + warp * 4 * 132;
    for (int k = 0; k < 128; k++) {
        float a[4], wv[4];
#pragma unroll
        for (int i = 0; i < 4; i++) a[i] = inw[i * 132 + k];
#pragma unroll
        for (int j = 0; j < 4; j++) wv[j] = wT[k * 132 + lane + 32 * j];
#pragma unroll
        for (int i = 0; i < 4; i++)
#pragma unroll
            for (int j = 0; j < 4; j++) acc[i][j] += a[i] * wv[j];
    }
#pragma unroll
    for (int i = 0; i < 4; i++) {
        int nl = warp * 4 + i;
#pragma unroll
        for (int j = 0; j < 4; j++) {
            int o = lane + 32 * j;
            g_x[(size_t)(n0 + nl) * DN + o] = acc[i][j] + bs[o];
        }
    }
}

// ---------------------------------------------------------------------------
// Fused edge kernel, f32x2-packed GEMM mainloops, double-buffered weight tiles.
// 64 edges/CTA, 256 threads. Thread outputs: o = lane*2 + 64*j2 + {0,1}.
// ---------------------------------------------------------------------------
__global__ __launch_bounds__(256, 1) void k_edge(
    const float* __restrict__ dist, const float* __restrict__ emask,
    const float* __restrict__ b1, const float* __restrict__ b2,
    const float* __restrict__ w3, const float* __restrict__ b3,
    const void* __restrict__ edges) {
    extern __shared__ float sm[];
    float* cat = sm;                       // [64][272]
    float* h1s = cat + ETILE * CATP;       // [64][260]
    float* wt = h1s + ETILE * H1P;         // [2][8][256] double-buffered k-tile
    float* b1s = wt + 4096;                // 256
    float* b2s = b1s + 256;                // 128
    float* w3s = b2s + 128;                // 128
    float* ems = w3s + 128;                // 64
    int* rows = (int*)(ems + 64);          // 64
    int* cols = rows + 64;                 // 64

    int tid = threadIdx.x, lane = tid & 31, warp = tid >> 5;
    int l2 = lane * 2;
    int e0 = blockIdx.x * ETILE;

    b1s[tid] = b1[tid];
    if (tid < 128) { b2s[tid] = b2[tid]; w3s[tid] = w3[tid]; }
    if (tid < 64) {
        int e = e0 + tid;
        if (g_e64) {
            const long long* e64 = (const long long*)edges;
            rows[tid] = (int)e64[e];
            cols[tid] = (int)e64[EE + e];
        } else {
            const int* e32 = (const int*)edges;
            rows[tid] = e32[e];
            cols[tid] = e32[EE + e];
        }
        float em = emask[e];
        ems[tid] = em;
        cat[tid * CATP + 256] = dist[e] * em;
#pragma unroll
        for (int p = 257; p < 264; p++) cat[tid * CATP + p] = 0.0f;
    }
    __syncthreads();

    // gather x_row / x_col (coalesced, L2-resident x)
#pragma unroll
    for (int i = 0; i < 8; i++) {
        int el = warp * 8 + i;
        const float* xr = &g_x[(size_t)rows[el] * DN];
        const float* xc = &g_x[(size_t)cols[el] * DN];
        *(float4*)&cat[el * CATP + lane * 4] = *(const float4*)&xr[lane * 4];
        *(float4*)&cat[el * CATP + 128 + lane * 4] = *(const float4*)&xc[lane * 4];
    }
    __syncthreads();

    // ---- GEMM1: [64e x 256o], K=264 (padded). Packed pairs along o. ----
    u64t acc[8][4] = {};
    {
        int t8 = tid * 8;
        float4 pa = *(const float4*)&g_w1T[t8];
        float4 pb = *(const float4*)&g_w1T[t8 + 4];
        const float* catw = cat + warp * 8 * CATP;
        for (int t = 0; t < 33; t++) {
            float* wb = wt + (t & 1) * 2048;
            *(float4*)&wb[t8] = pa;
            *(float4*)&wb[t8 + 4] = pb;
            __syncthreads();
            if (t < 32) {
                const float* src = &g_w1T[(t + 1) * 2048];
                pa = *(const float4*)&src[t8];
                pb = *(const float4*)&src[t8 + 4];
            }
#pragma unroll
            for (int kk = 0; kk < 8; kk++) {
                int k = t * 8 + kk;
                u64t ad[8], wv[4];
#pragma unroll
                for (int i = 0; i < 8; i++) ad[i] = dup2(catw[i * CATP + k]);
#pragma unroll
                for (int j = 0; j < 4; j++)
                    wv[j] = *(const u64t*)&wb[kk * 256 + l2 + 64 * j];
#pragma unroll
                for (int i = 0; i < 8; i++)
#pragma unroll
                    for (int j = 0; j < 4; j++) acc[i][j] = fma2(ad[i], wv[j], acc[i][j]);
            }
        }
    }
    // epilogue: bias + silu -> h1s (warp-private rows)
#pragma unroll
    for (int i = 0; i < 8; i++) {
        int el = warp * 8 + i;
#pragma unroll
        for (int j = 0; j < 4; j++) {
            int o0 = l2 + 64 * j;
            float v0, v1;
            unpack2(acc[i][j], v0, v1);
            float2 r;
            r.x = silu_(v0 + b1s[o0]);
            r.y = silu_(v1 + b1s[o0 + 1]);
            *(float2*)&h1s[el * H1P + o0] = r;
        }
    }
    __syncthreads();   // protect wt reuse (GEMM1 readers vs GEMM2 writers)

    // ---- GEMM2: [64e x 128o], K=256. Packed pairs along o. ----
    u64t acc2[8][2] = {};
    {
        int t8 = tid * 8;
        float4 pa = make_float4(0.f, 0.f, 0.f, 0.f), pb = pa;
        if (tid < 128) {
            pa = *(const float4*)&g_w2T[t8];
            pb = *(const float4*)&g_w2T[t8 + 4];
        }
        const float* h1w = h1s + warp * 8 * H1P;
        for (int t = 0; t < 32; t++) {
            float* wb = wt + (t & 1) * 1024;
            if (tid < 128) {
                *(float4*)&wb[t8] = pa;
                *(float4*)&wb[t8 + 4] = pb;
            }
            __syncthreads();
            if (tid < 128 && t < 31) {
                const float* src = &g_w2T[(t + 1) * 1024];
                pa = *(const float4*)&src[t8];
                pb = *(const float4*)&src[t8 + 4];
            }
#pragma unroll
            for (int kk = 0; kk < 8; kk++) {
                int k = t * 8 + kk;
                u64t ad[8], wv[2];
#pragma unroll
                for (int i = 0; i < 8; i++) ad[i] = dup2(h1w[i * H1P + k]);
#pragma unroll
                for (int j = 0; j < 2; j++)
                    wv[j] = *(const u64t*)&wb[kk * 128 + l2 + 64 * j];
#pragma unroll
                for (int i = 0; i < 8; i++)
#pragma unroll
                    for (int j = 0; j < 2; j++) acc2[i][j] = fma2(ad[i], wv[j], acc2[i][j]);
            }
        }
    }

    // ---- att = sigmoid(silu(h2) . w3 + b3) * mask ----
    float part[8];
#pragma unroll
    for (int i = 0; i < 8; i++) part[i] = 0.0f;
#pragma unroll
    for (int i = 0; i < 8; i++)
#pragma unroll
        for (int j = 0; j < 2; j++) {
            int o0 = l2 + 64 * j;
            float v0, v1;
            unpack2(acc2[i][j], v0, v1);
            part[i] += silu_(v0 + b2s[o0]) * w3s[o0];
            part[i] += silu_(v1 + b2s[o0 + 1]) * w3s[o0 + 1];
        }
#pragma unroll
    for (int off = 16; off > 0; off >>= 1)
#pragma unroll
        for (int i = 0; i < 8; i++)
            part[i] += __shfl_xor_sync(0xffffffffu, part[i], off);

    float b3v = b3[0];
    float attv[8];
#pragma unroll
    for (int i = 0; i < 8; i++) attv[i] = sigm(part[i] + b3v) * ems[warp * 8 + i];

    // ---- scatter: g_out[row] += x_col * att ----
#pragma unroll
    for (int i = 0; i < 8; i++) {
        int el = warp * 8 + i;
        float a = attv[i];
        float* dst = &g_out[(size_t)rows[el] * DN + lane * 4];
        const float4 v = *(const float4*)&cat[el * CATP + 128 + lane * 4];
        atomicAdd(dst + 0, v.x * a);
        atomicAdd(dst + 1, v.y * a);
        atomicAdd(dst + 2, v.z * a);
        atomicAdd(dst + 3, v.w * a);
    }
}

// ---------------------------------------------------------------------------
// node_mlp + residual + final LN + silu.   32 nodes/CTA.
// ---------------------------------------------------------------------------
__global__ __launch_bounds__(256, 1) void k_node(
    const float* __restrict__ w1, const float* __restrict__ b1,
    const float* __restrict__ g1, const float* __restrict__ bb1,
    const float* __restrict__ w2, const float* __restrict__ b2,
    const float* __restrict__ g2, const float* __restrict__ bb2,
    float* __restrict__ out) {
    extern __shared__ float sm[];
    float* w1T = sm;              // [128][132]
    float* w2T = w1T + 16896;     // [128][132]
    float* ins = w2T + 16896;     // [32][132]
    float* mids = ins + 4224;     // [32][132]
    float* b1s = mids + 4224;     // 128
    float* b2s = b1s + 128;       // 128
    int tid = threadIdx.x, lane = tid & 31, warp = tid >> 5;
    int n0 = blockIdx.x * 32;

    for (int idx = tid; idx < 128 * 128; idx += 256) {
        int o = idx >> 7, k = idx & 127;
        w1T[k * 132 + o] = w1[idx];
        w2T[k * 132 + o] = w2[idx];
    }
    if (tid < 128) { b1s[tid] = b1[tid]; b2s[tid] = b2[tid]; }
#pragma unroll
    for (int i = 0; i < 4; i++) {
        int nl = warp * 4 + i;
        float4 v = *(const float4*)&g_out[(size_t)(n0 + nl) * DN + lane * 4];
        v.x *= 0.01f; v.y *= 0.01f; v.z *= 0.01f; v.w *= 0.01f;  // / NORM_FACTOR
        *(float4*)&ins[nl * 132 + lane * 4] = v;
    }
    __syncthreads();

    // GEMM1
    float acc[4][4] = {};
    {
        const float* inw = ins + warp * 4 * 132;
        for (int k = 0; k < 128; k++) {
            float a[4], wv[4];
#pragma unroll
            for (int i = 0; i < 4; i++) a[i] = inw[i * 132 + k];
#pragma unroll
            for (int j = 0; j < 4; j++) wv[j] = w1T[k * 132 + lane + 32 * j];
#pragma unroll
            for (int i = 0; i < 4; i++)
#pragma unroll
                for (int j = 0; j < 4; j++) acc[i][j] += a[i] * wv[j];
        }
    }
    // LN1 + silu
    float lg1[4], lb1[4];
#pragma unroll
    for (int j = 0; j < 4; j++) { int o = lane + 32 * j; lg1[j] = g1[o]; lb1[j] = bb1[o]; }
#pragma unroll
    for (int i = 0; i < 4; i++) {
        float v[4], s1 = 0.f, s2 = 0.f;
#pragma unroll
        for (int j = 0; j < 4; j++) {
            v[j] = acc[i][j] + b1s[lane + 32 * j];
            s1 += v[j]; s2 += v[j] * v[j];
        }
#pragma unroll
        for (int off = 16; off > 0; off >>= 1) {
            s1 += __shfl_xor_sync(0xffffffffu, s1, off);
            s2 += __shfl_xor_sync(0xffffffffu, s2, off);
        }
        float mean = s1 * (1.0f / 128.0f);
        float var = s2 * (1.0f / 128.0f) - mean * mean;
        float inv = rsqrtf(var + 1e-5f);
        int nl = warp * 4 + i;
#pragma unroll
        for (int j = 0; j < 4; j++) {
            float y = (v[j] - mean) * inv * lg1[j] + lb1[j];
            mids[nl * 132 + lane + 32 * j] = silu_(y);
        }
    }
    __syncthreads();

    // GEMM2
    float acc2[4][4] = {};
    {
        const float* mw = mids + warp * 4 * 132;
        for (int k = 0; k < 128; k++) {
            float a[4], wv[4];
#pragma unroll
            for (int i = 0; i < 4; i++) a[i] = mw[i * 132 + k];
#pragma unroll
            for (int j = 0; j < 4; j++) wv[j] = w2T[k * 132 + lane + 32 * j];
#pragma unroll
            for (int i = 0; i < 4; i++)
#pragma unroll
                for (int j = 0; j < 4; j++) acc2[i][j] += a[i] * wv[j];
        }
    }
    // + residual, LN2, silu, store
    float lg2[4], lb2[4];
#pragma unroll
    for (int j = 0; j < 4; j++) { int o = lane + 32 * j; lg2[j] = g2[o]; lb2[j] = bb2[o]; }
#pragma unroll
    for (int i = 0; i < 4; i++) {
        int nl = warp * 4 + i;
        float v[4], s1 = 0.f, s2 = 0.f;
#pragma unroll
        for (int j = 0; j < 4; j++) {
            int o = lane + 32 * j;
            v[j] = acc2[i][j] + b2s[o] + g_x[(size_t)(n0 + nl) * DN + o];
            s1 += v[j]; s2 += v[j] * v[j];
        }
#pragma unroll
        for (int off = 16; off > 0; off >>= 1) {
            s1 += __shfl_xor_sync(0xffffffffu, s1, off);
            s2 += __shfl_xor_sync(0xffffffffu, s2, off);
        }
        float mean = s1 * (1.0f / 128.0f);
        float var = s2 * (1.0f / 128.0f) - mean * mean;
        float inv = rsqrtf(var + 1e-5f);
#pragma unroll
        for (int j = 0; j < 4; j++) {
            int o = lane + 32 * j;
            float y = (v[j] - mean) * inv * lg2[j] + lb2[j];
            out[(size_t)(n0 + nl) * DN + o] = silu_(y);
        }
    }
}

// ---------------------------------------------------------------------------
extern "C" void kernel_launch(void* const* d_in, const int* in_sizes, int n_in,
                              void* d_out, int out_size) {
    const float* h = (const float*)d_in[0];
    const float* distances = (const float*)d_in[1];
    const float* edge_mask = (const float*)d_in[3];
    const float* lin_w = (const float*)d_in[4];
    const float* lin_b = (const float*)d_in[5];
    const float* att_w1 = (const float*)d_in[6];
    const float* att_b1 = (const float*)d_in[7];
    const float* att_w2 = (const float*)d_in[8];
    const float* att_b2 = (const float*)d_in[9];
    const float* att_w3 = (const float*)d_in[10];
    const float* att_b3 = (const float*)d_in[11];
    const float* nm_w1 = (const float*)d_in[12];
    const float* nm_b1 = (const float*)d_in[13];
    const float* nm_ln_g = (const float*)d_in[14];
    const float* nm_ln_b = (const float*)d_in[15];
    const float* nm_w2 = (const float*)d_in[16];
    const float* nm_b2 = (const float*)d_in[17];
    const float* ln_g = (const float*)d_in[18];
    const float* ln_b = (const float*)d_in[19];
    const void* edges = d_in[20];

    cudaFuncSetAttribute(k_lin, cudaFuncAttributeMaxDynamicSharedMemorySize, 84992);
    cudaFuncSetAttribute(k_edge, cudaFuncAttributeMaxDynamicSharedMemorySize, 155392);
    cudaFuncSetAttribute(k_node, cudaFuncAttributeMaxDynamicSharedMemorySize, 169984);

    k_prep<<<392, 256>>>(att_w1, att_w2, edges);
    k_zero<<<(NN * DN + 255) / 256, 256>>>();
    k_lin<<<625, 256, 84992>>>(h, lin_w, lin_b);
    k_edge<<<EE / ETILE, 256, 155392>>>(distances, edge_mask, att_b1, att_b2,
                                        att_w3, att_b3, edges);
    k_node<<<625, 256, 169984>>>(nm_w1, nm_b1, nm_ln_g, nm_ln_b,
                                 nm_w2, nm_b2, ln_g, ln_b, (float*)d_out);
}

// round 4
// speedup vs baseline: 2.2477x; 1.9421x over previous
#include <cuda_runtime.h>
#include <cuda_bf16.h>

typedef unsigned int u32;
typedef unsigned long long u64;
typedef unsigned short u16;

#define DN 128
#define NN 20000
#define EE 640000
#define ET 128                  // edges per CTA
#define NCTA (EE / ET)          // 5000
#define ASTR 528                // A/h1 row stride bytes (264 halves)
#define WSTR 272                // W row stride bytes (136 halves)

// ---------------- device globals (no runtime alloc) ----------------
__device__ float g_x[NN * DN];
__device__ float g_out[NN * DN];
__device__ int g_e64;
// padded-row bf16 weight images, ready for direct smem memcpy:
__device__ uint4 g_w1i[2][2][2][2176];  // [oc][side][hi/lo]  chunk=[128 out][136 halves]
__device__ uint4 g_w2i[2][2][2176];     // [kc][hi/lo]        chunk=[128 out][136 halves]

// ---------------- smem layout (bytes) ----------------
#define SB_ROWS 0
#define SB_COLS 512
#define SB_DE   1024
#define SB_EMS  1536
#define SB_B1   2048
#define SB_B2   3072
#define SB_W3   3584
#define SB_W1C  4096
#define SB_ATT  5120
#define SB_PART 5632
#define SB_A_HI 8192            // 67584 = 128 x 528
#define SB_A_LO 75776           // 67584
#define SB_W_HI 143360          // 34816 = 128 x 272
#define SB_W_LO 178176          // 34816
#define SMEM_EDGE 212992

__device__ __forceinline__ u32 smem_u32(const void* p) {
    u32 a;
    asm("{ .reg .u64 t; cvta.to.shared.u64 t, %1; cvt.u32.u64 %0, t; }" : "=r"(a) : "l"(p));
    return a;
}
__device__ __forceinline__ float sigm(float v) { return 1.0f / (1.0f + __expf(-v)); }
__device__ __forceinline__ float silu_(float v) { return v * sigm(v); }

__device__ __forceinline__ void bsplit(float v, u16& h, u16& l) {
    __nv_bfloat16 hb = __float2bfloat16(v);
    __nv_bfloat16 lb = __float2bfloat16(v - __bfloat162float(hb));
    h = __bfloat16_as_ushort(hb);
    l = __bfloat16_as_ushort(lb);
}

// ldmatrix m16k16 (A, row-major): regs a0..a3 in mma A-fragment order
__device__ __forceinline__ void ldmA(u32 r[4], u32 base, int row0, int kh) {
    int lane = threadIdx.x & 31;
    int quad = lane >> 3;
    u32 addr = base + (u32)(row0 + (lane & 7) + (quad & 1) * 8) * ASTR +
               (u32)kh * 2 + (u32)(quad >> 1) * 16;
    asm volatile("ldmatrix.sync.aligned.m8n8.x4.shared.b16 {%0,%1,%2,%3}, [%4];"
                 : "=r"(r[0]), "=r"(r[1]), "=r"(r[2]), "=r"(r[3]) : "r"(addr));
}
// ldmatrix 2 B nblocks (n16 x k16) from [n][k] rows: (r0,r1)=nblock0, (r2,r3)=nblock1
__device__ __forceinline__ void ldmB(u32 r[4], u32 base, int n0, int kh) {
    int lane = threadIdx.x & 31;
    u32 addr = base + (u32)(n0 + (lane & 7) + (lane >> 4) * 8) * WSTR +
               (u32)kh * 2 + (u32)((lane >> 3) & 1) * 16;
    asm volatile("ldmatrix.sync.aligned.m8n8.x4.shared.b16 {%0,%1,%2,%3}, [%4];"
                 : "=r"(r[0]), "=r"(r[1]), "=r"(r[2]), "=r"(r[3]) : "r"(addr));
}
__device__ __forceinline__ void mma16816(float d[4], const u32 a[4], u32 b0, u32 b1) {
    asm volatile("mma.sync.aligned.m16n8k16.row.col.f32.bf16.bf16.f32 "
                 "{%0,%1,%2,%3}, {%4,%5,%6,%7}, {%8,%9}, {%0,%1,%2,%3};"
                 : "+f"(d[0]), "+f"(d[1]), "+f"(d[2]), "+f"(d[3])
                 : "r"(a[0]), "r"(a[1]), "r"(a[2]), "r"(a[3]), "r"(b0), "r"(b1));
}

// ---------------------------------------------------------------------------
// k_prep: build padded-row bf16 hi/lo weight images; detect edges dtype.
// 98304 elements -> grid 384 x 256.
// ---------------------------------------------------------------------------
__global__ void k_prep(const float* __restrict__ w1, const float* __restrict__ w2,
                       const void* __restrict__ edges) {
    int idx = blockIdx.x * 256 + threadIdx.x;
    u16 h, l;
    if (idx < 65536) {
        int k = idx & 127, o = (idx >> 7) & 127;
        int side = (idx >> 14) & 1, oc = (idx >> 15) & 1;
        bsplit(w1[(oc * 128 + o) * 257 + side * 128 + k], h, l);
        u32 off = (u32)o * WSTR + (u32)k * 2;
        *(u16*)((char*)g_w1i[oc][side][0] + off) = h;
        *(u16*)((char*)g_w1i[oc][side][1] + off) = l;
    } else {
        int j = idx - 65536;
        int k = j & 127, o = (j >> 7) & 127, kc = (j >> 14) & 1;
        bsplit(w2[o * 256 + kc * 128 + k], h, l);
        u32 off = (u32)o * WSTR + (u32)k * 2;
        *(u16*)((char*)g_w2i[kc][0] + off) = h;
        *(u16*)((char*)g_w2i[kc][1] + off) = l;
    }
    if (idx == 0) {
        const int* e32 = (const int*)edges;
        int nz = 0;
        for (int i = 0; i < 16; i++) nz |= e32[2 * i + 1];
        g_e64 = (nz == 0) ? 1 : 0;
    }
}

__global__ void k_zero() {
    int i = blockIdx.x * 256 + threadIdx.x;
    if (i < NN * DN) g_out[i] = 0.0f;
}

// ---------------------------------------------------------------------------
// x = h @ lin_w^T + lin_b   (32 nodes/CTA)
// ---------------------------------------------------------------------------
__global__ __launch_bounds__(256, 1) void k_lin(const float* __restrict__ h,
                                                const float* __restrict__ w,
                                                const float* __restrict__ b) {
    extern __shared__ float sm[];
    float* wT = sm;
    float* ins = sm + 128 * 132;
    float* bs = ins + 32 * 132;
    int tid = threadIdx.x, lane = tid & 31, warp = tid >> 5;
    int n0 = blockIdx.x * 32;

    for (int idx = tid; idx < 128 * 128; idx += 256) {
        int o = idx >> 7, k = idx & 127;
        wT[k * 132 + o] = w[idx];
    }
    if (tid < 128) bs[tid] = b[tid];
#pragma unroll
    for (int i = 0; i < 4; i++) {
        int nl = warp * 4 + i;
        float4 v = *(const float4*)&h[(size_t)(n0 + nl) * DN + lane * 4];
        *(float4*)&ins[nl * 132 + lane * 4] = v;
    }
    __syncthreads();

    float acc[4][4] = {};
    const float* inw = ins + warp * 4 * 132;
    for (int k = 0; k < 128; k++) {
        float a[4], wv[4];
#pragma unroll
        for (int i = 0; i < 4; i++) a[i] = inw[i * 132 + k];
#pragma unroll
        for (int j = 0; j < 4; j++) wv[j] = wT[k * 132 + lane + 32 * j];
#pragma unroll
        for (int i = 0; i < 4; i++)
#pragma unroll
            for (int j = 0; j < 4; j++) acc[i][j] += a[i] * wv[j];
    }
#pragma unroll
    for (int i = 0; i < 4; i++) {
        int nl = warp * 4 + i;
#pragma unroll
        for (int j = 0; j < 4; j++) {
            int o = lane + 32 * j;
            g_x[(size_t)(n0 + nl) * DN + o] = acc[i][j] + bs[o];
        }
    }
}

// ---------------------------------------------------------------------------
// Fused edge kernel on mma.sync bf16 hi/lo (3-product split, fp32-class acc).
// 128 edges/CTA, 8 warps = 4 edge-groups x 2 out-groups, warp tile 32x64.
// ---------------------------------------------------------------------------
__global__ __launch_bounds__(256, 1) void k_edge(
    const float* __restrict__ dist, const float* __restrict__ emask,
    const float* __restrict__ w1, const float* __restrict__ b1,
    const float* __restrict__ b2, const float* __restrict__ w3,
    const float* __restrict__ b3, const void* __restrict__ edges) {
    extern __shared__ char smc[];
    u32 smb = smem_u32(smc);
    float* smf = (float*)smc;
    int* rows = (int*)(smc + SB_ROWS);
    int* cols = (int*)(smc + SB_COLS);

    int tid = threadIdx.x, lane = tid & 31, warp = tid >> 5;
    int eg = warp & 3, og = warp >> 2;
    int Eb = eg * 32;
    int e0 = blockIdx.x * ET;

    // stage small vectors
    smf[SB_B1 / 4 + tid] = b1[tid];
    smf[SB_W1C / 4 + tid] = w1[tid * 257 + 256];
    if (tid < 128) {
        smf[SB_B2 / 4 + tid] = b2[tid];
        smf[SB_W3 / 4 + tid] = w3[tid];
        int e = e0 + tid;
        if (g_e64) {
            const long long* e64 = (const long long*)edges;
            rows[tid] = (int)e64[e];
            cols[tid] = (int)e64[EE + e];
        } else {
            const int* ei = (const int*)edges;
            rows[tid] = ei[e];
            cols[tid] = ei[EE + e];
        }
        float em = emask[e];
        smf[SB_EMS / 4 + tid] = em;
        smf[SB_DE / 4 + tid] = dist[e] * em;
    }
    __syncthreads();

    // ---- gather x_row / x_col -> A (bf16 hi/lo), k: 0-127 row, 128-255 col
#pragma unroll
    for (int i = 0; i < 16; i++) {
        int el = warp * 16 + i;
        const float4 vr = *(const float4*)&g_x[(size_t)rows[el] * DN + lane * 4];
        const float4 vc = *(const float4*)&g_x[(size_t)cols[el] * DN + lane * 4];
        u16 h0, l0, h1_, l1_, h2, l2, h3, l3;
        bsplit(vr.x, h0, l0); bsplit(vr.y, h1_, l1_); bsplit(vr.z, h2, l2); bsplit(vr.w, h3, l3);
        u64 hp = (u64)h0 | ((u64)h1_ << 16) | ((u64)h2 << 32) | ((u64)h3 << 48);
        u64 lp = (u64)l0 | ((u64)l1_ << 16) | ((u64)l2 << 32) | ((u64)l3 << 48);
        *(u64*)(smc + SB_A_HI + el * ASTR + lane * 8) = hp;
        *(u64*)(smc + SB_A_LO + el * ASTR + lane * 8) = lp;
        bsplit(vc.x, h0, l0); bsplit(vc.y, h1_, l1_); bsplit(vc.z, h2, l2); bsplit(vc.w, h3, l3);
        hp = (u64)h0 | ((u64)h1_ << 16) | ((u64)h2 << 32) | ((u64)h3 << 48);
        lp = (u64)l0 | ((u64)l1_ << 16) | ((u64)l2 << 32) | ((u64)l3 << 48);
        *(u64*)(smc + SB_A_HI + el * ASTR + 256 + lane * 8) = hp;
        *(u64*)(smc + SB_A_LO + el * ASTR + 256 + lane * 8) = lp;
    }

    // ---- GEMM1: D1[128e x 256o] in register acc, K=256 via 2 sides ----
    float acc1[2][2][8][4] = {};   // [oc][mtile][nblock][frag]
#pragma unroll
    for (int oc = 0; oc < 2; oc++) {
#pragma unroll
        for (int side = 0; side < 2; side++) {
            __syncthreads();
            {
                const uint4* sh = g_w1i[oc][side][0];
                const uint4* sl = g_w1i[oc][side][1];
                uint4* dh = (uint4*)(smc + SB_W_HI);
                uint4* dl = (uint4*)(smc + SB_W_LO);
                for (int i = tid; i < 2176; i += 256) { dh[i] = sh[i]; dl[i] = sl[i]; }
            }
            __syncthreads();
#pragma unroll
            for (int ks = 0; ks < 8; ks++) {
                int ka = side * 128 + ks * 16;
                u32 ah[2][4], al_[2][4];
                ldmA(ah[0], smb + SB_A_HI, Eb, ka);
                ldmA(ah[1], smb + SB_A_HI, Eb + 16, ka);
                ldmA(al_[0], smb + SB_A_LO, Eb, ka);
                ldmA(al_[1], smb + SB_A_LO, Eb + 16, ka);
#pragma unroll
                for (int nq = 0; nq < 4; nq++) {
                    u32 bh[4], bl[4];
                    ldmB(bh, smb + SB_W_HI, og * 64 + nq * 16, ks * 16);
                    ldmB(bl, smb + SB_W_LO, og * 64 + nq * 16, ks * 16);
#pragma unroll
                    for (int mt = 0; mt < 2; mt++) {
                        mma16816(acc1[oc][mt][nq * 2], ah[mt], bh[0], bh[1]);
                        mma16816(acc1[oc][mt][nq * 2], ah[mt], bl[0], bl[1]);
                        mma16816(acc1[oc][mt][nq * 2], al_[mt], bh[0], bh[1]);
                        mma16816(acc1[oc][mt][nq * 2 + 1], ah[mt], bh[2], bh[3]);
                        mma16816(acc1[oc][mt][nq * 2 + 1], ah[mt], bl[2], bl[3]);
                        mma16816(acc1[oc][mt][nq * 2 + 1], al_[mt], bh[2], bh[3]);
                    }
                }
            }
        }
    }
    __syncthreads();   // all warps done reading A -> safe to overlay h1

    // ---- epilogue1: + d*w1c + b1, silu, bf16-split -> h1 (A region) ----
    {
        int r0 = lane >> 2, cb = (lane & 3) * 2;
#pragma unroll
        for (int oc = 0; oc < 2; oc++)
#pragma unroll
            for (int mt = 0; mt < 2; mt++) {
                int e_lo = Eb + mt * 16 + r0, e_hi = e_lo + 8;
                float de_lo = smf[SB_DE / 4 + e_lo], de_hi = smf[SB_DE / 4 + e_hi];
#pragma unroll
                for (int nb = 0; nb < 8; nb++) {
                    int o = oc * 128 + og * 64 + nb * 8 + cb;
                    float b1a = smf[SB_B1 / 4 + o], b1b = smf[SB_B1 / 4 + o + 1];
                    float wca = smf[SB_W1C / 4 + o], wcb = smf[SB_W1C / 4 + o + 1];
                    float v0 = silu_(acc1[oc][mt][nb][0] + de_lo * wca + b1a);
                    float v1 = silu_(acc1[oc][mt][nb][1] + de_lo * wcb + b1b);
                    float v2 = silu_(acc1[oc][mt][nb][2] + de_hi * wca + b1a);
                    float v3 = silu_(acc1[oc][mt][nb][3] + de_hi * wcb + b1b);
                    u16 h0, l0, h1_, l1_;
                    bsplit(v0, h0, l0); bsplit(v1, h1_, l1_);
                    *(u32*)(smc + SB_A_HI + e_lo * ASTR + o * 2) = (u32)h0 | ((u32)h1_ << 16);
                    *(u32*)(smc + SB_A_LO + e_lo * ASTR + o * 2) = (u32)l0 | ((u32)l1_ << 16);
                    bsplit(v2, h0, l0); bsplit(v3, h1_, l1_);
                    *(u32*)(smc + SB_A_HI + e_hi * ASTR + o * 2) = (u32)h0 | ((u32)h1_ << 16);
                    *(u32*)(smc + SB_A_LO + e_hi * ASTR + o * 2) = (u32)l0 | ((u32)l1_ << 16);
                }
            }
    }

    // ---- GEMM2: D2[128e x 128o], K=256 in 2 k-chunks ----
    float acc2[2][8][4] = {};
#pragma unroll
    for (int kc = 0; kc < 2; kc++) {
        __syncthreads();
        {
            const uint4* sh = g_w2i[kc][0];
            const uint4* sl = g_w2i[kc][1];
            uint4* dh = (uint4*)(smc + SB_W_HI);
            uint4* dl = (uint4*)(smc + SB_W_LO);
            for (int i = tid; i < 2176; i += 256) { dh[i] = sh[i]; dl[i] = sl[i]; }
        }
        __syncthreads();
#pragma unroll
        for (int ks = 0; ks < 8; ks++) {
            int ka = kc * 128 + ks * 16;
            u32 ah[2][4], al_[2][4];
            ldmA(ah[0], smb + SB_A_HI, Eb, ka);
            ldmA(ah[1], smb + SB_A_HI, Eb + 16, ka);
            ldmA(al_[0], smb + SB_A_LO, Eb, ka);
            ldmA(al_[1], smb + SB_A_LO, Eb + 16, ka);
#pragma unroll
            for (int nq = 0; nq < 4; nq++) {
                u32 bh[4], bl[4];
                ldmB(bh, smb + SB_W_HI, og * 64 + nq * 16, ks * 16);
                ldmB(bl, smb + SB_W_LO, og * 64 + nq * 16, ks * 16);
#pragma unroll
                for (int mt = 0; mt < 2; mt++) {
                    mma16816(acc2[mt][nq * 2], ah[mt], bh[0], bh[1]);
                    mma16816(acc2[mt][nq * 2], ah[mt], bl[0], bl[1]);
                    mma16816(acc2[mt][nq * 2], al_[mt], bh[0], bh[1]);
                    mma16816(acc2[mt][nq * 2 + 1], ah[mt], bh[2], bh[3]);
                    mma16816(acc2[mt][nq * 2 + 1], ah[mt], bl[2], bl[3]);
                    mma16816(acc2[mt][nq * 2 + 1], al_[mt], bh[2], bh[3]);
                }
            }
        }
    }

    // ---- epilogue2: att partials, cross-out-group combine ----
    {
        int r0 = lane >> 2, cb = (lane & 3) * 2;
        float p[2][2] = {};
#pragma unroll
        for (int mt = 0; mt < 2; mt++)
#pragma unroll
            for (int nb = 0; nb < 8; nb++) {
                int o = og * 64 + nb * 8 + cb;
                float b2a = smf[SB_B2 / 4 + o], b2b = smf[SB_B2 / 4 + o + 1];
                float w3a = smf[SB_W3 / 4 + o], w3b = smf[SB_W3 / 4 + o + 1];
                p[mt][0] += silu_(acc2[mt][nb][0] + b2a) * w3a + silu_(acc2[mt][nb][1] + b2b) * w3b;
                p[mt][1] += silu_(acc2[mt][nb][2] + b2a) * w3a + silu_(acc2[mt][nb][3] + b2b) * w3b;
            }
#pragma unroll
        for (int off = 1; off <= 2; off <<= 1)
#pragma unroll
            for (int mt = 0; mt < 2; mt++) {
                p[mt][0] += __shfl_xor_sync(0xffffffffu, p[mt][0], off);
                p[mt][1] += __shfl_xor_sync(0xffffffffu, p[mt][1], off);
            }
        if ((lane & 3) == 0) {
#pragma unroll
            for (int mt = 0; mt < 2; mt++) {
                int e = Eb + mt * 16 + r0;
                smf[SB_PART / 4 + og * 128 + e] = p[mt][0];
                smf[SB_PART / 4 + og * 128 + e + 8] = p[mt][1];
            }
        }
    }
    __syncthreads();
    if (tid < 128) {
        float z = smf[SB_PART / 4 + tid] + smf[SB_PART / 4 + 128 + tid] + b3[0];
        smf[SB_ATT / 4 + tid] = sigm(z) * smf[SB_EMS / 4 + tid];
    }
    __syncthreads();

    // ---- scatter: g_out[row] += x_col * att ----
#pragma unroll
    for (int i = 0; i < 16; i++) {
        int el = warp * 16 + i;
        float a = smf[SB_ATT / 4 + el];
        const float4 v = *(const float4*)&g_x[(size_t)cols[el] * DN + lane * 4];
        float* dst = &g_out[(size_t)rows[el] * DN + lane * 4];
        atomicAdd(dst + 0, v.x * a);
        atomicAdd(dst + 1, v.y * a);
        atomicAdd(dst + 2, v.z * a);
        atomicAdd(dst + 3, v.w * a);
    }
}

// ---------------------------------------------------------------------------
// node_mlp + residual + final LN + silu.   32 nodes/CTA.
// ---------------------------------------------------------------------------
__global__ __launch_bounds__(256, 1) void k_node(
    const float* __restrict__ w1, const float* __restrict__ b1,
    const float* __restrict__ g1, const float* __restrict__ bb1,
    const float* __restrict__ w2, const float* __restrict__ b2,
    const float* __restrict__ g2, const float* __restrict__ bb2,
    float* __restrict__ out) {
    extern __shared__ float sm[];
    float* w1T = sm;
    float* w2T = w1T + 16896;
    float* ins = w2T + 16896;
    float* mids = ins + 4224;
    float* b1s = mids + 4224;
    float* b2s = b1s + 128;
    int tid = threadIdx.x, lane = tid & 31, warp = tid >> 5;
    int n0 = blockIdx.x * 32;

    for (int idx = tid; idx < 128 * 128; idx += 256) {
        int o = idx >> 7, k = idx & 127;
        w1T[k * 132 + o] = w1[idx];
        w2T[k * 132 + o] = w2[idx];
    }
    if (tid < 128) { b1s[tid] = b1[tid]; b2s[tid] = b2[tid]; }
#pragma unroll
    for (int i = 0; i < 4; i++) {
        int nl = warp * 4 + i;
        float4 v = *(const float4*)&g_out[(size_t)(n0 + nl) * DN + lane * 4];
        v.x *= 0.01f; v.y *= 0.01f; v.z *= 0.01f; v.w *= 0.01f;
        *(float4*)&ins[nl * 132 + lane * 4] = v;
    }
    __syncthreads();

    float acc[4][4] = {};
    {
        const float* inw = ins + warp * 4 * 132;
        for (int k = 0; k < 128; k++) {
            float a[4], wv[4];
#pragma unroll
            for (int i = 0; i < 4; i++) a[i] = inw[i * 132 + k];
#pragma unroll
            for (int j = 0; j < 4; j++) wv[j] = w1T[k * 132 + lane + 32 * j];
#pragma unroll
            for (int i = 0; i < 4; i++)
#pragma unroll
                for (int j = 0; j < 4; j++) acc[i][j] += a[i] * wv[j];
        }
    }
    float lg1[4], lb1[4];
#pragma unroll
    for (int j = 0; j < 4; j++) { int o = lane + 32 * j; lg1[j] = g1[o]; lb1[j] = bb1[o]; }
#pragma unroll
    for (int i = 0; i < 4; i++) {
        float v[4], s1 = 0.f, s2 = 0.f;
#pragma unroll
        for (int j = 0; j < 4; j++) {
            v[j] = acc[i][j] + b1s[lane + 32 * j];
            s1 += v[j]; s2 += v[j] * v[j];
        }
#pragma unroll
        for (int off = 16; off > 0; off >>= 1) {
            s1 += __shfl_xor_sync(0xffffffffu, s1, off);
            s2 += __shfl_xor_sync(0xffffffffu, s2, off);
        }
        float mean = s1 * (1.0f / 128.0f);
        float var = s2 * (1.0f / 128.0f) - mean * mean;
        float inv = rsqrtf(var + 1e-5f);
        int nl = warp * 4 + i;
#pragma unroll
        for (int j = 0; j < 4; j++) {
            float y = (v[j] - mean) * inv * lg1[j] + lb1[j];
            mids[nl * 132 + lane + 32 * j] = silu_(y);
        }
    }
    __syncthreads();

    float acc2[4][4] = {};
    {
        const float* mw = mids + warp * 4 * 132;
        for (int k = 0; k < 128; k++) {
            float a[4], wv[4];
#pragma unroll
            for (int i = 0; i < 4; i++) a[i] = mw[i * 132 + k];
#pragma unroll
            for (int j = 0; j < 4; j++) wv[j] = w2T[k * 132 + lane + 32 * j];
#pragma unroll
            for (int i = 0; i < 4; i++)
#pragma unroll
                for (int j = 0; j < 4; j++) acc2[i][j] += a[i] * wv[j];
        }
    }
    float lg2[4], lb2[4];
#pragma unroll
    for (int j = 0; j < 4; j++) { int o = lane + 32 * j; lg2[j] = g2[o]; lb2[j] = bb2[o]; }
#pragma unroll
    for (int i = 0; i < 4; i++) {
        int nl = warp * 4 + i;
        float v[4], s1 = 0.f, s2 = 0.f;
#pragma unroll
        for (int j = 0; j < 4; j++) {
            int o = lane + 32 * j;
            v[j] = acc2[i][j] + b2s[o] + g_x[(size_t)(n0 + nl) * DN + o];
            s1 += v[j]; s2 += v[j] * v[j];
        }
#pragma unroll
        for (int off = 16; off > 0; off >>= 1) {
            s1 += __shfl_xor_sync(0xffffffffu, s1, off);
            s2 += __shfl_xor_sync(0xffffffffu, s2, off);
        }
        float mean = s1 * (1.0f / 128.0f);
        float var = s2 * (1.0f / 128.0f) - mean * mean;
        float inv = rsqrtf(var + 1e-5f);
#pragma unroll
        for (int j = 0; j < 4; j++) {
            int o = lane + 32 * j;
            float y = (v[j] - mean) * inv * lg2[j] + lb2[j];
            out[(size_t)(n0 + nl) * DN + o] = silu_(y);
        }
    }
}

// ---------------------------------------------------------------------------
extern "C" void kernel_launch(void* const* d_in, const int* in_sizes, int n_in,
                              void* d_out, int out_size) {
    const float* h = (const float*)d_in[0];
    const float* distances = (const float*)d_in[1];
    const float* edge_mask = (const float*)d_in[3];
    const float* lin_w = (const float*)d_in[4];
    const float* lin_b = (const float*)d_in[5];
    const float* att_w1 = (const float*)d_in[6];
    const float* att_b1 = (const float*)d_in[7];
    const float* att_w2 = (const float*)d_in[8];
    const float* att_b2 = (const float*)d_in[9];
    const float* att_w3 = (const float*)d_in[10];
    const float* att_b3 = (const float*)d_in[11];
    const float* nm_w1 = (const float*)d_in[12];
    const float* nm_b1 = (const float*)d_in[13];
    const float* nm_ln_g = (const float*)d_in[14];
    const float* nm_ln_b = (const float*)d_in[15];
    const float* nm_w2 = (const float*)d_in[16];
    const float* nm_b2 = (const float*)d_in[17];
    const float* ln_g = (const float*)d_in[18];
    const float* ln_b = (const float*)d_in[19];
    const void* edges = d_in[20];

    cudaFuncSetAttribute(k_lin, cudaFuncAttributeMaxDynamicSharedMemorySize, 84992);
    cudaFuncSetAttribute(k_edge, cudaFuncAttributeMaxDynamicSharedMemorySize, SMEM_EDGE);
    cudaFuncSetAttribute(k_node, cudaFuncAttributeMaxDynamicSharedMemorySize, 169984);

    k_prep<<<384, 256>>>(att_w1, att_w2, edges);
    k_zero<<<(NN * DN + 255) / 256, 256>>>();
    k_lin<<<625, 256, 84992>>>(h, lin_w, lin_b);
    k_edge<<<NCTA, 256, SMEM_EDGE>>>(distances, edge_mask, att_w1, att_b1,
                                     att_b2, att_w3, att_b3, edges);
    k_node<<<625, 256, 169984>>>(nm_w1, nm_b1, nm_ln_g, nm_ln_b,
                                 nm_w2, nm_b2, ln_g, ln_b, (float*)d_out);
}

// round 5
// speedup vs baseline: 3.4008x; 1.5130x over previous
#include <cuda_runtime.h>
#include <cuda_bf16.h>

typedef unsigned int u32;
typedef unsigned long long u64;
typedef unsigned short u16;

#define DN 128
#define NN 20000
#define EE 640000
#define ET 64                   // edges per CTA
#define NCTA (EE / ET)          // 10000
#define ASTR 528                // A/h1 row stride bytes (264 halves)

// ---------------- device globals (no runtime alloc) ----------------
__device__ float g_x[NN * DN];
__device__ float g_out[NN * DN];
__device__ int g_e64;
// pre-packed B fragments in per-lane mma order (hi,lo interleaved uint4 pairs)
__device__ uint4 g_f1[16384];   // GEMM1: [og4][side2][ks8][nq4][lane32][hi/lo]  256KB
__device__ uint4 g_f2[8192];    // GEMM2: [og4][ks16][nq2][lane32][hi/lo]        128KB

// ---------------- smem layout (bytes) ----------------
#define SB_ROWS 0
#define SB_COLS 256
#define SB_DE   512
#define SB_EMS  768
#define SB_ATT  1024
#define SB_PART 1280
#define SB_B1   2304
#define SB_W1C  3328
#define SB_B2   4352
#define SB_W3   4864
#define SB_A_HI 5376            // 64 x 528 = 33792
#define SB_A_LO 39168           // 33792
#define SMEM_EDGE 72960

__device__ __forceinline__ u32 smem_u32(const void* p) {
    u32 a;
    asm("{ .reg .u64 t; cvta.to.shared.u64 t, %1; cvt.u32.u64 %0, t; }" : "=r"(a) : "l"(p));
    return a;
}
__device__ __forceinline__ float sigm(float v) { return 1.0f / (1.0f + __expf(-v)); }
__device__ __forceinline__ float silu_(float v) { return v * sigm(v); }

__device__ __forceinline__ void bsplit(float v, u16& h, u16& l) {
    __nv_bfloat16 hb = __float2bfloat16(v);
    __nv_bfloat16 lb = __float2bfloat16(v - __bfloat162float(hb));
    h = __bfloat16_as_ushort(hb);
    l = __bfloat16_as_ushort(lb);
}

// ldmatrix m16k16 (A, row-major): regs a0..a3 in mma A-fragment order
__device__ __forceinline__ void ldmA(u32 r[4], u32 base, int row0, int kh) {
    int lane = threadIdx.x & 31;
    int quad = lane >> 3;
    u32 addr = base + (u32)(row0 + (lane & 7) + (quad & 1) * 8) * ASTR +
               (u32)kh * 2 + (u32)(quad >> 1) * 16;
    asm volatile("ldmatrix.sync.aligned.m8n8.x4.shared.b16 {%0,%1,%2,%3}, [%4];"
                 : "=r"(r[0]), "=r"(r[1]), "=r"(r[2]), "=r"(r[3]) : "r"(addr));
}
__device__ __forceinline__ void mma16816(float d[4], const u32 a[4], u32 b0, u32 b1) {
    asm volatile("mma.sync.aligned.m16n8k16.row.col.f32.bf16.bf16.f32 "
                 "{%0,%1,%2,%3}, {%4,%5,%6,%7}, {%8,%9}, {%0,%1,%2,%3};"
                 : "+f"(d[0]), "+f"(d[1]), "+f"(d[2]), "+f"(d[3])
                 : "r"(a[0]), "r"(a[1]), "r"(a[2]), "r"(a[3]), "r"(b0), "r"(b1));
}

// ---------------------------------------------------------------------------
// k_prep: pack W1/W2 into per-lane B-fragment tables (hi/lo bf16 split).
// Fragment mapping (mma.m16n8k16 B): n = nbase + nb*8 + lane/4,
//   reg r holds k = kbase + r*8 + (lane%4)*2, +1  (two bf16 packed).
// 12288 fragment pairs -> grid 48 x 256.
// ---------------------------------------------------------------------------
__global__ void k_prep(const float* __restrict__ w1, const float* __restrict__ w2,
                       const void* __restrict__ edges) {
    int idx = blockIdx.x * 256 + threadIdx.x;
    if (idx < 8192) {       // GEMM1 frags from w1 [256 out][257 k]
        int lane = idx & 31, nq = (idx >> 5) & 3, ks = (idx >> 7) & 7;
        int side = (idx >> 10) & 1, og = (idx >> 11) & 3;
        int nb0 = og * 64 + nq * 16 + (lane >> 2);
        int kb = side * 128 + ks * 16 + (lane & 3) * 2;
        u32 wh[4], wl[4];
#pragma unroll
        for (int nb = 0; nb < 2; nb++)
#pragma unroll
            for (int r = 0; r < 2; r++) {
                const float* p = &w1[(nb0 + nb * 8) * 257 + kb + r * 8];
                u16 h0, l0, h1, l1;
                bsplit(p[0], h0, l0);
                bsplit(p[1], h1, l1);
                wh[nb * 2 + r] = (u32)h0 | ((u32)h1 << 16);
                wl[nb * 2 + r] = (u32)l0 | ((u32)l1 << 16);
            }
        g_f1[idx * 2] = make_uint4(wh[0], wh[1], wh[2], wh[3]);
        g_f1[idx * 2 + 1] = make_uint4(wl[0], wl[1], wl[2], wl[3]);
    } else {                // GEMM2 frags from w2 [128 out][256 k]
        int j = idx - 8192;
        int lane = j & 31, nq = (j >> 5) & 1, ks = (j >> 6) & 15, og = (j >> 10) & 3;
        int nb0 = og * 32 + nq * 16 + (lane >> 2);
        int kb = ks * 16 + (lane & 3) * 2;
        u32 wh[4], wl[4];
#pragma unroll
        for (int nb = 0; nb < 2; nb++)
#pragma unroll
            for (int r = 0; r < 2; r++) {
                const float* p = &w2[(nb0 + nb * 8) * 256 + kb + r * 8];
                u16 h0, l0, h1, l1;
                bsplit(p[0], h0, l0);
                bsplit(p[1], h1, l1);
                wh[nb * 2 + r] = (u32)h0 | ((u32)h1 << 16);
                wl[nb * 2 + r] = (u32)l0 | ((u32)l1 << 16);
            }
        g_f2[j * 2] = make_uint4(wh[0], wh[1], wh[2], wh[3]);
        g_f2[j * 2 + 1] = make_uint4(wl[0], wl[1], wl[2], wl[3]);
    }
    if (idx == 0) {
        const int* e32 = (const int*)edges;
        int nz = 0;
        for (int i = 0; i < 16; i++) nz |= e32[2 * i + 1];
        g_e64 = (nz == 0) ? 1 : 0;
    }
}

__global__ void k_zero() {
    int i = blockIdx.x * 256 + threadIdx.x;
    if (i < NN * DN) g_out[i] = 0.0f;
}

// ---------------------------------------------------------------------------
// x = h @ lin_w^T + lin_b   (32 nodes/CTA)
// ---------------------------------------------------------------------------
__global__ __launch_bounds__(256, 1) void k_lin(const float* __restrict__ h,
                                                const float* __restrict__ w,
                                                const float* __restrict__ b) {
    extern __shared__ float sm[];
    float* wT = sm;
    float* ins = sm + 128 * 132;
    float* bs = ins + 32 * 132;
    int tid = threadIdx.x, lane = tid & 31, warp = tid >> 5;
    int n0 = blockIdx.x * 32;

    for (int idx = tid; idx < 128 * 128; idx += 256) {
        int o = idx >> 7, k = idx & 127;
        wT[k * 132 + o] = w[idx];
    }
    if (tid < 128) bs[tid] = b[tid];
#pragma unroll
    for (int i = 0; i < 4; i++) {
        int nl = warp * 4 + i;
        float4 v = *(const float4*)&h[(size_t)(n0 + nl) * DN + lane * 4];
        *(float4*)&ins[nl * 132 + lane * 4] = v;
    }
    __syncthreads();

    float acc[4][4] = {};
    const float* inw = ins + warp * 4 * 132;
    for (int k = 0; k < 128; k++) {
        float a[4], wv[4];
#pragma unroll
        for (int i = 0; i < 4; i++) a[i] = inw[i * 132 + k];
#pragma unroll
        for (int j = 0; j < 4; j++) wv[j] = wT[k * 132 + lane + 32 * j];
#pragma unroll
        for (int i = 0; i < 4; i++)
#pragma unroll
            for (int j = 0; j < 4; j++) acc[i][j] += a[i] * wv[j];
    }
#pragma unroll
    for (int i = 0; i < 4; i++) {
        int nl = warp * 4 + i;
#pragma unroll
        for (int j = 0; j < 4; j++) {
            int o = lane + 32 * j;
            g_x[(size_t)(n0 + nl) * DN + o] = acc[i][j] + bs[o];
        }
    }
}

// ---------------------------------------------------------------------------
// Fused edge kernel: mma.sync bf16 hi/lo, B-frags direct from L2, 2 CTAs/SM.
// 64 edges/CTA, 8 warps = 2 edge-groups x 4 out-groups, warp tile 32x64.
// ---------------------------------------------------------------------------
__global__ __launch_bounds__(256, 2) void k_edge(
    const float* __restrict__ dist, const float* __restrict__ emask,
    const float* __restrict__ w1, const float* __restrict__ b1,
    const float* __restrict__ b2, const float* __restrict__ w3,
    const float* __restrict__ b3, const void* __restrict__ edges) {
    extern __shared__ char smc[];
    u32 smb = smem_u32(smc);
    float* smf = (float*)smc;
    int* rows = (int*)(smc + SB_ROWS);
    int* cols = (int*)(smc + SB_COLS);

    int tid = threadIdx.x, lane = tid & 31, warp = tid >> 5;
    int eg = warp & 1, og = warp >> 1;
    int Eb = eg * 32;
    int e0 = blockIdx.x * ET;

    // stage small vectors
    smf[SB_B1 / 4 + tid] = b1[tid];
    smf[SB_W1C / 4 + tid] = w1[tid * 257 + 256];
    if (tid < 128) {
        smf[SB_B2 / 4 + (tid & 127)] = b2[tid];
        smf[SB_W3 / 4 + (tid & 127)] = w3[tid];
    }
    if (tid < 64) {
        int e = e0 + tid;
        if (g_e64) {
            const long long* e64 = (const long long*)edges;
            rows[tid] = (int)e64[e];
            cols[tid] = (int)e64[EE + e];
        } else {
            const int* ei = (const int*)edges;
            rows[tid] = ei[e];
            cols[tid] = ei[EE + e];
        }
        float em = emask[e];
        smf[SB_EMS / 4 + tid] = em;
        smf[SB_DE / 4 + tid] = dist[e] * em;
    }
    __syncthreads();

    // ---- gather x_row / x_col -> A (bf16 hi/lo), k-halves: 0-127 row, 128-255 col
#pragma unroll
    for (int i = 0; i < 8; i++) {
        int el = warp * 8 + i;
        const float4 vr = *(const float4*)&g_x[(size_t)rows[el] * DN + lane * 4];
        const float4 vc = *(const float4*)&g_x[(size_t)cols[el] * DN + lane * 4];
        u16 h0, l0, h1, l1, h2, l2, h3, l3;
        bsplit(vr.x, h0, l0); bsplit(vr.y, h1, l1); bsplit(vr.z, h2, l2); bsplit(vr.w, h3, l3);
        u64 hp = (u64)h0 | ((u64)h1 << 16) | ((u64)h2 << 32) | ((u64)h3 << 48);
        u64 lp = (u64)l0 | ((u64)l1 << 16) | ((u64)l2 << 32) | ((u64)l3 << 48);
        *(u64*)(smc + SB_A_HI + el * ASTR + lane * 8) = hp;
        *(u64*)(smc + SB_A_LO + el * ASTR + lane * 8) = lp;
        bsplit(vc.x, h0, l0); bsplit(vc.y, h1, l1); bsplit(vc.z, h2, l2); bsplit(vc.w, h3, l3);
        hp = (u64)h0 | ((u64)h1 << 16) | ((u64)h2 << 32) | ((u64)h3 << 48);
        lp = (u64)l0 | ((u64)l1 << 16) | ((u64)l2 << 32) | ((u64)l3 << 48);
        *(u64*)(smc + SB_A_HI + el * ASTR + 256 + lane * 8) = hp;
        *(u64*)(smc + SB_A_LO + el * ASTR + 256 + lane * 8) = lp;
    }
    __syncthreads();

    // ---- GEMM1: D1[64e x 256o], warp slice 32e x 64o, K=256 (2 sides) ----
    float acc1[2][8][4] = {};   // [mtile][nblock][frag]
#pragma unroll
    for (int side = 0; side < 2; side++) {
#pragma unroll
        for (int ks = 0; ks < 8; ks++) {
            int ka = side * 128 + ks * 16;
            u32 ah[2][4], al_[2][4];
            ldmA(ah[0], smb + SB_A_HI, Eb, ka);
            ldmA(ah[1], smb + SB_A_HI, Eb + 16, ka);
            ldmA(al_[0], smb + SB_A_LO, Eb, ka);
            ldmA(al_[1], smb + SB_A_LO, Eb + 16, ka);
            int fbase = ((((og * 2 + side) * 8 + ks) * 4) * 32 + lane) * 2;
#pragma unroll
            for (int nq = 0; nq < 4; nq++) {
                uint4 fh = g_f1[fbase + nq * 64];
                uint4 fl = g_f1[fbase + nq * 64 + 1];
#pragma unroll
                for (int mt = 0; mt < 2; mt++) {
                    mma16816(acc1[mt][nq * 2], ah[mt], fh.x, fh.y);
                    mma16816(acc1[mt][nq * 2], ah[mt], fl.x, fl.y);
                    mma16816(acc1[mt][nq * 2], al_[mt], fh.x, fh.y);
                    mma16816(acc1[mt][nq * 2 + 1], ah[mt], fh.z, fh.w);
                    mma16816(acc1[mt][nq * 2 + 1], ah[mt], fl.z, fl.w);
                    mma16816(acc1[mt][nq * 2 + 1], al_[mt], fh.z, fh.w);
                }
            }
        }
    }
    __syncthreads();   // all warps done reading A -> safe to overlay h1

    // ---- epilogue1: + d*w1c + b1, silu, bf16-split -> h1 (A region) ----
    {
        int r0 = lane >> 2, cb = (lane & 3) * 2;
#pragma unroll
        for (int mt = 0; mt < 2; mt++) {
            int e_lo = Eb + mt * 16 + r0, e_hi = e_lo + 8;
            float de_lo = smf[SB_DE / 4 + e_lo], de_hi = smf[SB_DE / 4 + e_hi];
#pragma unroll
            for (int nb = 0; nb < 8; nb++) {
                int o = og * 64 + nb * 8 + cb;
                float b1a = smf[SB_B1 / 4 + o], b1b = smf[SB_B1 / 4 + o + 1];
                float wca = smf[SB_W1C / 4 + o], wcb = smf[SB_W1C / 4 + o + 1];
                float v0 = silu_(acc1[mt][nb][0] + de_lo * wca + b1a);
                float v1 = silu_(acc1[mt][nb][1] + de_lo * wcb + b1b);
                float v2 = silu_(acc1[mt][nb][2] + de_hi * wca + b1a);
                float v3 = silu_(acc1[mt][nb][3] + de_hi * wcb + b1b);
                u16 h0, l0, h1, l1;
                bsplit(v0, h0, l0); bsplit(v1, h1, l1);
                *(u32*)(smc + SB_A_HI + e_lo * ASTR + o * 2) = (u32)h0 | ((u32)h1 << 16);
                *(u32*)(smc + SB_A_LO + e_lo * ASTR + o * 2) = (u32)l0 | ((u32)l1 << 16);
                bsplit(v2, h0, l0); bsplit(v3, h1, l1);
                *(u32*)(smc + SB_A_HI + e_hi * ASTR + o * 2) = (u32)h0 | ((u32)h1 << 16);
                *(u32*)(smc + SB_A_LO + e_hi * ASTR + o * 2) = (u32)l0 | ((u32)l1 << 16);
            }
        }
    }
    __syncthreads();

    // ---- GEMM2: D2[64e x 128o], warp slice 32e x 32o, K=256 ----
    float acc2[2][4][4] = {};
#pragma unroll
    for (int ks = 0; ks < 16; ks++) {
        int ka = ks * 16;
        u32 ah[2][4], al_[2][4];
        ldmA(ah[0], smb + SB_A_HI, Eb, ka);
        ldmA(ah[1], smb + SB_A_HI, Eb + 16, ka);
        ldmA(al_[0], smb + SB_A_LO, Eb, ka);
        ldmA(al_[1], smb + SB_A_LO, Eb + 16, ka);
        int fbase = (((og * 16 + ks) * 2) * 32 + lane) * 2;
#pragma unroll
        for (int nq = 0; nq < 2; nq++) {
            uint4 fh = g_f2[fbase + nq * 64];
            uint4 fl = g_f2[fbase + nq * 64 + 1];
#pragma unroll
            for (int mt = 0; mt < 2; mt++) {
                mma16816(acc2[mt][nq * 2], ah[mt], fh.x, fh.y);
                mma16816(acc2[mt][nq * 2], ah[mt], fl.x, fl.y);
                mma16816(acc2[mt][nq * 2], al_[mt], fh.x, fh.y);
                mma16816(acc2[mt][nq * 2 + 1], ah[mt], fh.z, fh.w);
                mma16816(acc2[mt][nq * 2 + 1], ah[mt], fl.z, fl.w);
                mma16816(acc2[mt][nq * 2 + 1], al_[mt], fh.z, fh.w);
            }
        }
    }

    // ---- epilogue2: att partials, cross-og combine ----
    {
        int r0 = lane >> 2, cb = (lane & 3) * 2;
        float p[2][2] = {};
#pragma unroll
        for (int mt = 0; mt < 2; mt++)
#pragma unroll
            for (int nb = 0; nb < 4; nb++) {
                int o = og * 32 + nb * 8 + cb;
                float b2a = smf[SB_B2 / 4 + o], b2b = smf[SB_B2 / 4 + o + 1];
                float w3a = smf[SB_W3 / 4 + o], w3b = smf[SB_W3 / 4 + o + 1];
                p[mt][0] += silu_(acc2[mt][nb][0] + b2a) * w3a + silu_(acc2[mt][nb][1] + b2b) * w3b;
                p[mt][1] += silu_(acc2[mt][nb][2] + b2a) * w3a + silu_(acc2[mt][nb][3] + b2b) * w3b;
            }
#pragma unroll
        for (int off = 1; off <= 2; off <<= 1)
#pragma unroll
            for (int mt = 0; mt < 2; mt++) {
                p[mt][0] += __shfl_xor_sync(0xffffffffu, p[mt][0], off);
                p[mt][1] += __shfl_xor_sync(0xffffffffu, p[mt][1], off);
            }
        if ((lane & 3) == 0) {
#pragma unroll
            for (int mt = 0; mt < 2; mt++) {
                int e = Eb + mt * 16 + r0;
                smf[SB_PART / 4 + og * 64 + e] = p[mt][0];
                smf[SB_PART / 4 + og * 64 + e + 8] = p[mt][1];
            }
        }
    }
    __syncthreads();
    if (tid < 64) {
        float z = smf[SB_PART / 4 + tid] + smf[SB_PART / 4 + 64 + tid] +
                  smf[SB_PART / 4 + 128 + tid] + smf[SB_PART / 4 + 192 + tid] + b3[0];
        smf[SB_ATT / 4 + tid] = sigm(z) * smf[SB_EMS / 4 + tid];
    }
    __syncthreads();

    // ---- scatter: g_out[row] += x_col * att ----
#pragma unroll
    for (int i = 0; i < 8; i++) {
        int el = warp * 8 + i;
        float a = smf[SB_ATT / 4 + el];
        const float4 v = *(const float4*)&g_x[(size_t)cols[el] * DN + lane * 4];
        float* dst = &g_out[(size_t)rows[el] * DN + lane * 4];
        atomicAdd(dst + 0, v.x * a);
        atomicAdd(dst + 1, v.y * a);
        atomicAdd(dst + 2, v.z * a);
        atomicAdd(dst + 3, v.w * a);
    }
}

// ---------------------------------------------------------------------------
// node_mlp + residual + final LN + silu.   32 nodes/CTA.
// ---------------------------------------------------------------------------
__global__ __launch_bounds__(256, 1) void k_node(
    const float* __restrict__ w1, const float* __restrict__ b1,
    const float* __restrict__ g1, const float* __restrict__ bb1,
    const float* __restrict__ w2, const float* __restrict__ b2,
    const float* __restrict__ g2, const float* __restrict__ bb2,
    float* __restrict__ out) {
    extern __shared__ float sm[];
    float* w1T = sm;
    float* w2T = w1T + 16896;
    float* ins = w2T + 16896;
    float* mids = ins + 4224;
    float* b1s = mids + 4224;
    float* b2s = b1s + 128;
    int tid = threadIdx.x, lane = tid & 31, warp = tid >> 5;
    int n0 = blockIdx.x * 32;

    for (int idx = tid; idx < 128 * 128; idx += 256) {
        int o = idx >> 7, k = idx & 127;
        w1T[k * 132 + o] = w1[idx];
        w2T[k * 132 + o] = w2[idx];
    }
    if (tid < 128) { b1s[tid] = b1[tid]; b2s[tid] = b2[tid]; }
#pragma unroll
    for (int i = 0; i < 4; i++) {
        int nl = warp * 4 + i;
        float4 v = *(const float4*)&g_out[(size_t)(n0 + nl) * DN + lane * 4];
        v.x *= 0.01f; v.y *= 0.01f; v.z *= 0.01f; v.w *= 0.01f;
        *(float4*)&ins[nl * 132 + lane * 4] = v;
    }
    __syncthreads();

    float acc[4][4] = {};
    {
        const float* inw = ins + warp * 4 * 132;
        for (int k = 0; k < 128; k++) {
            float a[4], wv[4];
#pragma unroll
            for (int i = 0; i < 4; i++) a[i] = inw[i * 132 + k];
#pragma unroll
            for (int j = 0; j < 4; j++) wv[j] = w1T[k * 132 + lane + 32 * j];
#pragma unroll
            for (int i = 0; i < 4; i++)
#pragma unroll
                for (int j = 0; j < 4; j++) acc[i][j] += a[i] * wv[j];
        }
    }
    float lg1[4], lb1[4];
#pragma unroll
    for (int j = 0; j < 4; j++) { int o = lane + 32 * j; lg1[j] = g1[o]; lb1[j] = bb1[o]; }
#pragma unroll
    for (int i = 0; i < 4; i++) {
        float v[4], s1 = 0.f, s2 = 0.f;
#pragma unroll
        for (int j = 0; j < 4; j++) {
            v[j] = acc[i][j] + b1s[lane + 32 * j];
            s1 += v[j]; s2 += v[j] * v[j];
        }
#pragma unroll
        for (int off = 16; off > 0; off >>= 1) {
            s1 += __shfl_xor_sync(0xffffffffu, s1, off);
            s2 += __shfl_xor_sync(0xffffffffu, s2, off);
        }
        float mean = s1 * (1.0f / 128.0f);
        float var = s2 * (1.0f / 128.0f) - mean * mean;
        float inv = rsqrtf(var + 1e-5f);
        int nl = warp * 4 + i;
#pragma unroll
        for (int j = 0; j < 4; j++) {
            float y = (v[j] - mean) * inv * lg1[j] + lb1[j];
            mids[nl * 132 + lane + 32 * j] = silu_(y);
        }
    }
    __syncthreads();

    float acc2[4][4] = {};
    {
        const float* mw = mids + warp * 4 * 132;
        for (int k = 0; k < 128; k++) {
            float a[4], wv[4];
#pragma unroll
            for (int i = 0; i < 4; i++) a[i] = mw[i * 132 + k];
#pragma unroll
            for (int j = 0; j < 4; j++) wv[j] = w2T[k * 132 + lane + 32 * j];
#pragma unroll
            for (int i = 0; i < 4; i++)
#pragma unroll
                for (int j = 0; j < 4; j++) acc2[i][j] += a[i] * wv[j];
        }
    }
    float lg2[4], lb2[4];
#pragma unroll
    for (int j = 0; j < 4; j++) { int o = lane + 32 * j; lg2[j] = g2[o]; lb2[j] = bb2[o]; }
#pragma unroll
    for (int i = 0; i < 4; i++) {
        int nl = warp * 4 + i;
        float v[4], s1 = 0.f, s2 = 0.f;
#pragma unroll
        for (int j = 0; j < 4; j++) {
            int o = lane + 32 * j;
            v[j] = acc2[i][j] + b2s[o] + g_x[(size_t)(n0 + nl) * DN + o];
            s1 += v[j]; s2 += v[j] * v[j];
        }
#pragma unroll
        for (int off = 16; off > 0; off >>= 1) {
            s1 += __shfl_xor_sync(0xffffffffu, s1, off);
            s2 += __shfl_xor_sync(0xffffffffu, s2, off);
        }
        float mean = s1 * (1.0f / 128.0f);
        float var = s2 * (1.0f / 128.0f) - mean * mean;
        float inv = rsqrtf(var + 1e-5f);
#pragma unroll
        for (int j = 0; j < 4; j++) {
            int o = lane + 32 * j;
            float y = (v[j] - mean) * inv * lg2[j] + lb2[j];
            out[(size_t)(n0 + nl) * DN + o] = silu_(y);
        }
    }
}

// ---------------------------------------------------------------------------
extern "C" void kernel_launch(void* const* d_in, const int* in_sizes, int n_in,
                              void* d_out, int out_size) {
    const float* h = (const float*)d_in[0];
    const float* distances = (const float*)d_in[1];
    const float* edge_mask = (const float*)d_in[3];
    const float* lin_w = (const float*)d_in[4];
    const float* lin_b = (const float*)d_in[5];
    const float* att_w1 = (const float*)d_in[6];
    const float* att_b1 = (const float*)d_in[7];
    const float* att_w2 = (const float*)d_in[8];
    const float* att_b2 = (const float*)d_in[9];
    const float* att_w3 = (const float*)d_in[10];
    const float* att_b3 = (const float*)d_in[11];
    const float* nm_w1 = (const float*)d_in[12];
    const float* nm_b1 = (const float*)d_in[13];
    const float* nm_ln_g = (const float*)d_in[14];
    const float* nm_ln_b = (const float*)d_in[15];
    const float* nm_w2 = (const float*)d_in[16];
    const float* nm_b2 = (const float*)d_in[17];
    const float* ln_g = (const float*)d_in[18];
    const float* ln_b = (const float*)d_in[19];
    const void* edges = d_in[20];

    cudaFuncSetAttribute(k_lin, cudaFuncAttributeMaxDynamicSharedMemorySize, 84992);
    cudaFuncSetAttribute(k_edge, cudaFuncAttributeMaxDynamicSharedMemorySize, SMEM_EDGE);
    cudaFuncSetAttribute(k_node, cudaFuncAttributeMaxDynamicSharedMemorySize, 169984);

    k_prep<<<48, 256>>>(att_w1, att_w2, edges);
    k_zero<<<(NN * DN + 255) / 256, 256>>>();
    k_lin<<<625, 256, 84992>>>(h, lin_w, lin_b);
    k_edge<<<NCTA, 256, SMEM_EDGE>>>(distances, edge_mask, att_w1, att_b1,
                                     att_b2, att_w3, att_b3, edges);
    k_node<<<625, 256, 169984>>>(nm_w1, nm_b1, nm_ln_g, nm_ln_b,
                                 nm_w2, nm_b2, ln_g, ln_b, (float*)d_out);
}

// round 6
// speedup vs baseline: 5.5678x; 1.6372x over previous
#include <cuda_runtime.h>
#include <cuda_bf16.h>

typedef unsigned int u32;
typedef unsigned long long u64;
typedef unsigned short u16;

#define DN 128
#define NN 20000
#define EE 640000
#define ET 64                   // edges per CTA
#define NCTA (EE / ET)          // 10000
#define ASTR 528                // h1 row stride bytes (264 halves)
#define YSTR 272                // x row stride bytes in k_y (136 halves)

// ---------------- device globals (no runtime alloc) ----------------
__device__ float g_x[NN * DN];
__device__ float g_out[NN * DN];
__device__ float g_ya[NN * 256];   // x@W1a^T + b1
__device__ float g_yb[NN * 256];   // x@W1b^T
__device__ int g_e64;
// pre-packed B fragments in per-lane mma order (hi,lo interleaved uint4 pairs)
__device__ uint4 g_f1[16384];   // W1: [og4][side2][ks8][nq4][lane32][hi/lo]
__device__ uint4 g_f2[8192];    // W2: [og4][ks16][nq2][lane32][hi/lo]

// ---------------- k_edge smem layout (bytes) ----------------
#define SB_ROWS 0
#define SB_COLS 256
#define SB_DE   512
#define SB_EMS  768
#define SB_ATT  1024
#define SB_PART 1280
#define SB_B2   2304
#define SB_W3   2816
#define SB_W1C  3328
#define SB_A_HI 4352            // 64 x 528 = 33792
#define SB_A_LO 38144           // 33792
#define SMEM_EDGE 71936

// ---------------- k_y smem layout ----------------
#define SY_A_HI 0               // 32 x 272 = 8704
#define SY_A_LO 8704
#define SY_B1   17408           // 256 f
#define SMEM_Y  18432

__device__ __forceinline__ u32 smem_u32(const void* p) {
    u32 a;
    asm("{ .reg .u64 t; cvta.to.shared.u64 t, %1; cvt.u32.u64 %0, t; }" : "=r"(a) : "l"(p));
    return a;
}
__device__ __forceinline__ float sigm(float v) { return 1.0f / (1.0f + __expf(-v)); }
__device__ __forceinline__ float silu_(float v) { return v * sigm(v); }

__device__ __forceinline__ void bsplit(float v, u16& h, u16& l) {
    __nv_bfloat16 hb = __float2bfloat16(v);
    __nv_bfloat16 lb = __float2bfloat16(v - __bfloat162float(hb));
    h = __bfloat16_as_ushort(hb);
    l = __bfloat16_as_ushort(lb);
}

// ldmatrix m16k16 (A, row-major, stride S bytes)
template <int S>
__device__ __forceinline__ void ldmA(u32 r[4], u32 base, int row0, int kh) {
    int lane = threadIdx.x & 31;
    int quad = lane >> 3;
    u32 addr = base + (u32)(row0 + (lane & 7) + (quad & 1) * 8) * S +
               (u32)kh * 2 + (u32)(quad >> 1) * 16;
    asm volatile("ldmatrix.sync.aligned.m8n8.x4.shared.b16 {%0,%1,%2,%3}, [%4];"
                 : "=r"(r[0]), "=r"(r[1]), "=r"(r[2]), "=r"(r[3]) : "r"(addr));
}
__device__ __forceinline__ void mma16816(float d[4], const u32 a[4], u32 b0, u32 b1) {
    asm volatile("mma.sync.aligned.m16n8k16.row.col.f32.bf16.bf16.f32 "
                 "{%0,%1,%2,%3}, {%4,%5,%6,%7}, {%8,%9}, {%0,%1,%2,%3};"
                 : "+f"(d[0]), "+f"(d[1]), "+f"(d[2]), "+f"(d[3])
                 : "r"(a[0]), "r"(a[1]), "r"(a[2]), "r"(a[3]), "r"(b0), "r"(b1));
}

// ---------------------------------------------------------------------------
// k_prep: pack W1/W2 into per-lane B-fragment tables (hi/lo bf16 split).
// ---------------------------------------------------------------------------
__global__ void k_prep(const float* __restrict__ w1, const float* __restrict__ w2,
                       const void* __restrict__ edges) {
    int idx = blockIdx.x * 256 + threadIdx.x;
    if (idx < 8192) {       // W1 frags [256 out][257 k]
        int lane = idx & 31, nq = (idx >> 5) & 3, ks = (idx >> 7) & 7;
        int side = (idx >> 10) & 1, og = (idx >> 11) & 3;
        int nb0 = og * 64 + nq * 16 + (lane >> 2);
        int kb = side * 128 + ks * 16 + (lane & 3) * 2;
        u32 wh[4], wl[4];
#pragma unroll
        for (int nb = 0; nb < 2; nb++)
#pragma unroll
            for (int r = 0; r < 2; r++) {
                const float* p = &w1[(nb0 + nb * 8) * 257 + kb + r * 8];
                u16 h0, l0, h1, l1;
                bsplit(p[0], h0, l0);
                bsplit(p[1], h1, l1);
                wh[nb * 2 + r] = (u32)h0 | ((u32)h1 << 16);
                wl[nb * 2 + r] = (u32)l0 | ((u32)l1 << 16);
            }
        g_f1[idx * 2] = make_uint4(wh[0], wh[1], wh[2], wh[3]);
        g_f1[idx * 2 + 1] = make_uint4(wl[0], wl[1], wl[2], wl[3]);
    } else {                // W2 frags [128 out][256 k]
        int j = idx - 8192;
        int lane = j & 31, nq = (j >> 5) & 1, ks = (j >> 6) & 15, og = (j >> 10) & 3;
        int nb0 = og * 32 + nq * 16 + (lane >> 2);
        int kb = ks * 16 + (lane & 3) * 2;
        u32 wh[4], wl[4];
#pragma unroll
        for (int nb = 0; nb < 2; nb++)
#pragma unroll
            for (int r = 0; r < 2; r++) {
                const float* p = &w2[(nb0 + nb * 8) * 256 + kb + r * 8];
                u16 h0, l0, h1, l1;
                bsplit(p[0], h0, l0);
                bsplit(p[1], h1, l1);
                wh[nb * 2 + r] = (u32)h0 | ((u32)h1 << 16);
                wl[nb * 2 + r] = (u32)l0 | ((u32)l1 << 16);
            }
        g_f2[j * 2] = make_uint4(wh[0], wh[1], wh[2], wh[3]);
        g_f2[j * 2 + 1] = make_uint4(wl[0], wl[1], wl[2], wl[3]);
    }
    if (idx == 0) {
        const int* e32 = (const int*)edges;
        int nz = 0;
        for (int i = 0; i < 16; i++) nz |= e32[2 * i + 1];
        g_e64 = (nz == 0) ? 1 : 0;
    }
}

__global__ void k_zero() {
    int i = blockIdx.x * 256 + threadIdx.x;
    if (i < NN * DN) g_out[i] = 0.0f;
}

// ---------------------------------------------------------------------------
// x = h @ lin_w^T + lin_b   (32 nodes/CTA)
// ---------------------------------------------------------------------------
__global__ __launch_bounds__(256, 1) void k_lin(const float* __restrict__ h,
                                                const float* __restrict__ w,
                                                const float* __restrict__ b) {
    extern __shared__ float sm[];
    float* wT = sm;
    float* ins = sm + 128 * 132;
    float* bs = ins + 32 * 132;
    int tid = threadIdx.x, lane = tid & 31, warp = tid >> 5;
    int n0 = blockIdx.x * 32;

    for (int idx = tid; idx < 128 * 128; idx += 256) {
        int o = idx >> 7, k = idx & 127;
        wT[k * 132 + o] = w[idx];
    }
    if (tid < 128) bs[tid] = b[tid];
#pragma unroll
    for (int i = 0; i < 4; i++) {
        int nl = warp * 4 + i;
        float4 v = *(const float4*)&h[(size_t)(n0 + nl) * DN + lane * 4];
        *(float4*)&ins[nl * 132 + lane * 4] = v;
    }
    __syncthreads();

    float acc[4][4] = {};
    const float* inw = ins + warp * 4 * 132;
    for (int k = 0; k < 128; k++) {
        float a[4], wv[4];
#pragma unroll
        for (int i = 0; i < 4; i++) a[i] = inw[i * 132 + k];
#pragma unroll
        for (int j = 0; j < 4; j++) wv[j] = wT[k * 132 + lane + 32 * j];
#pragma unroll
        for (int i = 0; i < 4; i++)
#pragma unroll
            for (int j = 0; j < 4; j++) acc[i][j] += a[i] * wv[j];
    }
#pragma unroll
    for (int i = 0; i < 4; i++) {
        int nl = warp * 4 + i;
#pragma unroll
        for (int j = 0; j < 4; j++) {
            int o = lane + 32 * j;
            g_x[(size_t)(n0 + nl) * DN + o] = acc[i][j] + bs[o];
        }
    }
}

// ---------------------------------------------------------------------------
// k_y: per-node halves of GEMM1.  ya = x@W1a^T + b1, yb = x@W1b^T.
// 32 nodes/CTA, 8 warps: warp w<4 -> ya outs [w*64,w*64+64), w>=4 -> yb.
// ---------------------------------------------------------------------------
__global__ __launch_bounds__(256, 1) void k_y(const float* __restrict__ b1) {
    extern __shared__ char smc[];
    u32 smb = smem_u32(smc);
    float* b1s = (float*)(smc + SY_B1);
    int tid = threadIdx.x, lane = tid & 31, warp = tid >> 5;
    int n0 = blockIdx.x * 32;

    b1s[tid] = b1[tid];
    // gather x (hi/lo split) — warp handles 4 nodes
#pragma unroll
    for (int i = 0; i < 4; i++) {
        int el = warp * 4 + i;
        const float4 v = *(const float4*)&g_x[(size_t)(n0 + el) * DN + lane * 4];
        u16 h0, l0, h1, l1, h2, l2, h3, l3;
        bsplit(v.x, h0, l0); bsplit(v.y, h1, l1); bsplit(v.z, h2, l2); bsplit(v.w, h3, l3);
        u64 hp = (u64)h0 | ((u64)h1 << 16) | ((u64)h2 << 32) | ((u64)h3 << 48);
        u64 lp = (u64)l0 | ((u64)l1 << 16) | ((u64)l2 << 32) | ((u64)l3 << 48);
        *(u64*)(smc + SY_A_HI + el * YSTR + lane * 8) = hp;
        *(u64*)(smc + SY_A_LO + el * YSTR + lane * 8) = lp;
    }
    __syncthreads();

    int side = warp >> 2, og1 = warp & 3;
    float acc[2][8][4] = {};
#pragma unroll
    for (int ks = 0; ks < 8; ks++) {
        int ka = ks * 16;
        u32 ah[2][4], al_[2][4];
        ldmA<YSTR>(ah[0], smb + SY_A_HI, 0, ka);
        ldmA<YSTR>(ah[1], smb + SY_A_HI, 16, ka);
        ldmA<YSTR>(al_[0], smb + SY_A_LO, 0, ka);
        ldmA<YSTR>(al_[1], smb + SY_A_LO, 16, ka);
        int fbase = ((((og1 * 2 + side) * 8 + ks) * 4) * 32 + lane) * 2;
#pragma unroll
        for (int nq = 0; nq < 4; nq++) {
            uint4 fh = g_f1[fbase + nq * 64];
            uint4 fl = g_f1[fbase + nq * 64 + 1];
#pragma unroll
            for (int mt = 0; mt < 2; mt++) {
                mma16816(acc[mt][nq * 2], ah[mt], fh.x, fh.y);
                mma16816(acc[mt][nq * 2], ah[mt], fl.x, fl.y);
                mma16816(acc[mt][nq * 2], al_[mt], fh.x, fh.y);
                mma16816(acc[mt][nq * 2 + 1], ah[mt], fh.z, fh.w);
                mma16816(acc[mt][nq * 2 + 1], ah[mt], fl.z, fl.w);
                mma16816(acc[mt][nq * 2 + 1], al_[mt], fh.z, fh.w);
            }
        }
    }
    // epilogue: store (ya += b1)
    {
        int r0 = lane >> 2, cb = (lane & 3) * 2;
        float* dst = side == 0 ? g_ya : g_yb;
#pragma unroll
        for (int mt = 0; mt < 2; mt++) {
            int node = n0 + mt * 16 + r0;
#pragma unroll
            for (int nb = 0; nb < 8; nb++) {
                int o = og1 * 64 + nb * 8 + cb;
                float ba = side == 0 ? b1s[o] : 0.0f;
                float bb = side == 0 ? b1s[o + 1] : 0.0f;
                float2 v0 = make_float2(acc[mt][nb][0] + ba, acc[mt][nb][1] + bb);
                float2 v1 = make_float2(acc[mt][nb][2] + ba, acc[mt][nb][3] + bb);
                *(float2*)&dst[(size_t)node * 256 + o] = v0;
                *(float2*)&dst[(size_t)(node + 8) * 256 + o] = v1;
            }
        }
    }
}

// ---------------------------------------------------------------------------
// Fused edge kernel: gather ya/yb -> silu -> GEMM2 (mma bf16 hi/lo) -> att
// -> scatter.  64 edges/CTA, 8 warps = 2 eg x 4 og for GEMM2. 3 CTAs/SM.
// ---------------------------------------------------------------------------
__global__ __launch_bounds__(256, 3) void k_edge(
    const float* __restrict__ dist, const float* __restrict__ emask,
    const float* __restrict__ w1, const float* __restrict__ b2,
    const float* __restrict__ w3, const float* __restrict__ b3,
    const void* __restrict__ edges) {
    extern __shared__ char smc[];
    u32 smb = smem_u32(smc);
    float* smf = (float*)smc;
    int* rows = (int*)(smc + SB_ROWS);
    int* cols = (int*)(smc + SB_COLS);

    int tid = threadIdx.x, lane = tid & 31, warp = tid >> 5;
    int eg = warp & 1, og = warp >> 1;
    int Eb = eg * 32;
    int e0 = blockIdx.x * ET;

    // stage small vectors
    smf[SB_W1C / 4 + tid] = w1[tid * 257 + 256];
    if (tid < 128) {
        smf[SB_B2 / 4 + tid] = b2[tid];
        smf[SB_W3 / 4 + tid] = w3[tid];
    }
    if (tid < 64) {
        int e = e0 + tid;
        if (g_e64) {
            const long long* e64 = (const long long*)edges;
            rows[tid] = (int)e64[e];
            cols[tid] = (int)e64[EE + e];
        } else {
            const int* ei = (const int*)edges;
            rows[tid] = ei[e];
            cols[tid] = ei[EE + e];
        }
        float em = emask[e];
        smf[SB_EMS / 4 + tid] = em;
        smf[SB_DE / 4 + tid] = dist[e] * em;
    }
    __syncthreads();

    // ---- gather ya[row]+yb[col]+de*w1c -> silu -> h1 bf16 hi/lo tile ----
#pragma unroll
    for (int i = 0; i < 8; i++) {
        int el = warp * 8 + i;
        const float* ya = &g_ya[(size_t)rows[el] * 256];
        const float* yb = &g_yb[(size_t)cols[el] * 256];
        float de = smf[SB_DE / 4 + el];
#pragma unroll
        for (int j = 0; j < 2; j++) {
            int o4 = lane * 4 + j * 128;
            float4 a4 = *(const float4*)(ya + o4);
            float4 b4 = *(const float4*)(yb + o4);
            float4 wc = *(const float4*)(smf + SB_W1C / 4 + o4);
            float v0 = silu_(a4.x + b4.x + de * wc.x);
            float v1 = silu_(a4.y + b4.y + de * wc.y);
            float v2 = silu_(a4.z + b4.z + de * wc.z);
            float v3 = silu_(a4.w + b4.w + de * wc.w);
            u16 h0, l0, h1, l1, h2, l2, h3, l3;
            bsplit(v0, h0, l0); bsplit(v1, h1, l1); bsplit(v2, h2, l2); bsplit(v3, h3, l3);
            u64 hp = (u64)h0 | ((u64)h1 << 16) | ((u64)h2 << 32) | ((u64)h3 << 48);
            u64 lp = (u64)l0 | ((u64)l1 << 16) | ((u64)l2 << 32) | ((u64)l3 << 48);
            *(u64*)(smc + SB_A_HI + el * ASTR + o4 * 2) = hp;
            *(u64*)(smc + SB_A_LO + el * ASTR + o4 * 2) = lp;
        }
    }
    __syncthreads();

    // ---- GEMM2: D2[64e x 128o], warp slice 32e x 32o, K=256 ----
    float acc2[2][4][4] = {};
#pragma unroll
    for (int ks = 0; ks < 16; ks++) {
        int ka = ks * 16;
        u32 ah[2][4], al_[2][4];
        ldmA<ASTR>(ah[0], smb + SB_A_HI, Eb, ka);
        ldmA<ASTR>(ah[1], smb + SB_A_HI, Eb + 16, ka);
        ldmA<ASTR>(al_[0], smb + SB_A_LO, Eb, ka);
        ldmA<ASTR>(al_[1], smb + SB_A_LO, Eb + 16, ka);
        int fbase = (((og * 16 + ks) * 2) * 32 + lane) * 2;
#pragma unroll
        for (int nq = 0; nq < 2; nq++) {
            uint4 fh = g_f2[fbase + nq * 64];
            uint4 fl = g_f2[fbase + nq * 64 + 1];
#pragma unroll
            for (int mt = 0; mt < 2; mt++) {
                mma16816(acc2[mt][nq * 2], ah[mt], fh.x, fh.y);
                mma16816(acc2[mt][nq * 2], ah[mt], fl.x, fl.y);
                mma16816(acc2[mt][nq * 2], al_[mt], fh.x, fh.y);
                mma16816(acc2[mt][nq * 2 + 1], ah[mt], fh.z, fh.w);
                mma16816(acc2[mt][nq * 2 + 1], ah[mt], fl.z, fl.w);
                mma16816(acc2[mt][nq * 2 + 1], al_[mt], fh.z, fh.w);
            }
        }
    }

    // ---- epilogue2: att partials, cross-og combine ----
    {
        int r0 = lane >> 2, cb = (lane & 3) * 2;
        float p[2][2] = {};
#pragma unroll
        for (int mt = 0; mt < 2; mt++)
#pragma unroll
            for (int nb = 0; nb < 4; nb++) {
                int o = og * 32 + nb * 8 + cb;
                float b2a = smf[SB_B2 / 4 + o], b2b = smf[SB_B2 / 4 + o + 1];
                float w3a = smf[SB_W3 / 4 + o], w3b = smf[SB_W3 / 4 + o + 1];
                p[mt][0] += silu_(acc2[mt][nb][0] + b2a) * w3a + silu_(acc2[mt][nb][1] + b2b) * w3b;
                p[mt][1] += silu_(acc2[mt][nb][2] + b2a) * w3a + silu_(acc2[mt][nb][3] + b2b) * w3b;
            }
#pragma unroll
        for (int off = 1; off <= 2; off <<= 1)
#pragma unroll
            for (int mt = 0; mt < 2; mt++) {
                p[mt][0] += __shfl_xor_sync(0xffffffffu, p[mt][0], off);
                p[mt][1] += __shfl_xor_sync(0xffffffffu, p[mt][1], off);
            }
        if ((lane & 3) == 0) {
#pragma unroll
            for (int mt = 0; mt < 2; mt++) {
                int e = Eb + mt * 16 + r0;
                smf[SB_PART / 4 + og * 64 + e] = p[mt][0];
                smf[SB_PART / 4 + og * 64 + e + 8] = p[mt][1];
            }
        }
    }
    __syncthreads();
    if (tid < 64) {
        float z = smf[SB_PART / 4 + tid] + smf[SB_PART / 4 + 64 + tid] +
                  smf[SB_PART / 4 + 128 + tid] + smf[SB_PART / 4 + 192 + tid] + b3[0];
        smf[SB_ATT / 4 + tid] = sigm(z) * smf[SB_EMS / 4 + tid];
    }
    __syncthreads();

    // ---- scatter: g_out[row] += x_col * att ----
#pragma unroll
    for (int i = 0; i < 8; i++) {
        int el = warp * 8 + i;
        float a = smf[SB_ATT / 4 + el];
        const float4 v = *(const float4*)&g_x[(size_t)cols[el] * DN + lane * 4];
        float* dst = &g_out[(size_t)rows[el] * DN + lane * 4];
        atomicAdd(dst + 0, v.x * a);
        atomicAdd(dst + 1, v.y * a);
        atomicAdd(dst + 2, v.z * a);
        atomicAdd(dst + 3, v.w * a);
    }
}

// ---------------------------------------------------------------------------
// node_mlp + residual + final LN + silu.   32 nodes/CTA.
// ---------------------------------------------------------------------------
__global__ __launch_bounds__(256, 1) void k_node(
    const float* __restrict__ w1, const float* __restrict__ b1,
    const float* __restrict__ g1, const float* __restrict__ bb1,
    const float* __restrict__ w2, const float* __restrict__ b2,
    const float* __restrict__ g2, const float* __restrict__ bb2,
    float* __restrict__ out) {
    extern __shared__ float sm[];
    float* w1T = sm;
    float* w2T = w1T + 16896;
    float* ins = w2T + 16896;
    float* mids = ins + 4224;
    float* b1s = mids + 4224;
    float* b2s = b1s + 128;
    int tid = threadIdx.x, lane = tid & 31, warp = tid >> 5;
    int n0 = blockIdx.x * 32;

    for (int idx = tid; idx < 128 * 128; idx += 256) {
        int o = idx >> 7, k = idx & 127;
        w1T[k * 132 + o] = w1[idx];
        w2T[k * 132 + o] = w2[idx];
    }
    if (tid < 128) { b1s[tid] = b1[tid]; b2s[tid] = b2[tid]; }
#pragma unroll
    for (int i = 0; i < 4; i++) {
        int nl = warp * 4 + i;
        float4 v = *(const float4*)&g_out[(size_t)(n0 + nl) * DN + lane * 4];
        v.x *= 0.01f; v.y *= 0.01f; v.z *= 0.01f; v.w *= 0.01f;
        *(float4*)&ins[nl * 132 + lane * 4] = v;
    }
    __syncthreads();

    float acc[4][4] = {};
    {
        const float* inw = ins + warp * 4 * 132;
        for (int k = 0; k < 128; k++) {
            float a[4], wv[4];
#pragma unroll
            for (int i = 0; i < 4; i++) a[i] = inw[i * 132 + k];
#pragma unroll
            for (int j = 0; j < 4; j++) wv[j] = w1T[k * 132 + lane + 32 * j];
#pragma unroll
            for (int i = 0; i < 4; i++)
#pragma unroll
                for (int j = 0; j < 4; j++) acc[i][j] += a[i] * wv[j];
        }
    }
    float lg1[4], lb1[4];
#pragma unroll
    for (int j = 0; j < 4; j++) { int o = lane + 32 * j; lg1[j] = g1[o]; lb1[j] = bb1[o]; }
#pragma unroll
    for (int i = 0; i < 4; i++) {
        float v[4], s1 = 0.f, s2 = 0.f;
#pragma unroll
        for (int j = 0; j < 4; j++) {
            v[j] = acc[i][j] + b1s[lane + 32 * j];
            s1 += v[j]; s2 += v[j] * v[j];
        }
#pragma unroll
        for (int off = 16; off > 0; off >>= 1) {
            s1 += __shfl_xor_sync(0xffffffffu, s1, off);
            s2 += __shfl_xor_sync(0xffffffffu, s2, off);
        }
        float mean = s1 * (1.0f / 128.0f);
        float var = s2 * (1.0f / 128.0f) - mean * mean;
        float inv = rsqrtf(var + 1e-5f);
        int nl = warp * 4 + i;
#pragma unroll
        for (int j = 0; j < 4; j++) {
            float y = (v[j] - mean) * inv * lg1[j] + lb1[j];
            mids[nl * 132 + lane + 32 * j] = silu_(y);
        }
    }
    __syncthreads();

    float acc2[4][4] = {};
    {
        const float* mw = mids + warp * 4 * 132;
        for (int k = 0; k < 128; k++) {
            float a[4], wv[4];
#pragma unroll
            for (int i = 0; i < 4; i++) a[i] = mw[i * 132 + k];
#pragma unroll
            for (int j = 0; j < 4; j++) wv[j] = w2T[k * 132 + lane + 32 * j];
#pragma unroll
            for (int i = 0; i < 4; i++)
#pragma unroll
                for (int j = 0; j < 4; j++) acc2[i][j] += a[i] * wv[j];
        }
    }
    float lg2[4], lb2[4];
#pragma unroll
    for (int j = 0; j < 4; j++) { int o = lane + 32 * j; lg2[j] = g2[o]; lb2[j] = bb2[o]; }
#pragma unroll
    for (int i = 0; i < 4; i++) {
        int nl = warp * 4 + i;
        float v[4], s1 = 0.f, s2 = 0.f;
#pragma unroll
        for (int j = 0; j < 4; j++) {
            int o = lane + 32 * j;
            v[j] = acc2[i][j] + b2s[o] + g_x[(size_t)(n0 + nl) * DN + o];
            s1 += v[j]; s2 += v[j] * v[j];
        }
#pragma unroll
        for (int off = 16; off > 0; off >>= 1) {
            s1 += __shfl_xor_sync(0xffffffffu, s1, off);
            s2 += __shfl_xor_sync(0xffffffffu, s2, off);
        }
        float mean = s1 * (1.0f / 128.0f);
        float var = s2 * (1.0f / 128.0f) - mean * mean;
        float inv = rsqrtf(var + 1e-5f);
#pragma unroll
        for (int j = 0; j < 4; j++) {
            int o = lane + 32 * j;
            float y = (v[j] - mean) * inv * lg2[j] + lb2[j];
            out[(size_t)(n0 + nl) * DN + o] = silu_(y);
        }
    }
}

// ---------------------------------------------------------------------------
extern "C" void kernel_launch(void* const* d_in, const int* in_sizes, int n_in,
                              void* d_out, int out_size) {
    const float* h = (const float*)d_in[0];
    const float* distances = (const float*)d_in[1];
    const float* edge_mask = (const float*)d_in[3];
    const float* lin_w = (const float*)d_in[4];
    const float* lin_b = (const float*)d_in[5];
    const float* att_w1 = (const float*)d_in[6];
    const float* att_b1 = (const float*)d_in[7];
    const float* att_w2 = (const float*)d_in[8];
    const float* att_b2 = (const float*)d_in[9];
    const float* att_w3 = (const float*)d_in[10];
    const float* att_b3 = (const float*)d_in[11];
    const float* nm_w1 = (const float*)d_in[12];
    const float* nm_b1 = (const float*)d_in[13];
    const float* nm_ln_g = (const float*)d_in[14];
    const float* nm_ln_b = (const float*)d_in[15];
    const float* nm_w2 = (const float*)d_in[16];
    const float* nm_b2 = (const float*)d_in[17];
    const float* ln_g = (const float*)d_in[18];
    const float* ln_b = (const float*)d_in[19];
    const void* edges = d_in[20];

    cudaFuncSetAttribute(k_lin, cudaFuncAttributeMaxDynamicSharedMemorySize, 84992);
    cudaFuncSetAttribute(k_y, cudaFuncAttributeMaxDynamicSharedMemorySize, SMEM_Y);
    cudaFuncSetAttribute(k_edge, cudaFuncAttributeMaxDynamicSharedMemorySize, SMEM_EDGE);
    cudaFuncSetAttribute(k_node, cudaFuncAttributeMaxDynamicSharedMemorySize, 169984);

    k_prep<<<48, 256>>>(att_w1, att_w2, edges);
    k_zero<<<(NN * DN + 255) / 256, 256>>>();
    k_lin<<<625, 256, 84992>>>(h, lin_w, lin_b);
    k_y<<<625, 256, SMEM_Y>>>(att_b1);
    k_edge<<<NCTA, 256, SMEM_EDGE>>>(distances, edge_mask, att_w1, att_b2,
                                     att_w3, att_b3, edges);
    k_node<<<625, 256, 169984>>>(nm_w1, nm_b1, nm_ln_g, nm_ln_b,
                                 nm_w2, nm_b2, ln_g, ln_b, (float*)d_out);
}

// round 7
// speedup vs baseline: 6.2316x; 1.1192x over previous
#include <cuda_runtime.h>
#include <cuda_bf16.h>

typedef unsigned int u32;
typedef unsigned long long u64;
typedef unsigned short u16;

#define DN 128
#define NN 20000
#define EE 640000
#define ET 64                   // edges per CTA
#define NCTA (EE / ET)          // 10000
#define ASTR 528                // h1 row stride bytes (264 halves)
#define YSTR 272                // x row stride bytes in k_xy (136 halves)

// ---------------- device globals (no runtime alloc) ----------------
__device__ float g_x[NN * DN];
__device__ float g_out[NN * DN];
__device__ float g_ya[NN * 256];   // x@W1a^T + b1
__device__ float g_yb[NN * 256];   // x@W1b^T
__device__ int g_e64;
// pre-packed B fragments in per-lane mma order (hi,lo interleaved uint4 pairs)
__device__ uint4 g_f1[16384];   // W1: [og4][side2][ks8][nq4][lane32][hi/lo]
__device__ uint4 g_f2[8192];    // W2: [og4][ks16][nq2][lane32][hi/lo]
__device__ uint4 g_fl[4096];    // lin_w: [og8][ks8][lane32][hi/lo]

// ---------------- k_edge smem layout (bytes) ----------------
#define SB_ROWS 0
#define SB_COLS 256
#define SB_DE   512
#define SB_EMS  768
#define SB_ATT  1024
#define SB_PART 1280
#define SB_B2   2304
#define SB_W3   2816
#define SB_W1C  3328
#define SB_A_HI 4352            // 64 x 528 = 33792
#define SB_A_LO 38144           // 33792
#define SMEM_EDGE 71936

// ---------------- k_xy smem layout ----------------
#define SY_A_HI 0               // 32 x 272 = 8704
#define SY_A_LO 8704
#define SY_B1   17408           // 256 f
#define SY_LB   18432           // 128 f
#define SMEM_Y  18944

__device__ __forceinline__ u32 smem_u32(const void* p) {
    u32 a;
    asm("{ .reg .u64 t; cvta.to.shared.u64 t, %1; cvt.u32.u64 %0, t; }" : "=r"(a) : "l"(p));
    return a;
}
__device__ __forceinline__ float sigm(float v) { return 1.0f / (1.0f + __expf(-v)); }
__device__ __forceinline__ float silu_(float v) { return v * sigm(v); }

__device__ __forceinline__ void bsplit(float v, u16& h, u16& l) {
    __nv_bfloat16 hb = __float2bfloat16(v);
    __nv_bfloat16 lb = __float2bfloat16(v - __bfloat162float(hb));
    h = __bfloat16_as_ushort(hb);
    l = __bfloat16_as_ushort(lb);
}

// ldmatrix m16k16 (A, row-major, stride S bytes)
template <int S>
__device__ __forceinline__ void ldmA(u32 r[4], u32 base, int row0, int kh) {
    int lane = threadIdx.x & 31;
    int quad = lane >> 3;
    u32 addr = base + (u32)(row0 + (lane & 7) + (quad & 1) * 8) * S +
               (u32)kh * 2 + (u32)(quad >> 1) * 16;
    asm volatile("ldmatrix.sync.aligned.m8n8.x4.shared.b16 {%0,%1,%2,%3}, [%4];"
                 : "=r"(r[0]), "=r"(r[1]), "=r"(r[2]), "=r"(r[3]) : "r"(addr));
}
__device__ __forceinline__ void mma16816(float d[4], const u32 a[4], u32 b0, u32 b1) {
    asm volatile("mma.sync.aligned.m16n8k16.row.col.f32.bf16.bf16.f32 "
                 "{%0,%1,%2,%3}, {%4,%5,%6,%7}, {%8,%9}, {%0,%1,%2,%3};"
                 : "+f"(d[0]), "+f"(d[1]), "+f"(d[2]), "+f"(d[3])
                 : "r"(a[0]), "r"(a[1]), "r"(a[2]), "r"(a[3]), "r"(b0), "r"(b1));
}

// ---------------------------------------------------------------------------
// k_prep: pack W1/W2/lin_w into per-lane B-fragment tables (hi/lo bf16 split).
// 14336 fragment pairs -> grid 56 x 256.
// ---------------------------------------------------------------------------
__global__ void k_prep(const float* __restrict__ w1, const float* __restrict__ w2,
                       const float* __restrict__ lw, const void* __restrict__ edges) {
    int idx = blockIdx.x * 256 + threadIdx.x;
    if (idx < 8192) {       // W1 frags [256 out][257 k]
        int lane = idx & 31, nq = (idx >> 5) & 3, ks = (idx >> 7) & 7;
        int side = (idx >> 10) & 1, og = (idx >> 11) & 3;
        int nb0 = og * 64 + nq * 16 + (lane >> 2);
        int kb = side * 128 + ks * 16 + (lane & 3) * 2;
        u32 wh[4], wl[4];
#pragma unroll
        for (int nb = 0; nb < 2; nb++)
#pragma unroll
            for (int r = 0; r < 2; r++) {
                const float* p = &w1[(nb0 + nb * 8) * 257 + kb + r * 8];
                u16 h0, l0, h1, l1;
                bsplit(p[0], h0, l0);
                bsplit(p[1], h1, l1);
                wh[nb * 2 + r] = (u32)h0 | ((u32)h1 << 16);
                wl[nb * 2 + r] = (u32)l0 | ((u32)l1 << 16);
            }
        g_f1[idx * 2] = make_uint4(wh[0], wh[1], wh[2], wh[3]);
        g_f1[idx * 2 + 1] = make_uint4(wl[0], wl[1], wl[2], wl[3]);
    } else if (idx < 12288) {  // W2 frags [128 out][256 k]
        int j = idx - 8192;
        int lane = j & 31, nq = (j >> 5) & 1, ks = (j >> 6) & 15, og = (j >> 10) & 3;
        int nb0 = og * 32 + nq * 16 + (lane >> 2);
        int kb = ks * 16 + (lane & 3) * 2;
        u32 wh[4], wl[4];
#pragma unroll
        for (int nb = 0; nb < 2; nb++)
#pragma unroll
            for (int r = 0; r < 2; r++) {
                const float* p = &w2[(nb0 + nb * 8) * 256 + kb + r * 8];
                u16 h0, l0, h1, l1;
                bsplit(p[0], h0, l0);
                bsplit(p[1], h1, l1);
                wh[nb * 2 + r] = (u32)h0 | ((u32)h1 << 16);
                wl[nb * 2 + r] = (u32)l0 | ((u32)l1 << 16);
            }
        g_f2[j * 2] = make_uint4(wh[0], wh[1], wh[2], wh[3]);
        g_f2[j * 2 + 1] = make_uint4(wl[0], wl[1], wl[2], wl[3]);
    } else {                // lin_w frags [128 out][128 k]
        int j = idx - 12288;
        int lane = j & 31, ks = (j >> 5) & 7, og = (j >> 8) & 7;
        int nb0 = og * 16 + (lane >> 2);
        int kb = ks * 16 + (lane & 3) * 2;
        u32 wh[4], wl[4];
#pragma unroll
        for (int nb = 0; nb < 2; nb++)
#pragma unroll
            for (int r = 0; r < 2; r++) {
                const float* p = &lw[(nb0 + nb * 8) * 128 + kb + r * 8];
                u16 h0, l0, h1, l1;
                bsplit(p[0], h0, l0);
                bsplit(p[1], h1, l1);
                wh[nb * 2 + r] = (u32)h0 | ((u32)h1 << 16);
                wl[nb * 2 + r] = (u32)l0 | ((u32)l1 << 16);
            }
        g_fl[j * 2] = make_uint4(wh[0], wh[1], wh[2], wh[3]);
        g_fl[j * 2 + 1] = make_uint4(wl[0], wl[1], wl[2], wl[3]);
    }
    if (idx == 0) {
        const int* e32 = (const int*)edges;
        int nz = 0;
        for (int i = 0; i < 16; i++) nz |= e32[2 * i + 1];
        g_e64 = (nz == 0) ? 1 : 0;
    }
}

__global__ void k_zero() {
    int i = blockIdx.x * 256 + threadIdx.x;
    if (i < NN * DN) g_out[i] = 0.0f;
}

// ---------------------------------------------------------------------------
// k_xy: fused  x = h@lin_w^T + lin_b ;  ya = x@W1a^T + b1 ;  yb = x@W1b^T.
// 32 nodes/CTA. Phase1: 8 warps x 16 outs. Phase2: warps 0-3 ya, 4-7 yb.
// ---------------------------------------------------------------------------
__global__ __launch_bounds__(256, 1) void k_xy(const float* __restrict__ h,
                                               const float* __restrict__ lb,
                                               const float* __restrict__ b1) {
    extern __shared__ char smc[];
    u32 smb = smem_u32(smc);
    float* b1s = (float*)(smc + SY_B1);
    float* lbs = (float*)(smc + SY_LB);
    int tid = threadIdx.x, lane = tid & 31, warp = tid >> 5;
    int n0 = blockIdx.x * 32;

    b1s[tid] = b1[tid];
    if (tid < 128) lbs[tid] = lb[tid];
    // load h tile (hi/lo split) — warp handles 4 nodes
#pragma unroll
    for (int i = 0; i < 4; i++) {
        int el = warp * 4 + i;
        const float4 v = *(const float4*)&h[(size_t)(n0 + el) * DN + lane * 4];
        u16 h0, l0, h1, l1, h2, l2, h3, l3;
        bsplit(v.x, h0, l0); bsplit(v.y, h1, l1); bsplit(v.z, h2, l2); bsplit(v.w, h3, l3);
        u64 hp = (u64)h0 | ((u64)h1 << 16) | ((u64)h2 << 32) | ((u64)h3 << 48);
        u64 lp = (u64)l0 | ((u64)l1 << 16) | ((u64)l2 << 32) | ((u64)l3 << 48);
        *(u64*)(smc + SY_A_HI + el * YSTR + lane * 8) = hp;
        *(u64*)(smc + SY_A_LO + el * YSTR + lane * 8) = lp;
    }
    __syncthreads();

    // ---- phase 1: x = h@lin_w^T + lin_b.  warp -> outs [warp*16, +16) ----
    {
        float accl[2][2][4] = {};
#pragma unroll
        for (int ks = 0; ks < 8; ks++) {
            int ka = ks * 16;
            u32 ah[2][4], al_[2][4];
            ldmA<YSTR>(ah[0], smb + SY_A_HI, 0, ka);
            ldmA<YSTR>(ah[1], smb + SY_A_HI, 16, ka);
            ldmA<YSTR>(al_[0], smb + SY_A_LO, 0, ka);
            ldmA<YSTR>(al_[1], smb + SY_A_LO, 16, ka);
            int fbase = ((warp * 8 + ks) * 32 + lane) * 2;
            uint4 fh = g_fl[fbase];
            uint4 fl = g_fl[fbase + 1];
#pragma unroll
            for (int mt = 0; mt < 2; mt++) {
                mma16816(accl[mt][0], ah[mt], fh.x, fh.y);
                mma16816(accl[mt][0], ah[mt], fl.x, fl.y);
                mma16816(accl[mt][0], al_[mt], fh.x, fh.y);
                mma16816(accl[mt][1], ah[mt], fh.z, fh.w);
                mma16816(accl[mt][1], ah[mt], fl.z, fl.w);
                mma16816(accl[mt][1], al_[mt], fh.z, fh.w);
            }
        }
        __syncthreads();   // done reading h tile; overlay x tile
        int r0 = lane >> 2, cb = (lane & 3) * 2;
#pragma unroll
        for (int mt = 0; mt < 2; mt++) {
#pragma unroll
            for (int nb = 0; nb < 2; nb++) {
                int o = warp * 16 + nb * 8 + cb;
                float ba = lbs[o], bb = lbs[o + 1];
                float v0 = accl[mt][nb][0] + ba, v1 = accl[mt][nb][1] + bb;
                float v2 = accl[mt][nb][2] + ba, v3 = accl[mt][nb][3] + bb;
                int nl = mt * 16 + r0;
                *(float2*)&g_x[(size_t)(n0 + nl) * DN + o] = make_float2(v0, v1);
                *(float2*)&g_x[(size_t)(n0 + nl + 8) * DN + o] = make_float2(v2, v3);
                u16 h0, l0, h1, l1;
                bsplit(v0, h0, l0); bsplit(v1, h1, l1);
                *(u32*)(smc + SY_A_HI + nl * YSTR + o * 2) = (u32)h0 | ((u32)h1 << 16);
                *(u32*)(smc + SY_A_LO + nl * YSTR + o * 2) = (u32)l0 | ((u32)l1 << 16);
                bsplit(v2, h0, l0); bsplit(v3, h1, l1);
                *(u32*)(smc + SY_A_HI + (nl + 8) * YSTR + o * 2) = (u32)h0 | ((u32)h1 << 16);
                *(u32*)(smc + SY_A_LO + (nl + 8) * YSTR + o * 2) = (u32)l0 | ((u32)l1 << 16);
            }
        }
    }
    __syncthreads();

    // ---- phase 2: ya/yb.  warps 0-3 -> ya (side 0), 4-7 -> yb ----
    int side = warp >> 2, og1 = warp & 3;
    float acc[2][8][4] = {};
#pragma unroll
    for (int ks = 0; ks < 8; ks++) {
        int ka = ks * 16;
        u32 ah[2][4], al_[2][4];
        ldmA<YSTR>(ah[0], smb + SY_A_HI, 0, ka);
        ldmA<YSTR>(ah[1], smb + SY_A_HI, 16, ka);
        ldmA<YSTR>(al_[0], smb + SY_A_LO, 0, ka);
        ldmA<YSTR>(al_[1], smb + SY_A_LO, 16, ka);
        int fbase = ((((og1 * 2 + side) * 8 + ks) * 4) * 32 + lane) * 2;
#pragma unroll
        for (int nq = 0; nq < 4; nq++) {
            uint4 fh = g_f1[fbase + nq * 64];
            uint4 fl = g_f1[fbase + nq * 64 + 1];
#pragma unroll
            for (int mt = 0; mt < 2; mt++) {
                mma16816(acc[mt][nq * 2], ah[mt], fh.x, fh.y);
                mma16816(acc[mt][nq * 2], ah[mt], fl.x, fl.y);
                mma16816(acc[mt][nq * 2], al_[mt], fh.x, fh.y);
                mma16816(acc[mt][nq * 2 + 1], ah[mt], fh.z, fh.w);
                mma16816(acc[mt][nq * 2 + 1], ah[mt], fl.z, fl.w);
                mma16816(acc[mt][nq * 2 + 1], al_[mt], fh.z, fh.w);
            }
        }
    }
    // epilogue: store (ya += b1)
    {
        int r0 = lane >> 2, cb = (lane & 3) * 2;
        float* dst = side == 0 ? g_ya : g_yb;
#pragma unroll
        for (int mt = 0; mt < 2; mt++) {
            int node = n0 + mt * 16 + r0;
#pragma unroll
            for (int nb = 0; nb < 8; nb++) {
                int o = og1 * 64 + nb * 8 + cb;
                float ba = side == 0 ? b1s[o] : 0.0f;
                float bb = side == 0 ? b1s[o + 1] : 0.0f;
                float2 v0 = make_float2(acc[mt][nb][0] + ba, acc[mt][nb][1] + bb);
                float2 v1 = make_float2(acc[mt][nb][2] + ba, acc[mt][nb][3] + bb);
                *(float2*)&dst[(size_t)node * 256 + o] = v0;
                *(float2*)&dst[(size_t)(node + 8) * 256 + o] = v1;
            }
        }
    }
}

// ---------------------------------------------------------------------------
// Fused edge kernel: gather ya/yb -> silu -> GEMM2 (mma bf16 hi/lo) -> att
// -> scatter (red.global.v4).  64 edges/CTA, 8 warps, 3 CTAs/SM.
// ---------------------------------------------------------------------------
__global__ __launch_bounds__(256, 3) void k_edge(
    const float* __restrict__ dist, const float* __restrict__ emask,
    const float* __restrict__ w1, const float* __restrict__ b2,
    const float* __restrict__ w3, const float* __restrict__ b3,
    const void* __restrict__ edges) {
    extern __shared__ char smc[];
    u32 smb = smem_u32(smc);
    float* smf = (float*)smc;
    int* rows = (int*)(smc + SB_ROWS);
    int* cols = (int*)(smc + SB_COLS);

    int tid = threadIdx.x, lane = tid & 31, warp = tid >> 5;
    int eg = warp & 1, og = warp >> 1;
    int Eb = eg * 32;
    int e0 = blockIdx.x * ET;

    // stage small vectors
    smf[SB_W1C / 4 + tid] = w1[tid * 257 + 256];
    if (tid < 128) {
        smf[SB_B2 / 4 + tid] = b2[tid];
        smf[SB_W3 / 4 + tid] = w3[tid];
    }
    if (tid < 64) {
        int e = e0 + tid;
        if (g_e64) {
            const long long* e64 = (const long long*)edges;
            rows[tid] = (int)e64[e];
            cols[tid] = (int)e64[EE + e];
        } else {
            const int* ei = (const int*)edges;
            rows[tid] = ei[e];
            cols[tid] = ei[EE + e];
        }
        float em = emask[e];
        smf[SB_EMS / 4 + tid] = em;
        smf[SB_DE / 4 + tid] = dist[e] * em;
    }
    __syncthreads();

    // ---- gather ya[row]+yb[col]+de*w1c -> silu -> h1 bf16 hi/lo tile ----
#pragma unroll
    for (int i = 0; i < 8; i++) {
        int el = warp * 8 + i;
        const float* ya = &g_ya[(size_t)rows[el] * 256];
        const float* yb = &g_yb[(size_t)cols[el] * 256];
        float de = smf[SB_DE / 4 + el];
#pragma unroll
        for (int j = 0; j < 2; j++) {
            int o4 = lane * 4 + j * 128;
            float4 a4 = *(const float4*)(ya + o4);
            float4 b4 = *(const float4*)(yb + o4);
            float4 wc = *(const float4*)(smf + SB_W1C / 4 + o4);
            float v0 = silu_(a4.x + b4.x + de * wc.x);
            float v1 = silu_(a4.y + b4.y + de * wc.y);
            float v2 = silu_(a4.z + b4.z + de * wc.z);
            float v3 = silu_(a4.w + b4.w + de * wc.w);
            u16 h0, l0, h1, l1, h2, l2, h3, l3;
            bsplit(v0, h0, l0); bsplit(v1, h1, l1); bsplit(v2, h2, l2); bsplit(v3, h3, l3);
            u64 hp = (u64)h0 | ((u64)h1 << 16) | ((u64)h2 << 32) | ((u64)h3 << 48);
            u64 lp = (u64)l0 | ((u64)l1 << 16) | ((u64)l2 << 32) | ((u64)l3 << 48);
            *(u64*)(smc + SB_A_HI + el * ASTR + o4 * 2) = hp;
            *(u64*)(smc + SB_A_LO + el * ASTR + o4 * 2) = lp;
        }
    }
    __syncthreads();

    // ---- GEMM2: D2[64e x 128o], warp slice 32e x 32o, K=256 ----
    float acc2[2][4][4] = {};
#pragma unroll
    for (int ks = 0; ks < 16; ks++) {
        int ka = ks * 16;
        u32 ah[2][4], al_[2][4];
        ldmA<ASTR>(ah[0], smb + SB_A_HI, Eb, ka);
        ldmA<ASTR>(ah[1], smb + SB_A_HI, Eb + 16, ka);
        ldmA<ASTR>(al_[0], smb + SB_A_LO, Eb, ka);
        ldmA<ASTR>(al_[1], smb + SB_A_LO, Eb + 16, ka);
        int fbase = (((og * 16 + ks) * 2) * 32 + lane) * 2;
#pragma unroll
        for (int nq = 0; nq < 2; nq++) {
            uint4 fh = g_f2[fbase + nq * 64];
            uint4 fl = g_f2[fbase + nq * 64 + 1];
#pragma unroll
            for (int mt = 0; mt < 2; mt++) {
                mma16816(acc2[mt][nq * 2], ah[mt], fh.x, fh.y);
                mma16816(acc2[mt][nq * 2], ah[mt], fl.x, fl.y);
                mma16816(acc2[mt][nq * 2], al_[mt], fh.x, fh.y);
                mma16816(acc2[mt][nq * 2 + 1], ah[mt], fh.z, fh.w);
                mma16816(acc2[mt][nq * 2 + 1], ah[mt], fl.z, fl.w);
                mma16816(acc2[mt][nq * 2 + 1], al_[mt], fh.z, fh.w);
            }
        }
    }

    // ---- epilogue2: att partials, cross-og combine ----
    {
        int r0 = lane >> 2, cb = (lane & 3) * 2;
        float p[2][2] = {};
#pragma unroll
        for (int mt = 0; mt < 2; mt++)
#pragma unroll
            for (int nb = 0; nb < 4; nb++) {
                int o = og * 32 + nb * 8 + cb;
                float b2a = smf[SB_B2 / 4 + o], b2b = smf[SB_B2 / 4 + o + 1];
                float w3a = smf[SB_W3 / 4 + o], w3b = smf[SB_W3 / 4 + o + 1];
                p[mt][0] += silu_(acc2[mt][nb][0] + b2a) * w3a + silu_(acc2[mt][nb][1] + b2b) * w3b;
                p[mt][1] += silu_(acc2[mt][nb][2] + b2a) * w3a + silu_(acc2[mt][nb][3] + b2b) * w3b;
            }
#pragma unroll
        for (int off = 1; off <= 2; off <<= 1)
#pragma unroll
            for (int mt = 0; mt < 2; mt++) {
                p[mt][0] += __shfl_xor_sync(0xffffffffu, p[mt][0], off);
                p[mt][1] += __shfl_xor_sync(0xffffffffu, p[mt][1], off);
            }
        if ((lane & 3) == 0) {
#pragma unroll
            for (int mt = 0; mt < 2; mt++) {
                int e = Eb + mt * 16 + r0;
                smf[SB_PART / 4 + og * 64 + e] = p[mt][0];
                smf[SB_PART / 4 + og * 64 + e + 8] = p[mt][1];
            }
        }
    }
    __syncthreads();
    if (tid < 64) {
        float z = smf[SB_PART / 4 + tid] + smf[SB_PART / 4 + 64 + tid] +
                  smf[SB_PART / 4 + 128 + tid] + smf[SB_PART / 4 + 192 + tid] + b3[0];
        smf[SB_ATT / 4 + tid] = sigm(z) * smf[SB_EMS / 4 + tid];
    }
    __syncthreads();

    // ---- scatter: g_out[row] += x_col * att  (vector reduction, no return) ----
#pragma unroll
    for (int i = 0; i < 8; i++) {
        int el = warp * 8 + i;
        float a = smf[SB_ATT / 4 + el];
        const float4 v = *(const float4*)&g_x[(size_t)cols[el] * DN + lane * 4];
        float* dst = &g_out[(size_t)rows[el] * DN + lane * 4];
        asm volatile("red.global.add.v4.f32 [%0], {%1, %2, %3, %4};"
                     :: "l"(dst), "f"(v.x * a), "f"(v.y * a), "f"(v.z * a), "f"(v.w * a)
                     : "memory");
    }
}

// ---------------------------------------------------------------------------
// node_mlp + residual + final LN + silu.   32 nodes/CTA.
// ---------------------------------------------------------------------------
__global__ __launch_bounds__(256, 1) void k_node(
    const float* __restrict__ w1, const float* __restrict__ b1,
    const float* __restrict__ g1, const float* __restrict__ bb1,
    const float* __restrict__ w2, const float* __restrict__ b2,
    const float* __restrict__ g2, const float* __restrict__ bb2,
    float* __restrict__ out) {
    extern __shared__ float sm[];
    float* w1T = sm;
    float* w2T = w1T + 16896;
    float* ins = w2T + 16896;
    float* mids = ins + 4224;
    float* b1s = mids + 4224;
    float* b2s = b1s + 128;
    int tid = threadIdx.x, lane = tid & 31, warp = tid >> 5;
    int n0 = blockIdx.x * 32;

    for (int idx = tid; idx < 128 * 128; idx += 256) {
        int o = idx >> 7, k = idx & 127;
        w1T[k * 132 + o] = w1[idx];
        w2T[k * 132 + o] = w2[idx];
    }
    if (tid < 128) { b1s[tid] = b1[tid]; b2s[tid] = b2[tid]; }
#pragma unroll
    for (int i = 0; i < 4; i++) {
        int nl = warp * 4 + i;
        float4 v = *(const float4*)&g_out[(size_t)(n0 + nl) * DN + lane * 4];
        v.x *= 0.01f; v.y *= 0.01f; v.z *= 0.01f; v.w *= 0.01f;
        *(float4*)&ins[nl * 132 + lane * 4] = v;
    }
    __syncthreads();

    float acc[4][4] = {};
    {
        const float* inw = ins + warp * 4 * 132;
        for (int k = 0; k < 128; k++) {
            float a[4], wv[4];
#pragma unroll
            for (int i = 0; i < 4; i++) a[i] = inw[i * 132 + k];
#pragma unroll
            for (int j = 0; j < 4; j++) wv[j] = w1T[k * 132 + lane + 32 * j];
#pragma unroll
            for (int i = 0; i < 4; i++)
#pragma unroll
                for (int j = 0; j < 4; j++) acc[i][j] += a[i] * wv[j];
        }
    }
    float lg1[4], lb1[4];
#pragma unroll
    for (int j = 0; j < 4; j++) { int o = lane + 32 * j; lg1[j] = g1[o]; lb1[j] = bb1[o]; }
#pragma unroll
    for (int i = 0; i < 4; i++) {
        float v[4], s1 = 0.f, s2 = 0.f;
#pragma unroll
        for (int j = 0; j < 4; j++) {
            v[j] = acc[i][j] + b1s[lane + 32 * j];
            s1 += v[j]; s2 += v[j] * v[j];
        }
#pragma unroll
        for (int off = 16; off > 0; off >>= 1) {
            s1 += __shfl_xor_sync(0xffffffffu, s1, off);
            s2 += __shfl_xor_sync(0xffffffffu, s2, off);
        }
        float mean = s1 * (1.0f / 128.0f);
        float var = s2 * (1.0f / 128.0f) - mean * mean;
        float inv = rsqrtf(var + 1e-5f);
        int nl = warp * 4 + i;
#pragma unroll
        for (int j = 0; j < 4; j++) {
            float y = (v[j] - mean) * inv * lg1[j] + lb1[j];
            mids[nl * 132 + lane + 32 * j] = silu_(y);
        }
    }
    __syncthreads();

    float acc2[4][4] = {};
    {
        const float* mw = mids + warp * 4 * 132;
        for (int k = 0; k < 128; k++) {
            float a[4], wv[4];
#pragma unroll
            for (int i = 0; i < 4; i++) a[i] = mw[i * 132 + k];
#pragma unroll
            for (int j = 0; j < 4; j++) wv[j] = w2T[k * 132 + lane + 32 * j];
#pragma unroll
            for (int i = 0; i < 4; i++)
#pragma unroll
                for (int j = 0; j < 4; j++) acc2[i][j] += a[i] * wv[j];
        }
    }
    float lg2[4], lb2[4];
#pragma unroll
    for (int j = 0; j < 4; j++) { int o = lane + 32 * j; lg2[j] = g2[o]; lb2[j] = bb2[o]; }
#pragma unroll
    for (int i = 0; i < 4; i++) {
        int nl = warp * 4 + i;
        float v[4], s1 = 0.f, s2 = 0.f;
#pragma unroll
        for (int j = 0; j < 4; j++) {
            int o = lane + 32 * j;
            v[j] = acc2[i][j] + b2s[o] + g_x[(size_t)(n0 + nl) * DN + o];
            s1 += v[j]; s2 += v[j] * v[j];
        }
#pragma unroll
        for (int off = 16; off > 0; off >>= 1) {
            s1 += __shfl_xor_sync(0xffffffffu, s1, off);
            s2 += __shfl_xor_sync(0xffffffffu, s2, off);
        }
        float mean = s1 * (1.0f / 128.0f);
        float var = s2 * (1.0f / 128.0f) - mean * mean;
        float inv = rsqrtf(var + 1e-5f);
#pragma unroll
        for (int j = 0; j < 4; j++) {
            int o = lane + 32 * j;
            float y = (v[j] - mean) * inv * lg2[j] + lb2[j];
            out[(size_t)(n0 + nl) * DN + o] = silu_(y);
        }
    }
}

// ---------------------------------------------------------------------------
extern "C" void kernel_launch(void* const* d_in, const int* in_sizes, int n_in,
                              void* d_out, int out_size) {
    const float* h = (const float*)d_in[0];
    const float* distances = (const float*)d_in[1];
    const float* edge_mask = (const float*)d_in[3];
    const float* lin_w = (const float*)d_in[4];
    const float* lin_b = (const float*)d_in[5];
    const float* att_w1 = (const float*)d_in[6];
    const float* att_b1 = (const float*)d_in[7];
    const float* att_w2 = (const float*)d_in[8];
    const float* att_b2 = (const float*)d_in[9];
    const float* att_w3 = (const float*)d_in[10];
    const float* att_b3 = (const float*)d_in[11];
    const float* nm_w1 = (const float*)d_in[12];
    const float* nm_b1 = (const float*)d_in[13];
    const float* nm_ln_g = (const float*)d_in[14];
    const float* nm_ln_b = (const float*)d_in[15];
    const float* nm_w2 = (const float*)d_in[16];
    const float* nm_b2 = (const float*)d_in[17];
    const float* ln_g = (const float*)d_in[18];
    const float* ln_b = (const float*)d_in[19];
    const void* edges = d_in[20];

    cudaFuncSetAttribute(k_xy, cudaFuncAttributeMaxDynamicSharedMemorySize, SMEM_Y);
    cudaFuncSetAttribute(k_edge, cudaFuncAttributeMaxDynamicSharedMemorySize, SMEM_EDGE);
    cudaFuncSetAttribute(k_node, cudaFuncAttributeMaxDynamicSharedMemorySize, 169984);

    k_prep<<<56, 256>>>(att_w1, att_w2, lin_w, edges);
    k_zero<<<(NN * DN + 255) / 256, 256>>>();
    k_xy<<<625, 256, SMEM_Y>>>(h, lin_b, att_b1);
    k_edge<<<NCTA, 256, SMEM_EDGE>>>(distances, edge_mask, att_w1, att_b2,
                                     att_w3, att_b3, edges);
    k_node<<<625, 256, 169984>>>(nm_w1, nm_b1, nm_ln_g, nm_ln_b,
                                 nm_w2, nm_b2, ln_g, ln_b, (float*)d_out);
}

// round 8
// speedup vs baseline: 6.5087x; 1.0445x over previous
#include <cuda_runtime.h>
#include <cuda_bf16.h>

typedef unsigned int u32;
typedef unsigned long long u64;
typedef unsigned short u16;

#define DN 128
#define NN 20000
#define EE 640000
#define ET 64                   // edges per CTA
#define NCTA (EE / ET)          // 10000
#define ASTR 528                // h1 row stride bytes (264 halves)
#define YSTR 272                // x row stride bytes in k_xy (136 halves)

// ---------------- device globals (no runtime alloc) ----------------
__device__ float g_x[NN * DN];
__device__ float g_out[NN * DN];
__device__ float g_ya[NN * 256];   // x@W1a^T + b1
__device__ float g_yb[NN * 256];   // x@W1b^T
__device__ int g_e64;
// pre-packed B fragments in per-lane mma order (hi,lo interleaved uint4 pairs)
__device__ uint4 g_f1[16384];   // W1: [og4][side2][ks8][nq4][lane32][hi/lo]
__device__ uint4 g_f2[8192];    // W2: [og4][ks16][nq2][lane32][hi/lo]
__device__ uint4 g_fl[4096];    // lin_w: [og8][ks8][lane32][hi/lo]

// ---------------- k_edge smem layout (bytes) ----------------
#define SB_ROWS 0
#define SB_COLS 256
#define SB_DE   512
#define SB_EMS  768
#define SB_ATT  1024
#define SB_PART 1280
#define SB_B2   2304
#define SB_W3   2816
#define SB_W1C  3328
#define SB_A_HI 4352            // 64 x 528 = 33792
#define SB_A_LO 38144           // 33792
#define SMEM_EDGE 71936

// ---------------- k_xy smem layout ----------------
#define SY_A_HI 0               // 32 x 272 = 8704
#define SY_A_LO 8704
#define SY_B1   17408           // 256 f
#define SY_LB   18432           // 128 f
#define SMEM_Y  18944

__device__ __forceinline__ u32 smem_u32(const void* p) {
    u32 a;
    asm("{ .reg .u64 t; cvta.to.shared.u64 t, %1; cvt.u32.u64 %0, t; }" : "=r"(a) : "l"(p));
    return a;
}
// fast sigmoid/silu: MUFU.RCP instead of IEEE div chain
__device__ __forceinline__ float sigm(float v) {
    return __fdividef(1.0f, 1.0f + __expf(-v));
}
__device__ __forceinline__ float silu_(float v) { return v * sigm(v); }

__device__ __forceinline__ void bsplit(float v, u16& h, u16& l) {
    __nv_bfloat16 hb = __float2bfloat16(v);
    __nv_bfloat16 lb = __float2bfloat16(v - __bfloat162float(hb));
    h = __bfloat16_as_ushort(hb);
    l = __bfloat16_as_ushort(lb);
}

// ldmatrix m16k16 (A, row-major, stride S bytes)
template <int S>
__device__ __forceinline__ void ldmA(u32 r[4], u32 base, int row0, int kh) {
    int lane = threadIdx.x & 31;
    int quad = lane >> 3;
    u32 addr = base + (u32)(row0 + (lane & 7) + (quad & 1) * 8) * S +
               (u32)kh * 2 + (u32)(quad >> 1) * 16;
    asm volatile("ldmatrix.sync.aligned.m8n8.x4.shared.b16 {%0,%1,%2,%3}, [%4];"
                 : "=r"(r[0]), "=r"(r[1]), "=r"(r[2]), "=r"(r[3]) : "r"(addr));
}
__device__ __forceinline__ void mma16816(float d[4], const u32 a[4], u32 b0, u32 b1) {
    asm volatile("mma.sync.aligned.m16n8k16.row.col.f32.bf16.bf16.f32 "
                 "{%0,%1,%2,%3}, {%4,%5,%6,%7}, {%8,%9}, {%0,%1,%2,%3};"
                 : "+f"(d[0]), "+f"(d[1]), "+f"(d[2]), "+f"(d[3])
                 : "r"(a[0]), "r"(a[1]), "r"(a[2]), "r"(a[3]), "r"(b0), "r"(b1));
}

// ---------------------------------------------------------------------------
// k_prep: pack W1/W2/lin_w into per-lane B-fragment tables (hi/lo bf16 split).
// ---------------------------------------------------------------------------
__global__ void k_prep(const float* __restrict__ w1, const float* __restrict__ w2,
                       const float* __restrict__ lw, const void* __restrict__ edges) {
    int idx = blockIdx.x * 256 + threadIdx.x;
    if (idx < 8192) {       // W1 frags [256 out][257 k]
        int lane = idx & 31, nq = (idx >> 5) & 3, ks = (idx >> 7) & 7;
        int side = (idx >> 10) & 1, og = (idx >> 11) & 3;
        int nb0 = og * 64 + nq * 16 + (lane >> 2);
        int kb = side * 128 + ks * 16 + (lane & 3) * 2;
        u32 wh[4], wl[4];
#pragma unroll
        for (int nb = 0; nb < 2; nb++)
#pragma unroll
            for (int r = 0; r < 2; r++) {
                const float* p = &w1[(nb0 + nb * 8) * 257 + kb + r * 8];
                u16 h0, l0, h1, l1;
                bsplit(p[0], h0, l0);
                bsplit(p[1], h1, l1);
                wh[nb * 2 + r] = (u32)h0 | ((u32)h1 << 16);
                wl[nb * 2 + r] = (u32)l0 | ((u32)l1 << 16);
            }
        g_f1[idx * 2] = make_uint4(wh[0], wh[1], wh[2], wh[3]);
        g_f1[idx * 2 + 1] = make_uint4(wl[0], wl[1], wl[2], wl[3]);
    } else if (idx < 12288) {  // W2 frags [128 out][256 k]
        int j = idx - 8192;
        int lane = j & 31, nq = (j >> 5) & 1, ks = (j >> 6) & 15, og = (j >> 10) & 3;
        int nb0 = og * 32 + nq * 16 + (lane >> 2);
        int kb = ks * 16 + (lane & 3) * 2;
        u32 wh[4], wl[4];
#pragma unroll
        for (int nb = 0; nb < 2; nb++)
#pragma unroll
            for (int r = 0; r < 2; r++) {
                const float* p = &w2[(nb0 + nb * 8) * 256 + kb + r * 8];
                u16 h0, l0, h1, l1;
                bsplit(p[0], h0, l0);
                bsplit(p[1], h1, l1);
                wh[nb * 2 + r] = (u32)h0 | ((u32)h1 << 16);
                wl[nb * 2 + r] = (u32)l0 | ((u32)l1 << 16);
            }
        g_f2[j * 2] = make_uint4(wh[0], wh[1], wh[2], wh[3]);
        g_f2[j * 2 + 1] = make_uint4(wl[0], wl[1], wl[2], wl[3]);
    } else {                // lin_w frags [128 out][128 k]
        int j = idx - 12288;
        int lane = j & 31, ks = (j >> 5) & 7, og = (j >> 8) & 7;
        int nb0 = og * 16 + (lane >> 2);
        int kb = ks * 16 + (lane & 3) * 2;
        u32 wh[4], wl[4];
#pragma unroll
        for (int nb = 0; nb < 2; nb++)
#pragma unroll
            for (int r = 0; r < 2; r++) {
                const float* p = &lw[(nb0 + nb * 8) * 128 + kb + r * 8];
                u16 h0, l0, h1, l1;
                bsplit(p[0], h0, l0);
                bsplit(p[1], h1, l1);
                wh[nb * 2 + r] = (u32)h0 | ((u32)h1 << 16);
                wl[nb * 2 + r] = (u32)l0 | ((u32)l1 << 16);
            }
        g_fl[j * 2] = make_uint4(wh[0], wh[1], wh[2], wh[3]);
        g_fl[j * 2 + 1] = make_uint4(wl[0], wl[1], wl[2], wl[3]);
    }
    if (idx == 0) {
        const int* e32 = (const int*)edges;
        int nz = 0;
        for (int i = 0; i < 16; i++) nz |= e32[2 * i + 1];
        g_e64 = (nz == 0) ? 1 : 0;
    }
}

__global__ void k_zero() {
    int i = blockIdx.x * 256 + threadIdx.x;
    if (i < NN * DN) g_out[i] = 0.0f;
}

// ---------------------------------------------------------------------------
// k_xy: fused  x = h@lin_w^T + lin_b ;  ya = x@W1a^T + b1 ;  yb = x@W1b^T.
// 32 nodes/CTA. Phase1: 8 warps x 16 outs. Phase2: warps 0-3 ya, 4-7 yb.
// ---------------------------------------------------------------------------
__global__ __launch_bounds__(256, 1) void k_xy(const float* __restrict__ h,
                                               const float* __restrict__ lb,
                                               const float* __restrict__ b1) {
    extern __shared__ char smc[];
    u32 smb = smem_u32(smc);
    float* b1s = (float*)(smc + SY_B1);
    float* lbs = (float*)(smc + SY_LB);
    int tid = threadIdx.x, lane = tid & 31, warp = tid >> 5;
    int n0 = blockIdx.x * 32;

    b1s[tid] = b1[tid];
    if (tid < 128) lbs[tid] = lb[tid];
    // load h tile (hi/lo split) — warp handles 4 nodes
#pragma unroll
    for (int i = 0; i < 4; i++) {
        int el = warp * 4 + i;
        const float4 v = *(const float4*)&h[(size_t)(n0 + el) * DN + lane * 4];
        u16 h0, l0, h1, l1, h2, l2, h3, l3;
        bsplit(v.x, h0, l0); bsplit(v.y, h1, l1); bsplit(v.z, h2, l2); bsplit(v.w, h3, l3);
        u64 hp = (u64)h0 | ((u64)h1 << 16) | ((u64)h2 << 32) | ((u64)h3 << 48);
        u64 lp = (u64)l0 | ((u64)l1 << 16) | ((u64)l2 << 32) | ((u64)l3 << 48);
        *(u64*)(smc + SY_A_HI + el * YSTR + lane * 8) = hp;
        *(u64*)(smc + SY_A_LO + el * YSTR + lane * 8) = lp;
    }
    __syncthreads();

    // ---- phase 1: x = h@lin_w^T + lin_b.  warp -> outs [warp*16, +16) ----
    {
        float accl[2][2][4] = {};
#pragma unroll
        for (int ks = 0; ks < 8; ks++) {
            int ka = ks * 16;
            u32 ah[2][4], al_[2][4];
            ldmA<YSTR>(ah[0], smb + SY_A_HI, 0, ka);
            ldmA<YSTR>(ah[1], smb + SY_A_HI, 16, ka);
            ldmA<YSTR>(al_[0], smb + SY_A_LO, 0, ka);
            ldmA<YSTR>(al_[1], smb + SY_A_LO, 16, ka);
            int fbase = ((warp * 8 + ks) * 32 + lane) * 2;
            uint4 fh = g_fl[fbase];
            uint4 fl = g_fl[fbase + 1];
#pragma unroll
            for (int mt = 0; mt < 2; mt++) {
                mma16816(accl[mt][0], ah[mt], fh.x, fh.y);
                mma16816(accl[mt][0], ah[mt], fl.x, fl.y);
                mma16816(accl[mt][0], al_[mt], fh.x, fh.y);
                mma16816(accl[mt][1], ah[mt], fh.z, fh.w);
                mma16816(accl[mt][1], ah[mt], fl.z, fl.w);
                mma16816(accl[mt][1], al_[mt], fh.z, fh.w);
            }
        }
        __syncthreads();   // done reading h tile; overlay x tile
        int r0 = lane >> 2, cb = (lane & 3) * 2;
#pragma unroll
        for (int mt = 0; mt < 2; mt++) {
#pragma unroll
            for (int nb = 0; nb < 2; nb++) {
                int o = warp * 16 + nb * 8 + cb;
                float ba = lbs[o], bb = lbs[o + 1];
                float v0 = accl[mt][nb][0] + ba, v1 = accl[mt][nb][1] + bb;
                float v2 = accl[mt][nb][2] + ba, v3 = accl[mt][nb][3] + bb;
                int nl = mt * 16 + r0;
                *(float2*)&g_x[(size_t)(n0 + nl) * DN + o] = make_float2(v0, v1);
                *(float2*)&g_x[(size_t)(n0 + nl + 8) * DN + o] = make_float2(v2, v3);
                u16 h0, l0, h1, l1;
                bsplit(v0, h0, l0); bsplit(v1, h1, l1);
                *(u32*)(smc + SY_A_HI + nl * YSTR + o * 2) = (u32)h0 | ((u32)h1 << 16);
                *(u32*)(smc + SY_A_LO + nl * YSTR + o * 2) = (u32)l0 | ((u32)l1 << 16);
                bsplit(v2, h0, l0); bsplit(v3, h1, l1);
                *(u32*)(smc + SY_A_HI + (nl + 8) * YSTR + o * 2) = (u32)h0 | ((u32)h1 << 16);
                *(u32*)(smc + SY_A_LO + (nl + 8) * YSTR + o * 2) = (u32)l0 | ((u32)l1 << 16);
            }
        }
    }
    __syncthreads();

    // ---- phase 2: ya/yb.  warps 0-3 -> ya (side 0), 4-7 -> yb ----
    int side = warp >> 2, og1 = warp & 3;
    float acc[2][8][4] = {};
#pragma unroll
    for (int ks = 0; ks < 8; ks++) {
        int ka = ks * 16;
        u32 ah[2][4], al_[2][4];
        ldmA<YSTR>(ah[0], smb + SY_A_HI, 0, ka);
        ldmA<YSTR>(ah[1], smb + SY_A_HI, 16, ka);
        ldmA<YSTR>(al_[0], smb + SY_A_LO, 0, ka);
        ldmA<YSTR>(al_[1], smb + SY_A_LO, 16, ka);
        int fbase = ((((og1 * 2 + side) * 8 + ks) * 4) * 32 + lane) * 2;
#pragma unroll
        for (int nq = 0; nq < 4; nq++) {
            uint4 fh = g_f1[fbase + nq * 64];
            uint4 fl = g_f1[fbase + nq * 64 + 1];
#pragma unroll
            for (int mt = 0; mt < 2; mt++) {
                mma16816(acc[mt][nq * 2], ah[mt], fh.x, fh.y);
                mma16816(acc[mt][nq * 2], ah[mt], fl.x, fl.y);
                mma16816(acc[mt][nq * 2], al_[mt], fh.x, fh.y);
                mma16816(acc[mt][nq * 2 + 1], ah[mt], fh.z, fh.w);
                mma16816(acc[mt][nq * 2 + 1], ah[mt], fl.z, fl.w);
                mma16816(acc[mt][nq * 2 + 1], al_[mt], fh.z, fh.w);
            }
        }
    }
    // epilogue: store (ya += b1)
    {
        int r0 = lane >> 2, cb = (lane & 3) * 2;
        float* dst = side == 0 ? g_ya : g_yb;
#pragma unroll
        for (int mt = 0; mt < 2; mt++) {
            int node = n0 + mt * 16 + r0;
#pragma unroll
            for (int nb = 0; nb < 8; nb++) {
                int o = og1 * 64 + nb * 8 + cb;
                float ba = side == 0 ? b1s[o] : 0.0f;
                float bb = side == 0 ? b1s[o + 1] : 0.0f;
                float2 v0 = make_float2(acc[mt][nb][0] + ba, acc[mt][nb][1] + bb);
                float2 v1 = make_float2(acc[mt][nb][2] + ba, acc[mt][nb][3] + bb);
                *(float2*)&dst[(size_t)node * 256 + o] = v0;
                *(float2*)&dst[(size_t)(node + 8) * 256 + o] = v1;
            }
        }
    }
}

// ---------------------------------------------------------------------------
// Fused edge kernel: gather ya/yb -> silu -> GEMM2 (mma bf16 hi/lo) -> att
// -> scatter (red.global.v4).  64 edges/CTA, 8 warps = 4 eg x 2 og, 3 CTAs/SM.
// ---------------------------------------------------------------------------
__global__ __launch_bounds__(256, 3) void k_edge(
    const float* __restrict__ dist, const float* __restrict__ emask,
    const float* __restrict__ w1, const float* __restrict__ b2,
    const float* __restrict__ w3, const float* __restrict__ b3,
    const void* __restrict__ edges) {
    extern __shared__ char smc[];
    u32 smb = smem_u32(smc);
    float* smf = (float*)smc;
    int* rows = (int*)(smc + SB_ROWS);
    int* cols = (int*)(smc + SB_COLS);

    int tid = threadIdx.x, lane = tid & 31, warp = tid >> 5;
    int eg = warp & 3, og = warp >> 2;   // 4 edge-groups x 2 out-groups
    int Eb = eg * 16;
    int e0 = blockIdx.x * ET;

    // stage small vectors
    smf[SB_W1C / 4 + tid] = w1[tid * 257 + 256];
    if (tid < 128) {
        smf[SB_B2 / 4 + tid] = b2[tid];
        smf[SB_W3 / 4 + tid] = w3[tid];
    }
    if (tid < 64) {
        int e = e0 + tid;
        if (g_e64) {
            const long long* e64 = (const long long*)edges;
            rows[tid] = (int)e64[e];
            cols[tid] = (int)e64[EE + e];
        } else {
            const int* ei = (const int*)edges;
            rows[tid] = ei[e];
            cols[tid] = ei[EE + e];
        }
        float em = emask[e];
        smf[SB_EMS / 4 + tid] = em;
        smf[SB_DE / 4 + tid] = dist[e] * em;
    }
    __syncthreads();

    // ---- gather ya[row]+yb[col]+de*w1c -> silu -> h1 bf16 hi/lo tile ----
#pragma unroll
    for (int i = 0; i < 8; i++) {
        int el = warp * 8 + i;
        const float* ya = &g_ya[(size_t)rows[el] * 256];
        const float* yb = &g_yb[(size_t)cols[el] * 256];
        float de = smf[SB_DE / 4 + el];
#pragma unroll
        for (int j = 0; j < 2; j++) {
            int o4 = lane * 4 + j * 128;
            float4 a4 = *(const float4*)(ya + o4);
            float4 b4 = *(const float4*)(yb + o4);
            float4 wc = *(const float4*)(smf + SB_W1C / 4 + o4);
            float v0 = silu_(a4.x + b4.x + de * wc.x);
            float v1 = silu_(a4.y + b4.y + de * wc.y);
            float v2 = silu_(a4.z + b4.z + de * wc.z);
            float v3 = silu_(a4.w + b4.w + de * wc.w);
            u16 h0, l0, h1, l1, h2, l2, h3, l3;
            bsplit(v0, h0, l0); bsplit(v1, h1, l1); bsplit(v2, h2, l2); bsplit(v3, h3, l3);
            u64 hp = (u64)h0 | ((u64)h1 << 16) | ((u64)h2 << 32) | ((u64)h3 << 48);
            u64 lp = (u64)l0 | ((u64)l1 << 16) | ((u64)l2 << 32) | ((u64)l3 << 48);
            *(u64*)(smc + SB_A_HI + el * ASTR + o4 * 2) = hp;
            *(u64*)(smc + SB_A_LO + el * ASTR + o4 * 2) = lp;
        }
    }
    __syncthreads();

    // ---- GEMM2: D2[64e x 128o], warp slice 16e x 64o, K=256 ----
    float acc2[8][4] = {};     // [nq*2+half][frag]
#pragma unroll
    for (int ks = 0; ks < 16; ks++) {
        int ka = ks * 16;
        u32 ah[4], al_[4];
        ldmA<ASTR>(ah, smb + SB_A_HI, Eb, ka);
        ldmA<ASTR>(al_, smb + SB_A_LO, Eb, ka);
#pragma unroll
        for (int nq = 0; nq < 4; nq++) {
            // map (og, nq) -> fragment table coords (old_og in 0..3, old_nq in 0..1)
            int oo = og * 2 + (nq >> 1), on = nq & 1;
            int fbase = ((((oo * 16 + ks) * 2 + on)) * 32 + lane) * 2;
            uint4 fh = g_f2[fbase];
            uint4 fl = g_f2[fbase + 1];
            mma16816(acc2[nq * 2], ah, fh.x, fh.y);
            mma16816(acc2[nq * 2], ah, fl.x, fl.y);
            mma16816(acc2[nq * 2], al_, fh.x, fh.y);
            mma16816(acc2[nq * 2 + 1], ah, fh.z, fh.w);
            mma16816(acc2[nq * 2 + 1], ah, fl.z, fl.w);
            mma16816(acc2[nq * 2 + 1], al_, fh.z, fh.w);
        }
    }

    // ---- epilogue2: att partials over 64 outs, combine across 2 ogs ----
    {
        int r0 = lane >> 2, cb = (lane & 3) * 2;
        float p0 = 0.0f, p1 = 0.0f;
#pragma unroll
        for (int nb = 0; nb < 8; nb++) {
            int o = og * 64 + nb * 8 + cb;
            float b2a = smf[SB_B2 / 4 + o], b2b = smf[SB_B2 / 4 + o + 1];
            float w3a = smf[SB_W3 / 4 + o], w3b = smf[SB_W3 / 4 + o + 1];
            p0 += silu_(acc2[nb][0] + b2a) * w3a + silu_(acc2[nb][1] + b2b) * w3b;
            p1 += silu_(acc2[nb][2] + b2a) * w3a + silu_(acc2[nb][3] + b2b) * w3b;
        }
#pragma unroll
        for (int off = 1; off <= 2; off <<= 1) {
            p0 += __shfl_xor_sync(0xffffffffu, p0, off);
            p1 += __shfl_xor_sync(0xffffffffu, p1, off);
        }
        if ((lane & 3) == 0) {
            int e = Eb + r0;
            smf[SB_PART / 4 + og * 64 + e] = p0;
            smf[SB_PART / 4 + og * 64 + e + 8] = p1;
        }
    }
    __syncthreads();
    if (tid < 64) {
        float z = smf[SB_PART / 4 + tid] + smf[SB_PART / 4 + 64 + tid] + b3[0];
        smf[SB_ATT / 4 + tid] = sigm(z) * smf[SB_EMS / 4 + tid];
    }
    __syncthreads();

    // ---- scatter: g_out[row] += x_col * att  (vector reduction, no return) ----
#pragma unroll
    for (int i = 0; i < 8; i++) {
        int el = warp * 8 + i;
        float a = smf[SB_ATT / 4 + el];
        const float4 v = *(const float4*)&g_x[(size_t)cols[el] * DN + lane * 4];
        float* dst = &g_out[(size_t)rows[el] * DN + lane * 4];
        asm volatile("red.global.add.v4.f32 [%0], {%1, %2, %3, %4};"
                     :: "l"(dst), "f"(v.x * a), "f"(v.y * a), "f"(v.z * a), "f"(v.w * a)
                     : "memory");
    }
}

// ---------------------------------------------------------------------------
// node_mlp + residual + final LN + silu.   32 nodes/CTA.
// ---------------------------------------------------------------------------
__global__ __launch_bounds__(256, 1) void k_node(
    const float* __restrict__ w1, const float* __restrict__ b1,
    const float* __restrict__ g1, const float* __restrict__ bb1,
    const float* __restrict__ w2, const float* __restrict__ b2,
    const float* __restrict__ g2, const float* __restrict__ bb2,
    float* __restrict__ out) {
    extern __shared__ float sm[];
    float* w1T = sm;
    float* w2T = w1T + 16896;
    float* ins = w2T + 16896;
    float* mids = ins + 4224;
    float* b1s = mids + 4224;
    float* b2s = b1s + 128;
    int tid = threadIdx.x, lane = tid & 31, warp = tid >> 5;
    int n0 = blockIdx.x * 32;

    for (int idx = tid; idx < 128 * 128; idx += 256) {
        int o = idx >> 7, k = idx & 127;
        w1T[k * 132 + o] = w1[idx];
        w2T[k * 132 + o] = w2[idx];
    }
    if (tid < 128) { b1s[tid] = b1[tid]; b2s[tid] = b2[tid]; }
#pragma unroll
    for (int i = 0; i < 4; i++) {
        int nl = warp * 4 + i;
        float4 v = *(const float4*)&g_out[(size_t)(n0 + nl) * DN + lane * 4];
        v.x *= 0.01f; v.y *= 0.01f; v.z *= 0.01f; v.w *= 0.01f;
        *(float4*)&ins[nl * 132 + lane * 4] = v;
    }
    __syncthreads();

    float acc[4][4] = {};
    {
        const float* inw = ins + warp * 4 * 132;
        for (int k = 0; k < 128; k++) {
            float a[4], wv[4];
#pragma unroll
            for (int i = 0; i < 4; i++) a[i] = inw[i * 132 + k];
#pragma unroll
            for (int j = 0; j < 4; j++) wv[j] = w1T[k * 132 + lane + 32 * j];
#pragma unroll
            for (int i = 0; i < 4; i++)
#pragma unroll
                for (int j = 0; j < 4; j++) acc[i][j] += a[i] * wv[j];
        }
    }
    float lg1[4], lb1[4];
#pragma unroll
    for (int j = 0; j < 4; j++) { int o = lane + 32 * j; lg1[j] = g1[o]; lb1[j] = bb1[o]; }
#pragma unroll
    for (int i = 0; i < 4; i++) {
        float v[4], s1 = 0.f, s2 = 0.f;
#pragma unroll
        for (int j = 0; j < 4; j++) {
            v[j] = acc[i][j] + b1s[lane + 32 * j];
            s1 += v[j]; s2 += v[j] * v[j];
        }
#pragma unroll
        for (int off = 16; off > 0; off >>= 1) {
            s1 += __shfl_xor_sync(0xffffffffu, s1, off);
            s2 += __shfl_xor_sync(0xffffffffu, s2, off);
        }
        float mean = s1 * (1.0f / 128.0f);
        float var = s2 * (1.0f / 128.0f) - mean * mean;
        float inv = rsqrtf(var + 1e-5f);
        int nl = warp * 4 + i;
#pragma unroll
        for (int j = 0; j < 4; j++) {
            float y = (v[j] - mean) * inv * lg1[j] + lb1[j];
            mids[nl * 132 + lane + 32 * j] = silu_(y);
        }
    }
    __syncthreads();

    float acc2[4][4] = {};
    {
        const float* mw = mids + warp * 4 * 132;
        for (int k = 0; k < 128; k++) {
            float a[4], wv[4];
#pragma unroll
            for (int i = 0; i < 4; i++) a[i] = mw[i * 132 + k];
#pragma unroll
            for (int j = 0; j < 4; j++) wv[j] = w2T[k * 132 + lane + 32 * j];
#pragma unroll
            for (int i = 0; i < 4; i++)
#pragma unroll
                for (int j = 0; j < 4; j++) acc2[i][j] += a[i] * wv[j];
        }
    }
    float lg2[4], lb2[4];
#pragma unroll
    for (int j = 0; j < 4; j++) { int o = lane + 32 * j; lg2[j] = g2[o]; lb2[j] = bb2[o]; }
#pragma unroll
    for (int i = 0; i < 4; i++) {
        int nl = warp * 4 + i;
        float v[4], s1 = 0.f, s2 = 0.f;
#pragma unroll
        for (int j = 0; j < 4; j++) {
            int o = lane + 32 * j;
            v[j] = acc2[i][j] + b2s[o] + g_x[(size_t)(n0 + nl) * DN + o];
            s1 += v[j]; s2 += v[j] * v[j];
        }
#pragma unroll
        for (int off = 16; off > 0; off >>= 1) {
            s1 += __shfl_xor_sync(0xffffffffu, s1, off);
            s2 += __shfl_xor_sync(0xffffffffu, s2, off);
        }
        float mean = s1 * (1.0f / 128.0f);
        float var = s2 * (1.0f / 128.0f) - mean * mean;
        float inv = rsqrtf(var + 1e-5f);
#pragma unroll
        for (int j = 0; j < 4; j++) {
            int o = lane + 32 * j;
            float y = (v[j] - mean) * inv * lg2[j] + lb2[j];
            out[(size_t)(n0 + nl) * DN + o] = silu_(y);
        }
    }
}

// ---------------------------------------------------------------------------
extern "C" void kernel_launch(void* const* d_in, const int* in_sizes, int n_in,
                              void* d_out, int out_size) {
    const float* h = (const float*)d_in[0];
    const float* distances = (const float*)d_in[1];
    const float* edge_mask = (const float*)d_in[3];
    const float* lin_w = (const float*)d_in[4];
    const float* lin_b = (const float*)d_in[5];
    const float* att_w1 = (const float*)d_in[6];
    const float* att_b1 = (const float*)d_in[7];
    const float* att_w2 = (const float*)d_in[8];
    const float* att_b2 = (const float*)d_in[9];
    const float* att_w3 = (const float*)d_in[10];
    const float* att_b3 = (const float*)d_in[11];
    const float* nm_w1 = (const float*)d_in[12];
    const float* nm_b1 = (const float*)d_in[13];
    const float* nm_ln_g = (const float*)d_in[14];
    const float* nm_ln_b = (const float*)d_in[15];
    const float* nm_w2 = (const float*)d_in[16];
    const float* nm_b2 = (const float*)d_in[17];
    const float* ln_g = (const float*)d_in[18];
    const float* ln_b = (const float*)d_in[19];
    const void* edges = d_in[20];

    cudaFuncSetAttribute(k_xy, cudaFuncAttributeMaxDynamicSharedMemorySize, SMEM_Y);
    cudaFuncSetAttribute(k_edge, cudaFuncAttributeMaxDynamicSharedMemorySize, SMEM_EDGE);
    cudaFuncSetAttribute(k_node, cudaFuncAttributeMaxDynamicSharedMemorySize, 169984);

    k_prep<<<56, 256>>>(att_w1, att_w2, lin_w, edges);
    k_zero<<<(NN * DN + 255) / 256, 256>>>();
    k_xy<<<625, 256, SMEM_Y>>>(h, lin_b, att_b1);
    k_edge<<<NCTA, 256, SMEM_EDGE>>>(distances, edge_mask, att_w1, att_b2,
                                     att_w3, att_b3, edges);
    k_node<<<625, 256, 169984>>>(nm_w1, nm_b1, nm_ln_g, nm_ln_b,
                                 nm_w2, nm_b2, ln_g, ln_b, (float*)d_out);
}

// round 9
// speedup vs baseline: 7.5879x; 1.1658x over previous
#include <cuda_runtime.h>
#include <cuda_bf16.h>

typedef unsigned int u32;
typedef unsigned long long u64;
typedef unsigned short u16;

#define DN 128
#define NN 20000
#define EE 640000
#define ET 64                   // edges per CTA
#define NCTA (EE / ET)          // 10000
#define ASTR 528                // h1 row stride bytes (264 halves)
#define YSTR 272                // x row stride bytes in k_xy (136 halves)

// ---------------- device globals (no runtime alloc) ----------------
__device__ float g_x[NN * DN];
__device__ float g_out[NN * DN];
__device__ float g_ya[NN * 256];   // x@W1a^T + b1
__device__ float g_yb[NN * 256];   // x@W1b^T
__device__ int g_e64;
// pre-packed B fragments in per-lane mma order (hi,lo interleaved uint4 pairs)
__device__ uint4 g_f1[16384];   // W1: [og4][side2][ks8][nq4][lane32][hi/lo]
__device__ uint4 g_f2[8192];    // W2: [og4][ks16][nq2][lane32][hi/lo]
__device__ uint4 g_fl[4096];    // lin_w: [og8][ks8][lane32][hi/lo]

// ---------------- k_edge smem layout (bytes) ----------------
#define SB_ROWS 0
#define SB_COLS 256
#define SB_DE   512
#define SB_EMS  768
#define SB_ATT  1024
#define SB_PART 1280
#define SB_B2   2304
#define SB_W3   2816
#define SB_W1C  3328
#define SB_A_HI 4352            // 64 x 528 = 33792
#define SB_A_LO 38144           // 33792
#define SMEM_EDGE 71936

// ---------------- k_xy smem layout ----------------
#define SY_A_HI 0               // 32 x 272 = 8704
#define SY_A_LO 8704
#define SY_B1   17408           // 256 f
#define SY_LB   18432           // 128 f
#define SMEM_Y  18944

__device__ __forceinline__ u32 smem_u32(const void* p) {
    u32 a;
    asm("{ .reg .u64 t; cvta.to.shared.u64 t, %1; cvt.u32.u64 %0, t; }" : "=r"(a) : "l"(p));
    return a;
}
// fast sigmoid/silu: MUFU.RCP instead of IEEE div chain
__device__ __forceinline__ float sigm(float v) {
    return __fdividef(1.0f, 1.0f + __expf(-v));
}
__device__ __forceinline__ float silu_(float v) { return v * sigm(v); }

__device__ __forceinline__ void bsplit(float v, u16& h, u16& l) {
    __nv_bfloat16 hb = __float2bfloat16(v);
    __nv_bfloat16 lb = __float2bfloat16(v - __bfloat162float(hb));
    h = __bfloat16_as_ushort(hb);
    l = __bfloat16_as_ushort(lb);
}

// ldmatrix m16k16 (A, row-major, stride S bytes)
template <int S>
__device__ __forceinline__ void ldmA(u32 r[4], u32 base, int row0, int kh) {
    int lane = threadIdx.x & 31;
    int quad = lane >> 3;
    u32 addr = base + (u32)(row0 + (lane & 7) + (quad & 1) * 8) * S +
               (u32)kh * 2 + (u32)(quad >> 1) * 16;
    asm volatile("ldmatrix.sync.aligned.m8n8.x4.shared.b16 {%0,%1,%2,%3}, [%4];"
                 : "=r"(r[0]), "=r"(r[1]), "=r"(r[2]), "=r"(r[3]) : "r"(addr));
}
__device__ __forceinline__ void mma16816(float d[4], const u32 a[4], u32 b0, u32 b1) {
    asm volatile("mma.sync.aligned.m16n8k16.row.col.f32.bf16.bf16.f32 "
                 "{%0,%1,%2,%3}, {%4,%5,%6,%7}, {%8,%9}, {%0,%1,%2,%3};"
                 : "+f"(d[0]), "+f"(d[1]), "+f"(d[2]), "+f"(d[3])
                 : "r"(a[0]), "r"(a[1]), "r"(a[2]), "r"(a[3]), "r"(b0), "r"(b1));
}

// ---------------------------------------------------------------------------
// k_prep: pack W1/W2/lin_w into per-lane B-fragment tables (hi/lo bf16 split).
// ---------------------------------------------------------------------------
__global__ void k_prep(const float* __restrict__ w1, const float* __restrict__ w2,
                       const float* __restrict__ lw, const void* __restrict__ edges) {
    int idx = blockIdx.x * 256 + threadIdx.x;
    if (idx < 8192) {       // W1 frags [256 out][257 k]
        int lane = idx & 31, nq = (idx >> 5) & 3, ks = (idx >> 7) & 7;
        int side = (idx >> 10) & 1, og = (idx >> 11) & 3;
        int nb0 = og * 64 + nq * 16 + (lane >> 2);
        int kb = side * 128 + ks * 16 + (lane & 3) * 2;
        u32 wh[4], wl[4];
#pragma unroll
        for (int nb = 0; nb < 2; nb++)
#pragma unroll
            for (int r = 0; r < 2; r++) {
                const float* p = &w1[(nb0 + nb * 8) * 257 + kb + r * 8];
                u16 h0, l0, h1, l1;
                bsplit(p[0], h0, l0);
                bsplit(p[1], h1, l1);
                wh[nb * 2 + r] = (u32)h0 | ((u32)h1 << 16);
                wl[nb * 2 + r] = (u32)l0 | ((u32)l1 << 16);
            }
        g_f1[idx * 2] = make_uint4(wh[0], wh[1], wh[2], wh[3]);
        g_f1[idx * 2 + 1] = make_uint4(wl[0], wl[1], wl[2], wl[3]);
    } else if (idx < 12288) {  // W2 frags [128 out][256 k]
        int j = idx - 8192;
        int lane = j & 31, nq = (j >> 5) & 1, ks = (j >> 6) & 15, og = (j >> 10) & 3;
        int nb0 = og * 32 + nq * 16 + (lane >> 2);
        int kb = ks * 16 + (lane & 3) * 2;
        u32 wh[4], wl[4];
#pragma unroll
        for (int nb = 0; nb < 2; nb++)
#pragma unroll
            for (int r = 0; r < 2; r++) {
                const float* p = &w2[(nb0 + nb * 8) * 256 + kb + r * 8];
                u16 h0, l0, h1, l1;
                bsplit(p[0], h0, l0);
                bsplit(p[1], h1, l1);
                wh[nb * 2 + r] = (u32)h0 | ((u32)h1 << 16);
                wl[nb * 2 + r] = (u32)l0 | ((u32)l1 << 16);
            }
        g_f2[j * 2] = make_uint4(wh[0], wh[1], wh[2], wh[3]);
        g_f2[j * 2 + 1] = make_uint4(wl[0], wl[1], wl[2], wl[3]);
    } else {                // lin_w frags [128 out][128 k]
        int j = idx - 12288;
        int lane = j & 31, ks = (j >> 5) & 7, og = (j >> 8) & 7;
        int nb0 = og * 16 + (lane >> 2);
        int kb = ks * 16 + (lane & 3) * 2;
        u32 wh[4], wl[4];
#pragma unroll
        for (int nb = 0; nb < 2; nb++)
#pragma unroll
            for (int r = 0; r < 2; r++) {
                const float* p = &lw[(nb0 + nb * 8) * 128 + kb + r * 8];
                u16 h0, l0, h1, l1;
                bsplit(p[0], h0, l0);
                bsplit(p[1], h1, l1);
                wh[nb * 2 + r] = (u32)h0 | ((u32)h1 << 16);
                wl[nb * 2 + r] = (u32)l0 | ((u32)l1 << 16);
            }
        g_fl[j * 2] = make_uint4(wh[0], wh[1], wh[2], wh[3]);
        g_fl[j * 2 + 1] = make_uint4(wl[0], wl[1], wl[2], wl[3]);
    }
    if (idx == 0) {
        const int* e32 = (const int*)edges;
        int nz = 0;
        for (int i = 0; i < 16; i++) nz |= e32[2 * i + 1];
        g_e64 = (nz == 0) ? 1 : 0;
    }
}

__global__ void k_zero() {
    int i = blockIdx.x * 256 + threadIdx.x;
    if (i < NN * DN) g_out[i] = 0.0f;
}

// ---------------------------------------------------------------------------
// k_xy: fused  x = h@lin_w^T + lin_b ;  ya = x@W1a^T + b1 ;  yb = x@W1b^T.
// 32 nodes/CTA. Phase1: 8 warps x 16 outs. Phase2: warps 0-3 ya, 4-7 yb.
// ---------------------------------------------------------------------------
__global__ __launch_bounds__(256, 1) void k_xy(const float* __restrict__ h,
                                               const float* __restrict__ lb,
                                               const float* __restrict__ b1) {
    extern __shared__ char smc[];
    u32 smb = smem_u32(smc);
    float* b1s = (float*)(smc + SY_B1);
    float* lbs = (float*)(smc + SY_LB);
    int tid = threadIdx.x, lane = tid & 31, warp = tid >> 5;
    int n0 = blockIdx.x * 32;

    b1s[tid] = b1[tid];
    if (tid < 128) lbs[tid] = lb[tid];
    // load h tile (hi/lo split) — warp handles 4 nodes
#pragma unroll
    for (int i = 0; i < 4; i++) {
        int el = warp * 4 + i;
        const float4 v = *(const float4*)&h[(size_t)(n0 + el) * DN + lane * 4];
        u16 h0, l0, h1, l1, h2, l2, h3, l3;
        bsplit(v.x, h0, l0); bsplit(v.y, h1, l1); bsplit(v.z, h2, l2); bsplit(v.w, h3, l3);
        u64 hp = (u64)h0 | ((u64)h1 << 16) | ((u64)h2 << 32) | ((u64)h3 << 48);
        u64 lp = (u64)l0 | ((u64)l1 << 16) | ((u64)l2 << 32) | ((u64)l3 << 48);
        *(u64*)(smc + SY_A_HI + el * YSTR + lane * 8) = hp;
        *(u64*)(smc + SY_A_LO + el * YSTR + lane * 8) = lp;
    }
    __syncthreads();

    // ---- phase 1: x = h@lin_w^T + lin_b.  warp -> outs [warp*16, +16) ----
    {
        float accl[2][2][4] = {};
#pragma unroll
        for (int ks = 0; ks < 8; ks++) {
            int ka = ks * 16;
            u32 ah[2][4], al_[2][4];
            ldmA<YSTR>(ah[0], smb + SY_A_HI, 0, ka);
            ldmA<YSTR>(ah[1], smb + SY_A_HI, 16, ka);
            ldmA<YSTR>(al_[0], smb + SY_A_LO, 0, ka);
            ldmA<YSTR>(al_[1], smb + SY_A_LO, 16, ka);
            int fbase = ((warp * 8 + ks) * 32 + lane) * 2;
            uint4 fh = g_fl[fbase];
            uint4 fl = g_fl[fbase + 1];
#pragma unroll
            for (int mt = 0; mt < 2; mt++) {
                mma16816(accl[mt][0], ah[mt], fh.x, fh.y);
                mma16816(accl[mt][0], ah[mt], fl.x, fl.y);
                mma16816(accl[mt][0], al_[mt], fh.x, fh.y);
                mma16816(accl[mt][1], ah[mt], fh.z, fh.w);
                mma16816(accl[mt][1], ah[mt], fl.z, fl.w);
                mma16816(accl[mt][1], al_[mt], fh.z, fh.w);
            }
        }
        __syncthreads();   // done reading h tile; overlay x tile
        int r0 = lane >> 2, cb = (lane & 3) * 2;
#pragma unroll
        for (int mt = 0; mt < 2; mt++) {
#pragma unroll
            for (int nb = 0; nb < 2; nb++) {
                int o = warp * 16 + nb * 8 + cb;
                float ba = lbs[o], bb = lbs[o + 1];
                float v0 = accl[mt][nb][0] + ba, v1 = accl[mt][nb][1] + bb;
                float v2 = accl[mt][nb][2] + ba, v3 = accl[mt][nb][3] + bb;
                int nl = mt * 16 + r0;
                *(float2*)&g_x[(size_t)(n0 + nl) * DN + o] = make_float2(v0, v1);
                *(float2*)&g_x[(size_t)(n0 + nl + 8) * DN + o] = make_float2(v2, v3);
                u16 h0, l0, h1, l1;
                bsplit(v0, h0, l0); bsplit(v1, h1, l1);
                *(u32*)(smc + SY_A_HI + nl * YSTR + o * 2) = (u32)h0 | ((u32)h1 << 16);
                *(u32*)(smc + SY_A_LO + nl * YSTR + o * 2) = (u32)l0 | ((u32)l1 << 16);
                bsplit(v2, h0, l0); bsplit(v3, h1, l1);
                *(u32*)(smc + SY_A_HI + (nl + 8) * YSTR + o * 2) = (u32)h0 | ((u32)h1 << 16);
                *(u32*)(smc + SY_A_LO + (nl + 8) * YSTR + o * 2) = (u32)l0 | ((u32)l1 << 16);
            }
        }
    }
    __syncthreads();

    // ---- phase 2: ya/yb.  warps 0-3 -> ya (side 0), 4-7 -> yb ----
    int side = warp >> 2, og1 = warp & 3;
    float acc[2][8][4] = {};
#pragma unroll
    for (int ks = 0; ks < 8; ks++) {
        int ka = ks * 16;
        u32 ah[2][4], al_[2][4];
        ldmA<YSTR>(ah[0], smb + SY_A_HI, 0, ka);
        ldmA<YSTR>(ah[1], smb + SY_A_HI, 16, ka);
        ldmA<YSTR>(al_[0], smb + SY_A_LO, 0, ka);
        ldmA<YSTR>(al_[1], smb + SY_A_LO, 16, ka);
        int fbase = ((((og1 * 2 + side) * 8 + ks) * 4) * 32 + lane) * 2;
#pragma unroll
        for (int nq = 0; nq < 4; nq++) {
            uint4 fh = g_f1[fbase + nq * 64];
            uint4 fl = g_f1[fbase + nq * 64 + 1];
#pragma unroll
            for (int mt = 0; mt < 2; mt++) {
                mma16816(acc[mt][nq * 2], ah[mt], fh.x, fh.y);
                mma16816(acc[mt][nq * 2], ah[mt], fl.x, fl.y);
                mma16816(acc[mt][nq * 2], al_[mt], fh.x, fh.y);
                mma16816(acc[mt][nq * 2 + 1], ah[mt], fh.z, fh.w);
                mma16816(acc[mt][nq * 2 + 1], ah[mt], fl.z, fl.w);
                mma16816(acc[mt][nq * 2 + 1], al_[mt], fh.z, fh.w);
            }
        }
    }
    // epilogue: store (ya += b1)
    {
        int r0 = lane >> 2, cb = (lane & 3) * 2;
        float* dst = side == 0 ? g_ya : g_yb;
#pragma unroll
        for (int mt = 0; mt < 2; mt++) {
            int node = n0 + mt * 16 + r0;
#pragma unroll
            for (int nb = 0; nb < 8; nb++) {
                int o = og1 * 64 + nb * 8 + cb;
                float ba = side == 0 ? b1s[o] : 0.0f;
                float bb = side == 0 ? b1s[o + 1] : 0.0f;
                float2 v0 = make_float2(acc[mt][nb][0] + ba, acc[mt][nb][1] + bb);
                float2 v1 = make_float2(acc[mt][nb][2] + ba, acc[mt][nb][3] + bb);
                *(float2*)&dst[(size_t)node * 256 + o] = v0;
                *(float2*)&dst[(size_t)(node + 8) * 256 + o] = v1;
            }
        }
    }
}

// ---------------------------------------------------------------------------
// Fused edge kernel: gather ya/yb -> silu -> GEMM2 (mma bf16 hi/lo) -> att
// -> scatter (red.global.v4).  64 edges/CTA, 8 warps = 2 eg x 4 og, 3 CTAs/SM.
// ---------------------------------------------------------------------------
__global__ __launch_bounds__(256, 3) void k_edge(
    const float* __restrict__ dist, const float* __restrict__ emask,
    const float* __restrict__ w1, const float* __restrict__ b2,
    const float* __restrict__ w3, const float* __restrict__ b3,
    const void* __restrict__ edges) {
    extern __shared__ char smc[];
    u32 smb = smem_u32(smc);
    float* smf = (float*)smc;
    int* rows = (int*)(smc + SB_ROWS);
    int* cols = (int*)(smc + SB_COLS);

    int tid = threadIdx.x, lane = tid & 31, warp = tid >> 5;
    int eg = warp & 1, og = warp >> 1;   // 2 edge-groups x 4 out-groups
    int Eb = eg * 32;
    int e0 = blockIdx.x * ET;

    // stage small vectors
    smf[SB_W1C / 4 + tid] = w1[tid * 257 + 256];
    if (tid < 128) {
        smf[SB_B2 / 4 + tid] = b2[tid];
        smf[SB_W3 / 4 + tid] = w3[tid];
    }
    if (tid < 64) {
        int e = e0 + tid;
        if (g_e64) {
            const long long* e64 = (const long long*)edges;
            rows[tid] = (int)e64[e];
            cols[tid] = (int)e64[EE + e];
        } else {
            const int* ei = (const int*)edges;
            rows[tid] = ei[e];
            cols[tid] = ei[EE + e];
        }
        float em = emask[e];
        smf[SB_EMS / 4 + tid] = em;
        smf[SB_DE / 4 + tid] = dist[e] * em;
    }
    __syncthreads();

    // ---- gather ya[row]+yb[col]+de*w1c -> silu -> h1 bf16 hi/lo tile ----
    {
        // hoist loop-invariant w1c slices (depend only on lane)
        float4 wc0 = *(const float4*)(smf + SB_W1C / 4 + lane * 4);
        float4 wc1 = *(const float4*)(smf + SB_W1C / 4 + lane * 4 + 128);
#pragma unroll
        for (int i = 0; i < 8; i++) {
            int el = warp * 8 + i;
            const float* ya = &g_ya[(size_t)rows[el] * 256];
            const float* yb = &g_yb[(size_t)cols[el] * 256];
            float de = smf[SB_DE / 4 + el];
#pragma unroll
            for (int j = 0; j < 2; j++) {
                int o4 = lane * 4 + j * 128;
                float4 a4 = *(const float4*)(ya + o4);
                float4 b4 = *(const float4*)(yb + o4);
                float4 wc = j == 0 ? wc0 : wc1;
                float v0 = silu_(a4.x + b4.x + de * wc.x);
                float v1 = silu_(a4.y + b4.y + de * wc.y);
                float v2 = silu_(a4.z + b4.z + de * wc.z);
                float v3 = silu_(a4.w + b4.w + de * wc.w);
                u16 h0, l0, h1, l1, h2, l2, h3, l3;
                bsplit(v0, h0, l0); bsplit(v1, h1, l1); bsplit(v2, h2, l2); bsplit(v3, h3, l3);
                u64 hp = (u64)h0 | ((u64)h1 << 16) | ((u64)h2 << 32) | ((u64)h3 << 48);
                u64 lp = (u64)l0 | ((u64)l1 << 16) | ((u64)l2 << 32) | ((u64)l3 << 48);
                *(u64*)(smc + SB_A_HI + el * ASTR + o4 * 2) = hp;
                *(u64*)(smc + SB_A_LO + el * ASTR + o4 * 2) = lp;
            }
        }
    }
    __syncthreads();

    // ---- GEMM2: D2[64e x 128o], warp slice 32e x 32o, K=256 ----
    float acc2[2][4][4] = {};
#pragma unroll
    for (int ks = 0; ks < 16; ks++) {
        int ka = ks * 16;
        u32 ah[2][4], al_[2][4];
        ldmA<ASTR>(ah[0], smb + SB_A_HI, Eb, ka);
        ldmA<ASTR>(ah[1], smb + SB_A_HI, Eb + 16, ka);
        ldmA<ASTR>(al_[0], smb + SB_A_LO, Eb, ka);
        ldmA<ASTR>(al_[1], smb + SB_A_LO, Eb + 16, ka);
        int fbase = (((og * 16 + ks) * 2) * 32 + lane) * 2;
#pragma unroll
        for (int nq = 0; nq < 2; nq++) {
            uint4 fh = g_f2[fbase + nq * 64];
            uint4 fl = g_f2[fbase + nq * 64 + 1];
#pragma unroll
            for (int mt = 0; mt < 2; mt++) {
                mma16816(acc2[mt][nq * 2], ah[mt], fh.x, fh.y);
                mma16816(acc2[mt][nq * 2], ah[mt], fl.x, fl.y);
                mma16816(acc2[mt][nq * 2], al_[mt], fh.x, fh.y);
                mma16816(acc2[mt][nq * 2 + 1], ah[mt], fh.z, fh.w);
                mma16816(acc2[mt][nq * 2 + 1], ah[mt], fl.z, fl.w);
                mma16816(acc2[mt][nq * 2 + 1], al_[mt], fh.z, fh.w);
            }
        }
    }

    // ---- epilogue2: att partials, cross-og combine ----
    {
        int r0 = lane >> 2, cb = (lane & 3) * 2;
        float p[2][2] = {};
#pragma unroll
        for (int mt = 0; mt < 2; mt++)
#pragma unroll
            for (int nb = 0; nb < 4; nb++) {
                int o = og * 32 + nb * 8 + cb;
                float b2a = smf[SB_B2 / 4 + o], b2b = smf[SB_B2 / 4 + o + 1];
                float w3a = smf[SB_W3 / 4 + o], w3b = smf[SB_W3 / 4 + o + 1];
                p[mt][0] += silu_(acc2[mt][nb][0] + b2a) * w3a + silu_(acc2[mt][nb][1] + b2b) * w3b;
                p[mt][1] += silu_(acc2[mt][nb][2] + b2a) * w3a + silu_(acc2[mt][nb][3] + b2b) * w3b;
            }
#pragma unroll
        for (int off = 1; off <= 2; off <<= 1)
#pragma unroll
            for (int mt = 0; mt < 2; mt++) {
                p[mt][0] += __shfl_xor_sync(0xffffffffu, p[mt][0], off);
                p[mt][1] += __shfl_xor_sync(0xffffffffu, p[mt][1], off);
            }
        if ((lane & 3) == 0) {
#pragma unroll
            for (int mt = 0; mt < 2; mt++) {
                int e = Eb + mt * 16 + r0;
                smf[SB_PART / 4 + og * 64 + e] = p[mt][0];
                smf[SB_PART / 4 + og * 64 + e + 8] = p[mt][1];
            }
        }
    }
    __syncthreads();
    if (tid < 64) {
        float z = smf[SB_PART / 4 + tid] + smf[SB_PART / 4 + 64 + tid] +
                  smf[SB_PART / 4 + 128 + tid] + smf[SB_PART / 4 + 192 + tid] + b3[0];
        smf[SB_ATT / 4 + tid] = sigm(z) * smf[SB_EMS / 4 + tid];
    }
    __syncthreads();

    // ---- scatter: g_out[row] += x_col * att  (vector reduction, no return) ----
#pragma unroll
    for (int i = 0; i < 8; i++) {
        int el = warp * 8 + i;
        float a = smf[SB_ATT / 4 + el];
        const float4 v = *(const float4*)&g_x[(size_t)cols[el] * DN + lane * 4];
        float* dst = &g_out[(size_t)rows[el] * DN + lane * 4];
        asm volatile("red.global.add.v4.f32 [%0], {%1, %2, %3, %4};"
                     :: "l"(dst), "f"(v.x * a), "f"(v.y * a), "f"(v.z * a), "f"(v.w * a)
                     : "memory");
    }
}

// ---------------------------------------------------------------------------
// node_mlp + residual + final LN + silu.   32 nodes/CTA.
// ---------------------------------------------------------------------------
__global__ __launch_bounds__(256, 1) void k_node(
    const float* __restrict__ w1, const float* __restrict__ b1,
    const float* __restrict__ g1, const float* __restrict__ bb1,
    const float* __restrict__ w2, const float* __restrict__ b2,
    const float* __restrict__ g2, const float* __restrict__ bb2,
    float* __restrict__ out) {
    extern __shared__ float sm[];
    float* w1T = sm;
    float* w2T = w1T + 16896;
    float* ins = w2T + 16896;
    float* mids = ins + 4224;
    float* b1s = mids + 4224;
    float* b2s = b1s + 128;
    int tid = threadIdx.x, lane = tid & 31, warp = tid >> 5;
    int n0 = blockIdx.x * 32;

    for (int idx = tid; idx < 128 * 128; idx += 256) {
        int o = idx >> 7, k = idx & 127;
        w1T[k * 132 + o] = w1[idx];
        w2T[k * 132 + o] = w2[idx];
    }
    if (tid < 128) { b1s[tid] = b1[tid]; b2s[tid] = b2[tid]; }
#pragma unroll
    for (int i = 0; i < 4; i++) {
        int nl = warp * 4 + i;
        float4 v = *(const float4*)&g_out[(size_t)(n0 + nl) * DN + lane * 4];
        v.x *= 0.01f; v.y *= 0.01f; v.z *= 0.01f; v.w *= 0.01f;
        *(float4*)&ins[nl * 132 + lane * 4] = v;
    }
    __syncthreads();

    float acc[4][4] = {};
    {
        const float* inw = ins + warp * 4 * 132;
        for (int k = 0; k < 128; k++) {
            float a[4], wv[4];
#pragma unroll
            for (int i = 0; i < 4; i++) a[i] = inw[i * 132 + k];
#pragma unroll
            for (int j = 0; j < 4; j++) wv[j] = w1T[k * 132 + lane + 32 * j];
#pragma unroll
            for (int i = 0; i < 4; i++)
#pragma unroll
                for (int j = 0; j < 4; j++) acc[i][j] += a[i] * wv[j];
        }
    }
    float lg1[4], lb1[4];
#pragma unroll
    for (int j = 0; j < 4; j++) { int o = lane + 32 * j; lg1[j] = g1[o]; lb1[j] = bb1[o]; }
#pragma unroll
    for (int i = 0; i < 4; i++) {
        float v[4], s1 = 0.f, s2 = 0.f;
#pragma unroll
        for (int j = 0; j < 4; j++) {
            v[j] = acc[i][j] + b1s[lane + 32 * j];
            s1 += v[j]; s2 += v[j] * v[j];
        }
#pragma unroll
        for (int off = 16; off > 0; off >>= 1) {
            s1 += __shfl_xor_sync(0xffffffffu, s1, off);
            s2 += __shfl_xor_sync(0xffffffffu, s2, off);
        }
        float mean = s1 * (1.0f / 128.0f);
        float var = s2 * (1.0f / 128.0f) - mean * mean;
        float inv = rsqrtf(var + 1e-5f);
        int nl = warp * 4 + i;
#pragma unroll
        for (int j = 0; j < 4; j++) {
            float y = (v[j] - mean) * inv * lg1[j] + lb1[j];
            mids[nl * 132 + lane + 32 * j] = silu_(y);
        }
    }
    __syncthreads();

    float acc2[4][4] = {};
    {
        const float* mw = mids + warp * 4 * 132;
        for (int k = 0; k < 128; k++) {
            float a[4], wv[4];
#pragma unroll
            for (int i = 0; i < 4; i++) a[i] = mw[i * 132 + k];
#pragma unroll
            for (int j = 0; j < 4; j++) wv[j] = w2T[k * 132 + lane + 32 * j];
#pragma unroll
            for (int i = 0; i < 4; i++)
#pragma unroll
                for (int j = 0; j < 4; j++) acc2[i][j] += a[i] * wv[j];
        }
    }
    float lg2[4], lb2[4];
#pragma unroll
    for (int j = 0; j < 4; j++) { int o = lane + 32 * j; lg2[j] = g2[o]; lb2[j] = bb2[o]; }
#pragma unroll
    for (int i = 0; i < 4; i++) {
        int nl = warp * 4 + i;
        float v[4], s1 = 0.f, s2 = 0.f;
#pragma unroll
        for (int j = 0; j < 4; j++) {
            int o = lane + 32 * j;
            v[j] = acc2[i][j] + b2s[o] + g_x[(size_t)(n0 + nl) * DN + o];
            s1 += v[j]; s2 += v[j] * v[j];
        }
#pragma unroll
        for (int off = 16; off > 0; off >>= 1) {
            s1 += __shfl_xor_sync(0xffffffffu, s1, off);
            s2 += __shfl_xor_sync(0xffffffffu, s2, off);
        }
        float mean = s1 * (1.0f / 128.0f);
        float var = s2 * (1.0f / 128.0f) - mean * mean;
        float inv = rsqrtf(var + 1e-5f);
#pragma unroll
        for (int j = 0; j < 4; j++) {
            int o = lane + 32 * j;
            float y = (v[j] - mean) * inv * lg2[j] + lb2[j];
            out[(size_t)(n0 + nl) * DN + o] = silu_(y);
        }
    }
}

// ---------------------------------------------------------------------------
extern "C" void kernel_launch(void* const* d_in, const int* in_sizes, int n_in,
                              void* d_out, int out_size) {
    const float* h = (const float*)d_in[0];
    const float* distances = (const float*)d_in[1];
    const float* edge_mask = (const float*)d_in[3];
    const float* lin_w = (const float*)d_in[4];
    const float* lin_b = (const float*)d_in[5];
    const float* att_w1 = (const float*)d_in[6];
    const float* att_b1 = (const float*)d_in[7];
    const float* att_w2 = (const float*)d_in[8];
    const float* att_b2 = (const float*)d_in[9];
    const float* att_w3 = (const float*)d_in[10];
    const float* att_b3 = (const float*)d_in[11];
    const float* nm_w1 = (const float*)d_in[12];
    const float* nm_b1 = (const float*)d_in[13];
    const float* nm_ln_g = (const float*)d_in[14];
    const float* nm_ln_b = (const float*)d_in[15];
    const float* nm_w2 = (const float*)d_in[16];
    const float* nm_b2 = (const float*)d_in[17];
    const float* ln_g = (const float*)d_in[18];
    const float* ln_b = (const float*)d_in[19];
    const void* edges = d_in[20];

    cudaFuncSetAttribute(k_xy, cudaFuncAttributeMaxDynamicSharedMemorySize, SMEM_Y);
    cudaFuncSetAttribute(k_edge, cudaFuncAttributeMaxDynamicSharedMemorySize, SMEM_EDGE);
    cudaFuncSetAttribute(k_node, cudaFuncAttributeMaxDynamicSharedMemorySize, 169984);

    k_prep<<<56, 256>>>(att_w1, att_w2, lin_w, edges);
    k_zero<<<(NN * DN + 255) / 256, 256>>>();
    k_xy<<<625, 256, SMEM_Y>>>(h, lin_b, att_b1);
    k_edge<<<NCTA, 256, SMEM_EDGE>>>(distances, edge_mask, att_w1, att_b2,
                                     att_w3, att_b3, edges);
    k_node<<<625, 256, 169984>>>(nm_w1, nm_b1, nm_ln_g, nm_ln_b,
                                 nm_w2, nm_b2, ln_g, ln_b, (float*)d_out);
}

// round 10
// speedup vs baseline: 8.4394x; 1.1122x over previous
#include <cuda_runtime.h>
#include <cuda_bf16.h>

typedef unsigned int u32;
typedef unsigned long long u64;
typedef unsigned short u16;

#define DN 128
#define NN 20000
#define EE 640000
#define ET 64                   // edges per CTA
#define NCTA (EE / ET)          // 10000
#define ASTR 528                // h1 row stride bytes (264 halves)
#define YSTR 272                // x row stride bytes (136 halves)

// ---------------- device globals (no runtime alloc) ----------------
__device__ float g_x[NN * DN];
__device__ float g_out[NN * DN];
__device__ float g_ya[NN * 256];   // x@W1a^T + b1
__device__ float g_yb[NN * 256];   // x@W1b^T
__device__ int g_e64;
// pre-packed B fragments in per-lane mma order (hi,lo interleaved uint4 pairs)
__device__ uint4 g_f1[16384];   // W1: [og4][side2][ks8][nq4][lane32][hi/lo]
__device__ uint4 g_f2[8192];    // W2: [og4][ks16][nq2][lane32][hi/lo]
__device__ uint4 g_fl[4096];    // lin_w: [og8][ks8][lane32][hi/lo]
__device__ uint4 g_fn1[4096];   // nm_w1: [og8][ks8][lane32][hi/lo]
__device__ uint4 g_fn2[4096];   // nm_w2: [og8][ks8][lane32][hi/lo]

// ---------------- k_edge smem layout (bytes) ----------------
#define SB_ROWS 0
#define SB_COLS 256
#define SB_DE   512
#define SB_EMS  768
#define SB_ATT  1024
#define SB_PART 1280
#define SB_B2   2304
#define SB_W3   2816
#define SB_W1C  3328
#define SB_A_HI 4352            // 64 x 528 = 33792
#define SB_A_LO 38144           // 33792
#define SMEM_EDGE 71936

// ---------------- k_xy smem layout ----------------
#define SY_A_HI 0               // 32 x 272 = 8704
#define SY_A_LO 8704
#define SY_B1   17408           // 256 f
#define SY_LB   18432           // 128 f
#define SMEM_Y  18944

// ---------------- k_node smem layout ----------------
#define SN_A_HI 0               // 32 x 272 = 8704
#define SN_A_LO 8704
#define SN_MID  17408           // 32 x 132 f = 16896
#define SN_B1   34304           // 128 f
#define SN_B2   34816
#define SN_G1   35328
#define SN_BB1  35840
#define SN_G2   36352
#define SN_BB2  36864
#define SMEM_N  37376

__device__ __forceinline__ u32 smem_u32(const void* p) {
    u32 a;
    asm("{ .reg .u64 t; cvta.to.shared.u64 t, %1; cvt.u32.u64 %0, t; }" : "=r"(a) : "l"(p));
    return a;
}
// fast sigmoid/silu: MUFU.RCP instead of IEEE div chain
__device__ __forceinline__ float sigm(float v) {
    return __fdividef(1.0f, 1.0f + __expf(-v));
}
__device__ __forceinline__ float silu_(float v) { return v * sigm(v); }

__device__ __forceinline__ void bsplit(float v, u16& h, u16& l) {
    __nv_bfloat16 hb = __float2bfloat16(v);
    __nv_bfloat16 lb = __float2bfloat16(v - __bfloat162float(hb));
    h = __bfloat16_as_ushort(hb);
    l = __bfloat16_as_ushort(lb);
}

// ldmatrix m16k16 (A, row-major, stride S bytes)
template <int S>
__device__ __forceinline__ void ldmA(u32 r[4], u32 base, int row0, int kh) {
    int lane = threadIdx.x & 31;
    int quad = lane >> 3;
    u32 addr = base + (u32)(row0 + (lane & 7) + (quad & 1) * 8) * S +
               (u32)kh * 2 + (u32)(quad >> 1) * 16;
    asm volatile("ldmatrix.sync.aligned.m8n8.x4.shared.b16 {%0,%1,%2,%3}, [%4];"
                 : "=r"(r[0]), "=r"(r[1]), "=r"(r[2]), "=r"(r[3]) : "r"(addr));
}
__device__ __forceinline__ void mma16816(float d[4], const u32 a[4], u32 b0, u32 b1) {
    asm volatile("mma.sync.aligned.m16n8k16.row.col.f32.bf16.bf16.f32 "
                 "{%0,%1,%2,%3}, {%4,%5,%6,%7}, {%8,%9}, {%0,%1,%2,%3};"
                 : "+f"(d[0]), "+f"(d[1]), "+f"(d[2]), "+f"(d[3])
                 : "r"(a[0]), "r"(a[1]), "r"(a[2]), "r"(a[3]), "r"(b0), "r"(b1));
}

// pack a 128x128 K-major fp32 weight into per-lane frag pairs at table[j*2(+1)]
__device__ __forceinline__ void pack128(const float* __restrict__ w, uint4* tab, int j) {
    int lane = j & 31, ks = (j >> 5) & 7, og = (j >> 8) & 7;
    int nb0 = og * 16 + (lane >> 2);
    int kb = ks * 16 + (lane & 3) * 2;
    u32 wh[4], wl[4];
#pragma unroll
    for (int nb = 0; nb < 2; nb++)
#pragma unroll
        for (int r = 0; r < 2; r++) {
            const float* p = &w[(nb0 + nb * 8) * 128 + kb + r * 8];
            u16 h0, l0, h1, l1;
            bsplit(p[0], h0, l0);
            bsplit(p[1], h1, l1);
            wh[nb * 2 + r] = (u32)h0 | ((u32)h1 << 16);
            wl[nb * 2 + r] = (u32)l0 | ((u32)l1 << 16);
        }
    tab[j * 2] = make_uint4(wh[0], wh[1], wh[2], wh[3]);
    tab[j * 2 + 1] = make_uint4(wl[0], wl[1], wl[2], wl[3]);
}

// ---------------------------------------------------------------------------
// k_prep: pack W1/W2/lin_w/nm_w1/nm_w2 into fragment tables. grid 72 x 256.
// ---------------------------------------------------------------------------
__global__ void k_prep(const float* __restrict__ w1, const float* __restrict__ w2,
                       const float* __restrict__ lw, const float* __restrict__ nw1,
                       const float* __restrict__ nw2, const void* __restrict__ edges) {
    int idx = blockIdx.x * 256 + threadIdx.x;
    if (idx < 8192) {       // W1 frags [256 out][257 k]
        int lane = idx & 31, nq = (idx >> 5) & 3, ks = (idx >> 7) & 7;
        int side = (idx >> 10) & 1, og = (idx >> 11) & 3;
        int nb0 = og * 64 + nq * 16 + (lane >> 2);
        int kb = side * 128 + ks * 16 + (lane & 3) * 2;
        u32 wh[4], wl[4];
#pragma unroll
        for (int nb = 0; nb < 2; nb++)
#pragma unroll
            for (int r = 0; r < 2; r++) {
                const float* p = &w1[(nb0 + nb * 8) * 257 + kb + r * 8];
                u16 h0, l0, h1, l1;
                bsplit(p[0], h0, l0);
                bsplit(p[1], h1, l1);
                wh[nb * 2 + r] = (u32)h0 | ((u32)h1 << 16);
                wl[nb * 2 + r] = (u32)l0 | ((u32)l1 << 16);
            }
        g_f1[idx * 2] = make_uint4(wh[0], wh[1], wh[2], wh[3]);
        g_f1[idx * 2 + 1] = make_uint4(wl[0], wl[1], wl[2], wl[3]);
    } else if (idx < 12288) {  // W2 frags [128 out][256 k]
        int j = idx - 8192;
        int lane = j & 31, nq = (j >> 5) & 1, ks = (j >> 6) & 15, og = (j >> 10) & 3;
        int nb0 = og * 32 + nq * 16 + (lane >> 2);
        int kb = ks * 16 + (lane & 3) * 2;
        u32 wh[4], wl[4];
#pragma unroll
        for (int nb = 0; nb < 2; nb++)
#pragma unroll
            for (int r = 0; r < 2; r++) {
                const float* p = &w2[(nb0 + nb * 8) * 256 + kb + r * 8];
                u16 h0, l0, h1, l1;
                bsplit(p[0], h0, l0);
                bsplit(p[1], h1, l1);
                wh[nb * 2 + r] = (u32)h0 | ((u32)h1 << 16);
                wl[nb * 2 + r] = (u32)l0 | ((u32)l1 << 16);
            }
        g_f2[j * 2] = make_uint4(wh[0], wh[1], wh[2], wh[3]);
        g_f2[j * 2 + 1] = make_uint4(wl[0], wl[1], wl[2], wl[3]);
    } else if (idx < 14336) {  // lin_w frags [128 out][128 k]
        pack128(lw, g_fl, idx - 12288);
    } else if (idx < 16384) {  // nm_w1 frags
        pack128(nw1, g_fn1, idx - 14336);
    } else {                   // nm_w2 frags
        pack128(nw2, g_fn2, idx - 16384);
    }
    if (idx == 0) {
        const int* e32 = (const int*)edges;
        int nz = 0;
        for (int i = 0; i < 16; i++) nz |= e32[2 * i + 1];
        g_e64 = (nz == 0) ? 1 : 0;
    }
}

__global__ void k_zero() {
    int i = blockIdx.x * 256 + threadIdx.x;
    if (i < NN * DN) g_out[i] = 0.0f;
}

// ---------------------------------------------------------------------------
// k_xy: fused  x = h@lin_w^T + lin_b ;  ya = x@W1a^T + b1 ;  yb = x@W1b^T.
// 32 nodes/CTA. Phase1: 8 warps x 16 outs. Phase2: warps 0-3 ya, 4-7 yb.
// ---------------------------------------------------------------------------
__global__ __launch_bounds__(256, 1) void k_xy(const float* __restrict__ h,
                                               const float* __restrict__ lb,
                                               const float* __restrict__ b1) {
    extern __shared__ char smc[];
    u32 smb = smem_u32(smc);
    float* b1s = (float*)(smc + SY_B1);
    float* lbs = (float*)(smc + SY_LB);
    int tid = threadIdx.x, lane = tid & 31, warp = tid >> 5;
    int n0 = blockIdx.x * 32;

    b1s[tid] = b1[tid];
    if (tid < 128) lbs[tid] = lb[tid];
    // load h tile (hi/lo split) — warp handles 4 nodes
#pragma unroll
    for (int i = 0; i < 4; i++) {
        int el = warp * 4 + i;
        const float4 v = *(const float4*)&h[(size_t)(n0 + el) * DN + lane * 4];
        u16 h0, l0, h1, l1, h2, l2, h3, l3;
        bsplit(v.x, h0, l0); bsplit(v.y, h1, l1); bsplit(v.z, h2, l2); bsplit(v.w, h3, l3);
        u64 hp = (u64)h0 | ((u64)h1 << 16) | ((u64)h2 << 32) | ((u64)h3 << 48);
        u64 lp = (u64)l0 | ((u64)l1 << 16) | ((u64)l2 << 32) | ((u64)l3 << 48);
        *(u64*)(smc + SY_A_HI + el * YSTR + lane * 8) = hp;
        *(u64*)(smc + SY_A_LO + el * YSTR + lane * 8) = lp;
    }
    __syncthreads();

    // ---- phase 1: x = h@lin_w^T + lin_b.  warp -> outs [warp*16, +16) ----
    {
        float accl[2][2][4] = {};
#pragma unroll
        for (int ks = 0; ks < 8; ks++) {
            int ka = ks * 16;
            u32 ah[2][4], al_[2][4];
            ldmA<YSTR>(ah[0], smb + SY_A_HI, 0, ka);
            ldmA<YSTR>(ah[1], smb + SY_A_HI, 16, ka);
            ldmA<YSTR>(al_[0], smb + SY_A_LO, 0, ka);
            ldmA<YSTR>(al_[1], smb + SY_A_LO, 16, ka);
            int fbase = ((warp * 8 + ks) * 32 + lane) * 2;
            uint4 fh = g_fl[fbase];
            uint4 fl = g_fl[fbase + 1];
#pragma unroll
            for (int mt = 0; mt < 2; mt++) {
                mma16816(accl[mt][0], ah[mt], fh.x, fh.y);
                mma16816(accl[mt][0], ah[mt], fl.x, fl.y);
                mma16816(accl[mt][0], al_[mt], fh.x, fh.y);
                mma16816(accl[mt][1], ah[mt], fh.z, fh.w);
                mma16816(accl[mt][1], ah[mt], fl.z, fl.w);
                mma16816(accl[mt][1], al_[mt], fh.z, fh.w);
            }
        }
        __syncthreads();   // done reading h tile; overlay x tile
        int r0 = lane >> 2, cb = (lane & 3) * 2;
#pragma unroll
        for (int mt = 0; mt < 2; mt++) {
#pragma unroll
            for (int nb = 0; nb < 2; nb++) {
                int o = warp * 16 + nb * 8 + cb;
                float ba = lbs[o], bb = lbs[o + 1];
                float v0 = accl[mt][nb][0] + ba, v1 = accl[mt][nb][1] + bb;
                float v2 = accl[mt][nb][2] + ba, v3 = accl[mt][nb][3] + bb;
                int nl = mt * 16 + r0;
                *(float2*)&g_x[(size_t)(n0 + nl) * DN + o] = make_float2(v0, v1);
                *(float2*)&g_x[(size_t)(n0 + nl + 8) * DN + o] = make_float2(v2, v3);
                u16 h0, l0, h1, l1;
                bsplit(v0, h0, l0); bsplit(v1, h1, l1);
                *(u32*)(smc + SY_A_HI + nl * YSTR + o * 2) = (u32)h0 | ((u32)h1 << 16);
                *(u32*)(smc + SY_A_LO + nl * YSTR + o * 2) = (u32)l0 | ((u32)l1 << 16);
                bsplit(v2, h0, l0); bsplit(v3, h1, l1);
                *(u32*)(smc + SY_A_HI + (nl + 8) * YSTR + o * 2) = (u32)h0 | ((u32)h1 << 16);
                *(u32*)(smc + SY_A_LO + (nl + 8) * YSTR + o * 2) = (u32)l0 | ((u32)l1 << 16);
            }
        }
    }
    __syncthreads();

    // ---- phase 2: ya/yb.  warps 0-3 -> ya (side 0), 4-7 -> yb ----
    int side = warp >> 2, og1 = warp & 3;
    float acc[2][8][4] = {};
#pragma unroll
    for (int ks = 0; ks < 8; ks++) {
        int ka = ks * 16;
        u32 ah[2][4], al_[2][4];
        ldmA<YSTR>(ah[0], smb + SY_A_HI, 0, ka);
        ldmA<YSTR>(ah[1], smb + SY_A_HI, 16, ka);
        ldmA<YSTR>(al_[0], smb + SY_A_LO, 0, ka);
        ldmA<YSTR>(al_[1], smb + SY_A_LO, 16, ka);
        int fbase = ((((og1 * 2 + side) * 8 + ks) * 4) * 32 + lane) * 2;
#pragma unroll
        for (int nq = 0; nq < 4; nq++) {
            uint4 fh = g_f1[fbase + nq * 64];
            uint4 fl = g_f1[fbase + nq * 64 + 1];
#pragma unroll
            for (int mt = 0; mt < 2; mt++) {
                mma16816(acc[mt][nq * 2], ah[mt], fh.x, fh.y);
                mma16816(acc[mt][nq * 2], ah[mt], fl.x, fl.y);
                mma16816(acc[mt][nq * 2], al_[mt], fh.x, fh.y);
                mma16816(acc[mt][nq * 2 + 1], ah[mt], fh.z, fh.w);
                mma16816(acc[mt][nq * 2 + 1], ah[mt], fl.z, fl.w);
                mma16816(acc[mt][nq * 2 + 1], al_[mt], fh.z, fh.w);
            }
        }
    }
    // epilogue: store (ya += b1)
    {
        int r0 = lane >> 2, cb = (lane & 3) * 2;
        float* dst = side == 0 ? g_ya : g_yb;
#pragma unroll
        for (int mt = 0; mt < 2; mt++) {
            int node = n0 + mt * 16 + r0;
#pragma unroll
            for (int nb = 0; nb < 8; nb++) {
                int o = og1 * 64 + nb * 8 + cb;
                float ba = side == 0 ? b1s[o] : 0.0f;
                float bb = side == 0 ? b1s[o + 1] : 0.0f;
                float2 v0 = make_float2(acc[mt][nb][0] + ba, acc[mt][nb][1] + bb);
                float2 v1 = make_float2(acc[mt][nb][2] + ba, acc[mt][nb][3] + bb);
                *(float2*)&dst[(size_t)node * 256 + o] = v0;
                *(float2*)&dst[(size_t)(node + 8) * 256 + o] = v1;
            }
        }
    }
}

// ---------------------------------------------------------------------------
// Fused edge kernel: gather ya/yb -> silu -> GEMM2 (mma bf16 hi/lo) -> att
// -> scatter (red.global.v4).  64 edges/CTA, 8 warps = 2 eg x 4 og, 3 CTAs/SM.
// ---------------------------------------------------------------------------
__global__ __launch_bounds__(256, 3) void k_edge(
    const float* __restrict__ dist, const float* __restrict__ emask,
    const float* __restrict__ w1, const float* __restrict__ b2,
    const float* __restrict__ w3, const float* __restrict__ b3,
    const void* __restrict__ edges) {
    extern __shared__ char smc[];
    u32 smb = smem_u32(smc);
    float* smf = (float*)smc;
    int* rows = (int*)(smc + SB_ROWS);
    int* cols = (int*)(smc + SB_COLS);

    int tid = threadIdx.x, lane = tid & 31, warp = tid >> 5;
    int eg = warp & 1, og = warp >> 1;   // 2 edge-groups x 4 out-groups
    int Eb = eg * 32;
    int e0 = blockIdx.x * ET;

    // stage small vectors
    smf[SB_W1C / 4 + tid] = w1[tid * 257 + 256];
    if (tid < 128) {
        smf[SB_B2 / 4 + tid] = b2[tid];
        smf[SB_W3 / 4 + tid] = w3[tid];
    }
    if (tid < 64) {
        int e = e0 + tid;
        if (g_e64) {
            const long long* e64 = (const long long*)edges;
            rows[tid] = (int)e64[e];
            cols[tid] = (int)e64[EE + e];
        } else {
            const int* ei = (const int*)edges;
            rows[tid] = ei[e];
            cols[tid] = ei[EE + e];
        }
        float em = emask[e];
        smf[SB_EMS / 4 + tid] = em;
        smf[SB_DE / 4 + tid] = dist[e] * em;
    }
    __syncthreads();

    // ---- gather ya[row]+yb[col]+de*w1c -> silu -> h1 bf16 hi/lo tile ----
    {
        float4 wc0 = *(const float4*)(smf + SB_W1C / 4 + lane * 4);
        float4 wc1 = *(const float4*)(smf + SB_W1C / 4 + lane * 4 + 128);
#pragma unroll
        for (int i = 0; i < 8; i++) {
            int el = warp * 8 + i;
            const float* ya = &g_ya[(size_t)rows[el] * 256];
            const float* yb = &g_yb[(size_t)cols[el] * 256];
            float de = smf[SB_DE / 4 + el];
#pragma unroll
            for (int j = 0; j < 2; j++) {
                int o4 = lane * 4 + j * 128;
                float4 a4 = *(const float4*)(ya + o4);
                float4 b4 = *(const float4*)(yb + o4);
                float4 wc = j == 0 ? wc0 : wc1;
                float v0 = silu_(a4.x + b4.x + de * wc.x);
                float v1 = silu_(a4.y + b4.y + de * wc.y);
                float v2 = silu_(a4.z + b4.z + de * wc.z);
                float v3 = silu_(a4.w + b4.w + de * wc.w);
                u16 h0, l0, h1, l1, h2, l2, h3, l3;
                bsplit(v0, h0, l0); bsplit(v1, h1, l1); bsplit(v2, h2, l2); bsplit(v3, h3, l3);
                u64 hp = (u64)h0 | ((u64)h1 << 16) | ((u64)h2 << 32) | ((u64)h3 << 48);
                u64 lp = (u64)l0 | ((u64)l1 << 16) | ((u64)l2 << 32) | ((u64)l3 << 48);
                *(u64*)(smc + SB_A_HI + el * ASTR + o4 * 2) = hp;
                *(u64*)(smc + SB_A_LO + el * ASTR + o4 * 2) = lp;
            }
        }
    }
    __syncthreads();

    // ---- GEMM2: D2[64e x 128o], warp slice 32e x 32o, K=256 ----
    float acc2[2][4][4] = {};
#pragma unroll
    for (int ks = 0; ks < 16; ks++) {
        int ka = ks * 16;
        u32 ah[2][4], al_[2][4];
        ldmA<ASTR>(ah[0], smb + SB_A_HI, Eb, ka);
        ldmA<ASTR>(ah[1], smb + SB_A_HI, Eb + 16, ka);
        ldmA<ASTR>(al_[0], smb + SB_A_LO, Eb, ka);
        ldmA<ASTR>(al_[1], smb + SB_A_LO, Eb + 16, ka);
        int fbase = (((og * 16 + ks) * 2) * 32 + lane) * 2;
#pragma unroll
        for (int nq = 0; nq < 2; nq++) {
            uint4 fh = g_f2[fbase + nq * 64];
            uint4 fl = g_f2[fbase + nq * 64 + 1];
#pragma unroll
            for (int mt = 0; mt < 2; mt++) {
                mma16816(acc2[mt][nq * 2], ah[mt], fh.x, fh.y);
                mma16816(acc2[mt][nq * 2], ah[mt], fl.x, fl.y);
                mma16816(acc2[mt][nq * 2], al_[mt], fh.x, fh.y);
                mma16816(acc2[mt][nq * 2 + 1], ah[mt], fh.z, fh.w);
                mma16816(acc2[mt][nq * 2 + 1], ah[mt], fl.z, fl.w);
                mma16816(acc2[mt][nq * 2 + 1], al_[mt], fh.z, fh.w);
            }
        }
    }

    // ---- epilogue2: att partials, cross-og combine ----
    {
        int r0 = lane >> 2, cb = (lane & 3) * 2;
        float p[2][2] = {};
#pragma unroll
        for (int mt = 0; mt < 2; mt++)
#pragma unroll
            for (int nb = 0; nb < 4; nb++) {
                int o = og * 32 + nb * 8 + cb;
                float b2a = smf[SB_B2 / 4 + o], b2b = smf[SB_B2 / 4 + o + 1];
                float w3a = smf[SB_W3 / 4 + o], w3b = smf[SB_W3 / 4 + o + 1];
                p[mt][0] += silu_(acc2[mt][nb][0] + b2a) * w3a + silu_(acc2[mt][nb][1] + b2b) * w3b;
                p[mt][1] += silu_(acc2[mt][nb][2] + b2a) * w3a + silu_(acc2[mt][nb][3] + b2b) * w3b;
            }
#pragma unroll
        for (int off = 1; off <= 2; off <<= 1)
#pragma unroll
            for (int mt = 0; mt < 2; mt++) {
                p[mt][0] += __shfl_xor_sync(0xffffffffu, p[mt][0], off);
                p[mt][1] += __shfl_xor_sync(0xffffffffu, p[mt][1], off);
            }
        if ((lane & 3) == 0) {
#pragma unroll
            for (int mt = 0; mt < 2; mt++) {
                int e = Eb + mt * 16 + r0;
                smf[SB_PART / 4 + og * 64 + e] = p[mt][0];
                smf[SB_PART / 4 + og * 64 + e + 8] = p[mt][1];
            }
        }
    }
    __syncthreads();
    if (tid < 64) {
        float z = smf[SB_PART / 4 + tid] + smf[SB_PART / 4 + 64 + tid] +
                  smf[SB_PART / 4 + 128 + tid] + smf[SB_PART / 4 + 192 + tid] + b3[0];
        smf[SB_ATT / 4 + tid] = sigm(z) * smf[SB_EMS / 4 + tid];
    }
    __syncthreads();

    // ---- scatter: g_out[row] += x_col * att  (vector reduction, no return) ----
#pragma unroll
    for (int i = 0; i < 8; i++) {
        int el = warp * 8 + i;
        float a = smf[SB_ATT / 4 + el];
        const float4 v = *(const float4*)&g_x[(size_t)cols[el] * DN + lane * 4];
        float* dst = &g_out[(size_t)rows[el] * DN + lane * 4];
        asm volatile("red.global.add.v4.f32 [%0], {%1, %2, %3, %4};"
                     :: "l"(dst), "f"(v.x * a), "f"(v.y * a), "f"(v.z * a), "f"(v.w * a)
                     : "memory");
    }
}

// ---------------------------------------------------------------------------
// k_node (mma): node_mlp + residual + final LN + silu.  32 nodes/CTA.
// GEMMs via fragment tables; LN via smem round-trip + warp shuffles.
// ---------------------------------------------------------------------------
__global__ __launch_bounds__(256, 3) void k_node(
    const float* __restrict__ b1, const float* __restrict__ g1,
    const float* __restrict__ bb1, const float* __restrict__ b2,
    const float* __restrict__ g2, const float* __restrict__ bb2,
    float* __restrict__ out) {
    extern __shared__ char smc[];
    u32 smb = smem_u32(smc);
    float* mid = (float*)(smc + SN_MID);
    float* b1s = (float*)(smc + SN_B1);
    float* b2s = (float*)(smc + SN_B2);
    float* g1s = (float*)(smc + SN_G1);
    float* bb1s = (float*)(smc + SN_BB1);
    float* g2s = (float*)(smc + SN_G2);
    float* bb2s = (float*)(smc + SN_BB2);
    int tid = threadIdx.x, lane = tid & 31, warp = tid >> 5;
    int n0 = blockIdx.x * 32;

    if (tid < 128) {
        b1s[tid] = b1[tid]; b2s[tid] = b2[tid];
        g1s[tid] = g1[tid]; bb1s[tid] = bb1[tid];
        g2s[tid] = g2[tid]; bb2s[tid] = bb2[tid];
    }
    // load input (g_out / NORM_FACTOR), bsplit -> A
#pragma unroll
    for (int i = 0; i < 4; i++) {
        int el = warp * 4 + i;
        float4 v = *(const float4*)&g_out[(size_t)(n0 + el) * DN + lane * 4];
        v.x *= 0.01f; v.y *= 0.01f; v.z *= 0.01f; v.w *= 0.01f;
        u16 h0, l0, h1, l1, h2, l2, h3, l3;
        bsplit(v.x, h0, l0); bsplit(v.y, h1, l1); bsplit(v.z, h2, l2); bsplit(v.w, h3, l3);
        u64 hp = (u64)h0 | ((u64)h1 << 16) | ((u64)h2 << 32) | ((u64)h3 << 48);
        u64 lp = (u64)l0 | ((u64)l1 << 16) | ((u64)l2 << 32) | ((u64)l3 << 48);
        *(u64*)(smc + SN_A_HI + el * YSTR + lane * 8) = hp;
        *(u64*)(smc + SN_A_LO + el * YSTR + lane * 8) = lp;
    }
    __syncthreads();

    int r0 = lane >> 2, cb = (lane & 3) * 2;

    // ---- GEMM1 (nm_w1): warp -> outs [warp*16, +16) ----
    {
        float acc[2][2][4] = {};
#pragma unroll
        for (int ks = 0; ks < 8; ks++) {
            int ka = ks * 16;
            u32 ah[2][4], al_[2][4];
            ldmA<YSTR>(ah[0], smb + SN_A_HI, 0, ka);
            ldmA<YSTR>(ah[1], smb + SN_A_HI, 16, ka);
            ldmA<YSTR>(al_[0], smb + SN_A_LO, 0, ka);
            ldmA<YSTR>(al_[1], smb + SN_A_LO, 16, ka);
            int fbase = ((warp * 8 + ks) * 32 + lane) * 2;
            uint4 fh = g_fn1[fbase];
            uint4 fl = g_fn1[fbase + 1];
#pragma unroll
            for (int mt = 0; mt < 2; mt++) {
                mma16816(acc[mt][0], ah[mt], fh.x, fh.y);
                mma16816(acc[mt][0], ah[mt], fl.x, fl.y);
                mma16816(acc[mt][0], al_[mt], fh.x, fh.y);
                mma16816(acc[mt][1], ah[mt], fh.z, fh.w);
                mma16816(acc[mt][1], ah[mt], fl.z, fl.w);
                mma16816(acc[mt][1], al_[mt], fh.z, fh.w);
            }
        }
        // store +b1 to MID
#pragma unroll
        for (int mt = 0; mt < 2; mt++)
#pragma unroll
            for (int nb = 0; nb < 2; nb++) {
                int o = warp * 16 + nb * 8 + cb;
                float ba = b1s[o], bb = b1s[o + 1];
                int nl = mt * 16 + r0;
                *(float2*)&mid[nl * 132 + o] = make_float2(acc[mt][nb][0] + ba, acc[mt][nb][1] + bb);
                *(float2*)&mid[(nl + 8) * 132 + o] = make_float2(acc[mt][nb][2] + ba, acc[mt][nb][3] + bb);
            }
    }
    __syncthreads();

    // ---- LN1 + silu -> A (bf16 hi/lo) ----
#pragma unroll
    for (int i = 0; i < 4; i++) {
        int nl = warp * 4 + i;
        float v[4], s1 = 0.f, s2 = 0.f;
#pragma unroll
        for (int j = 0; j < 4; j++) {
            v[j] = mid[nl * 132 + lane + 32 * j];
            s1 += v[j]; s2 += v[j] * v[j];
        }
#pragma unroll
        for (int off = 16; off > 0; off >>= 1) {
            s1 += __shfl_xor_sync(0xffffffffu, s1, off);
            s2 += __shfl_xor_sync(0xffffffffu, s2, off);
        }
        float mean = s1 * (1.0f / 128.0f);
        float var = s2 * (1.0f / 128.0f) - mean * mean;
        float inv = rsqrtf(var + 1e-5f);
#pragma unroll
        for (int j = 0; j < 4; j++) {
            int o = lane + 32 * j;
            float y = silu_((v[j] - mean) * inv * g1s[o] + bb1s[o]);
            u16 hh, ll;
            bsplit(y, hh, ll);
            *(u16*)(smc + SN_A_HI + nl * YSTR + o * 2) = hh;
            *(u16*)(smc + SN_A_LO + nl * YSTR + o * 2) = ll;
        }
    }
    __syncthreads();

    // ---- GEMM2 (nm_w2) ----
    {
        float acc[2][2][4] = {};
#pragma unroll
        for (int ks = 0; ks < 8; ks++) {
            int ka = ks * 16;
            u32 ah[2][4], al_[2][4];
            ldmA<YSTR>(ah[0], smb + SN_A_HI, 0, ka);
            ldmA<YSTR>(ah[1], smb + SN_A_HI, 16, ka);
            ldmA<YSTR>(al_[0], smb + SN_A_LO, 0, ka);
            ldmA<YSTR>(al_[1], smb + SN_A_LO, 16, ka);
            int fbase = ((warp * 8 + ks) * 32 + lane) * 2;
            uint4 fh = g_fn2[fbase];
            uint4 fl = g_fn2[fbase + 1];
#pragma unroll
            for (int mt = 0; mt < 2; mt++) {
                mma16816(acc[mt][0], ah[mt], fh.x, fh.y);
                mma16816(acc[mt][0], ah[mt], fl.x, fl.y);
                mma16816(acc[mt][0], al_[mt], fh.x, fh.y);
                mma16816(acc[mt][1], ah[mt], fh.z, fh.w);
                mma16816(acc[mt][1], ah[mt], fl.z, fl.w);
                mma16816(acc[mt][1], al_[mt], fh.z, fh.w);
            }
        }
        // store +b2 to MID
#pragma unroll
        for (int mt = 0; mt < 2; mt++)
#pragma unroll
            for (int nb = 0; nb < 2; nb++) {
                int o = warp * 16 + nb * 8 + cb;
                float ba = b2s[o], bb = b2s[o + 1];
                int nl = mt * 16 + r0;
                *(float2*)&mid[nl * 132 + o] = make_float2(acc[mt][nb][0] + ba, acc[mt][nb][1] + bb);
                *(float2*)&mid[(nl + 8) * 132 + o] = make_float2(acc[mt][nb][2] + ba, acc[mt][nb][3] + bb);
            }
    }
    __syncthreads();

    // ---- + residual, LN2, silu, store ----
#pragma unroll
    for (int i = 0; i < 4; i++) {
        int nl = warp * 4 + i;
        float v[4], s1 = 0.f, s2 = 0.f;
#pragma unroll
        for (int j = 0; j < 4; j++) {
            int o = lane + 32 * j;
            v[j] = mid[nl * 132 + o] + g_x[(size_t)(n0 + nl) * DN + o];
            s1 += v[j]; s2 += v[j] * v[j];
        }
#pragma unroll
        for (int off = 16; off > 0; off >>= 1) {
            s1 += __shfl_xor_sync(0xffffffffu, s1, off);
            s2 += __shfl_xor_sync(0xffffffffu, s2, off);
        }
        float mean = s1 * (1.0f / 128.0f);
        float var = s2 * (1.0f / 128.0f) - mean * mean;
        float inv = rsqrtf(var + 1e-5f);
#pragma unroll
        for (int j = 0; j < 4; j++) {
            int o = lane + 32 * j;
            float y = (v[j] - mean) * inv * g2s[o] + bb2s[o];
            out[(size_t)(n0 + nl) * DN + o] = silu_(y);
        }
    }
}

// ---------------------------------------------------------------------------
extern "C" void kernel_launch(void* const* d_in, const int* in_sizes, int n_in,
                              void* d_out, int out_size) {
    const float* h = (const float*)d_in[0];
    const float* distances = (const float*)d_in[1];
    const float* edge_mask = (const float*)d_in[3];
    const float* lin_w = (const float*)d_in[4];
    const float* lin_b = (const float*)d_in[5];
    const float* att_w1 = (const float*)d_in[6];
    const float* att_b1 = (const float*)d_in[7];
    const float* att_w2 = (const float*)d_in[8];
    const float* att_b2 = (const float*)d_in[9];
    const float* att_w3 = (const float*)d_in[10];
    const float* att_b3 = (const float*)d_in[11];
    const float* nm_w1 = (const float*)d_in[12];
    const float* nm_b1 = (const float*)d_in[13];
    const float* nm_ln_g = (const float*)d_in[14];
    const float* nm_ln_b = (const float*)d_in[15];
    const float* nm_w2 = (const float*)d_in[16];
    const float* nm_b2 = (const float*)d_in[17];
    const float* ln_g = (const float*)d_in[18];
    const float* ln_b = (const float*)d_in[19];
    const void* edges = d_in[20];

    cudaFuncSetAttribute(k_xy, cudaFuncAttributeMaxDynamicSharedMemorySize, SMEM_Y);
    cudaFuncSetAttribute(k_edge, cudaFuncAttributeMaxDynamicSharedMemorySize, SMEM_EDGE);
    cudaFuncSetAttribute(k_node, cudaFuncAttributeMaxDynamicSharedMemorySize, SMEM_N);

    k_prep<<<72, 256>>>(att_w1, att_w2, lin_w, nm_w1, nm_w2, edges);
    k_zero<<<(NN * DN + 255) / 256, 256>>>();
    k_xy<<<625, 256, SMEM_Y>>>(h, lin_b, att_b1);
    k_edge<<<NCTA, 256, SMEM_EDGE>>>(distances, edge_mask, att_w1, att_b2,
                                     att_w3, att_b3, edges);
    k_node<<<625, 256, SMEM_N>>>(nm_b1, nm_ln_g, nm_ln_b,
                                 nm_b2, ln_g, ln_b, (float*)d_out);
}

// round 11
// speedup vs baseline: 8.7496x; 1.0368x over previous
#include <cuda_runtime.h>
#include <cuda_bf16.h>

typedef unsigned int u32;
typedef unsigned long long u64;
typedef unsigned short u16;

#define DN 128
#define NN 20000
#define EE 640000
#define ET 64                   // edges per CTA
#define NCTA (EE / ET)          // 10000
#define ASTR 528                // h1 row stride bytes (264 halves)
#define YSTR 272                // x row stride bytes (136 halves)

// ---------------- device globals (no runtime alloc) ----------------
__device__ float g_x[NN * DN];
__device__ float g_out[NN * DN];
__device__ float g_ya[NN * 256];   // x@W1a^T + b1
__device__ float g_yb[NN * 256];   // x@W1b^T
__device__ int g_e64;
// pre-packed B fragments in per-lane mma order (hi,lo interleaved uint4 pairs)
__device__ uint4 g_f1[16384];   // W1: [og4][side2][ks8][nq4][lane32][hi/lo]
__device__ uint4 g_f2[8192];    // W2: [og4][ks16][nq2][lane32][hi/lo]
__device__ uint4 g_fl[4096];    // lin_w: [og8][ks8][lane32][hi/lo]
__device__ uint4 g_fn1[4096];   // nm_w1: [og8][ks8][lane32][hi/lo]
__device__ uint4 g_fn2[4096];   // nm_w2: [og8][ks8][lane32][hi/lo]

// ---------------- k_edge smem layout (bytes) ----------------
#define SB_ROWS 0
#define SB_COLS 256
#define SB_DE   512
#define SB_EMS  768
#define SB_ATT  1024
#define SB_PART 1280
#define SB_B2   2304
#define SB_W3   2816
#define SB_W1C  3328
#define SB_A_HI 4352            // 64 x 528 = 33792
#define SB_A_LO 38144           // 33792
#define SMEM_EDGE 71936

// ---------------- k_xy smem layout ----------------
#define SY_A_HI 0               // 32 x 272 = 8704
#define SY_A_LO 8704
#define SY_B1   17408           // 256 f
#define SY_LB   18432           // 128 f
#define SMEM_Y  18944

// ---------------- k_node smem layout ----------------
#define SN_A_HI 0               // 32 x 272 = 8704
#define SN_A_LO 8704
#define SN_MID  17408           // 32 x 132 f = 16896
#define SN_B1   34304           // 128 f
#define SN_B2   34816
#define SN_G1   35328
#define SN_BB1  35840
#define SN_G2   36352
#define SN_BB2  36864
#define SMEM_N  37376

__device__ __forceinline__ u32 smem_u32(const void* p) {
    u32 a;
    asm("{ .reg .u64 t; cvta.to.shared.u64 t, %1; cvt.u32.u64 %0, t; }" : "=r"(a) : "l"(p));
    return a;
}
// fast sigmoid/silu: MUFU.RCP instead of IEEE div chain
__device__ __forceinline__ float sigm(float v) {
    return __fdividef(1.0f, 1.0f + __expf(-v));
}
__device__ __forceinline__ float silu_(float v) { return v * sigm(v); }

__device__ __forceinline__ void bsplit(float v, u16& h, u16& l) {
    __nv_bfloat16 hb = __float2bfloat16(v);
    __nv_bfloat16 lb = __float2bfloat16(v - __bfloat162float(hb));
    h = __bfloat16_as_ushort(hb);
    l = __bfloat16_as_ushort(lb);
}
// pack-pair split: (v0,v1) -> hi-pair u32 (v0 low half), lo-pair u32.
// Identical RN rounding to bsplit, ~40% fewer instructions.
__device__ __forceinline__ void bsplit2(float v0, float v1, u32& hp, u32& lp) {
    asm("cvt.rn.bf16x2.f32 %0, %1, %2;" : "=r"(hp) : "f"(v1), "f"(v0));
    float h0 = __uint_as_float(hp << 16);
    float h1 = __uint_as_float(hp & 0xffff0000u);
    asm("cvt.rn.bf16x2.f32 %0, %1, %2;" : "=r"(lp) : "f"(v1 - h1), "f"(v0 - h0));
}

// ldmatrix m16k16 (A, row-major, stride S bytes)
template <int S>
__device__ __forceinline__ void ldmA(u32 r[4], u32 base, int row0, int kh) {
    int lane = threadIdx.x & 31;
    int quad = lane >> 3;
    u32 addr = base + (u32)(row0 + (lane & 7) + (quad & 1) * 8) * S +
               (u32)kh * 2 + (u32)(quad >> 1) * 16;
    asm volatile("ldmatrix.sync.aligned.m8n8.x4.shared.b16 {%0,%1,%2,%3}, [%4];"
                 : "=r"(r[0]), "=r"(r[1]), "=r"(r[2]), "=r"(r[3]) : "r"(addr));
}
__device__ __forceinline__ void mma16816(float d[4], const u32 a[4], u32 b0, u32 b1) {
    asm volatile("mma.sync.aligned.m16n8k16.row.col.f32.bf16.bf16.f32 "
                 "{%0,%1,%2,%3}, {%4,%5,%6,%7}, {%8,%9}, {%0,%1,%2,%3};"
                 : "+f"(d[0]), "+f"(d[1]), "+f"(d[2]), "+f"(d[3])
                 : "r"(a[0]), "r"(a[1]), "r"(a[2]), "r"(a[3]), "r"(b0), "r"(b1));
}

// pack a 128x128 K-major fp32 weight into per-lane frag pairs at table[j*2(+1)]
__device__ __forceinline__ void pack128(const float* __restrict__ w, uint4* tab, int j) {
    int lane = j & 31, ks = (j >> 5) & 7, og = (j >> 8) & 7;
    int nb0 = og * 16 + (lane >> 2);
    int kb = ks * 16 + (lane & 3) * 2;
    u32 wh[4], wl[4];
#pragma unroll
    for (int nb = 0; nb < 2; nb++)
#pragma unroll
        for (int r = 0; r < 2; r++) {
            const float* p = &w[(nb0 + nb * 8) * 128 + kb + r * 8];
            u16 h0, l0, h1, l1;
            bsplit(p[0], h0, l0);
            bsplit(p[1], h1, l1);
            wh[nb * 2 + r] = (u32)h0 | ((u32)h1 << 16);
            wl[nb * 2 + r] = (u32)l0 | ((u32)l1 << 16);
        }
    tab[j * 2] = make_uint4(wh[0], wh[1], wh[2], wh[3]);
    tab[j * 2 + 1] = make_uint4(wl[0], wl[1], wl[2], wl[3]);
}

// ---------------------------------------------------------------------------
// k_prep: pack W1/W2/lin_w/nm_w1/nm_w2 into fragment tables. grid 72 x 256.
// ---------------------------------------------------------------------------
__global__ void k_prep(const float* __restrict__ w1, const float* __restrict__ w2,
                       const float* __restrict__ lw, const float* __restrict__ nw1,
                       const float* __restrict__ nw2, const void* __restrict__ edges) {
    int idx = blockIdx.x * 256 + threadIdx.x;
    if (idx < 8192) {       // W1 frags [256 out][257 k]
        int lane = idx & 31, nq = (idx >> 5) & 3, ks = (idx >> 7) & 7;
        int side = (idx >> 10) & 1, og = (idx >> 11) & 3;
        int nb0 = og * 64 + nq * 16 + (lane >> 2);
        int kb = side * 128 + ks * 16 + (lane & 3) * 2;
        u32 wh[4], wl[4];
#pragma unroll
        for (int nb = 0; nb < 2; nb++)
#pragma unroll
            for (int r = 0; r < 2; r++) {
                const float* p = &w1[(nb0 + nb * 8) * 257 + kb + r * 8];
                u16 h0, l0, h1, l1;
                bsplit(p[0], h0, l0);
                bsplit(p[1], h1, l1);
                wh[nb * 2 + r] = (u32)h0 | ((u32)h1 << 16);
                wl[nb * 2 + r] = (u32)l0 | ((u32)l1 << 16);
            }
        g_f1[idx * 2] = make_uint4(wh[0], wh[1], wh[2], wh[3]);
        g_f1[idx * 2 + 1] = make_uint4(wl[0], wl[1], wl[2], wl[3]);
    } else if (idx < 12288) {  // W2 frags [128 out][256 k]
        int j = idx - 8192;
        int lane = j & 31, nq = (j >> 5) & 1, ks = (j >> 6) & 15, og = (j >> 10) & 3;
        int nb0 = og * 32 + nq * 16 + (lane >> 2);
        int kb = ks * 16 + (lane & 3) * 2;
        u32 wh[4], wl[4];
#pragma unroll
        for (int nb = 0; nb < 2; nb++)
#pragma unroll
            for (int r = 0; r < 2; r++) {
                const float* p = &w2[(nb0 + nb * 8) * 256 + kb + r * 8];
                u16 h0, l0, h1, l1;
                bsplit(p[0], h0, l0);
                bsplit(p[1], h1, l1);
                wh[nb * 2 + r] = (u32)h0 | ((u32)h1 << 16);
                wl[nb * 2 + r] = (u32)l0 | ((u32)l1 << 16);
            }
        g_f2[j * 2] = make_uint4(wh[0], wh[1], wh[2], wh[3]);
        g_f2[j * 2 + 1] = make_uint4(wl[0], wl[1], wl[2], wl[3]);
    } else if (idx < 14336) {  // lin_w frags [128 out][128 k]
        pack128(lw, g_fl, idx - 12288);
    } else if (idx < 16384) {  // nm_w1 frags
        pack128(nw1, g_fn1, idx - 14336);
    } else {                   // nm_w2 frags
        pack128(nw2, g_fn2, idx - 16384);
    }
    if (idx == 0) {
        const int* e32 = (const int*)edges;
        int nz = 0;
        for (int i = 0; i < 16; i++) nz |= e32[2 * i + 1];
        g_e64 = (nz == 0) ? 1 : 0;
    }
}

__global__ void k_zero4() {
    int i = blockIdx.x * 256 + threadIdx.x;
    if (i < NN * DN / 4)
        *(float4*)&g_out[i * 4] = make_float4(0.f, 0.f, 0.f, 0.f);
}

// ---------------------------------------------------------------------------
// k_xy: fused  x = h@lin_w^T + lin_b ;  ya = x@W1a^T + b1 ;  yb = x@W1b^T.
// 32 nodes/CTA, 2 CTAs/SM (phase-2 split into two nq-passes: 32 acc regs).
// ---------------------------------------------------------------------------
__global__ __launch_bounds__(256, 2) void k_xy(const float* __restrict__ h,
                                               const float* __restrict__ lb,
                                               const float* __restrict__ b1) {
    extern __shared__ char smc[];
    u32 smb = smem_u32(smc);
    float* b1s = (float*)(smc + SY_B1);
    float* lbs = (float*)(smc + SY_LB);
    int tid = threadIdx.x, lane = tid & 31, warp = tid >> 5;
    int n0 = blockIdx.x * 32;

    b1s[tid] = b1[tid];
    if (tid < 128) lbs[tid] = lb[tid];
    // load h tile (hi/lo split) — warp handles 4 nodes
#pragma unroll
    for (int i = 0; i < 4; i++) {
        int el = warp * 4 + i;
        const float4 v = *(const float4*)&h[(size_t)(n0 + el) * DN + lane * 4];
        u32 hp0, lp0, hp1, lp1;
        bsplit2(v.x, v.y, hp0, lp0);
        bsplit2(v.z, v.w, hp1, lp1);
        *(u64*)(smc + SY_A_HI + el * YSTR + lane * 8) = (u64)hp0 | ((u64)hp1 << 32);
        *(u64*)(smc + SY_A_LO + el * YSTR + lane * 8) = (u64)lp0 | ((u64)lp1 << 32);
    }
    __syncthreads();

    // ---- phase 1: x = h@lin_w^T + lin_b.  warp -> outs [warp*16, +16) ----
    {
        float accl[2][2][4] = {};
#pragma unroll
        for (int ks = 0; ks < 8; ks++) {
            int ka = ks * 16;
            u32 ah[2][4], al_[2][4];
            ldmA<YSTR>(ah[0], smb + SY_A_HI, 0, ka);
            ldmA<YSTR>(ah[1], smb + SY_A_HI, 16, ka);
            ldmA<YSTR>(al_[0], smb + SY_A_LO, 0, ka);
            ldmA<YSTR>(al_[1], smb + SY_A_LO, 16, ka);
            int fbase = ((warp * 8 + ks) * 32 + lane) * 2;
            uint4 fh = g_fl[fbase];
            uint4 fl = g_fl[fbase + 1];
#pragma unroll
            for (int mt = 0; mt < 2; mt++) {
                mma16816(accl[mt][0], ah[mt], fh.x, fh.y);
                mma16816(accl[mt][0], ah[mt], fl.x, fl.y);
                mma16816(accl[mt][0], al_[mt], fh.x, fh.y);
                mma16816(accl[mt][1], ah[mt], fh.z, fh.w);
                mma16816(accl[mt][1], ah[mt], fl.z, fl.w);
                mma16816(accl[mt][1], al_[mt], fh.z, fh.w);
            }
        }
        __syncthreads();   // done reading h tile; overlay x tile
        int r0 = lane >> 2, cb = (lane & 3) * 2;
#pragma unroll
        for (int mt = 0; mt < 2; mt++) {
#pragma unroll
            for (int nb = 0; nb < 2; nb++) {
                int o = warp * 16 + nb * 8 + cb;
                float ba = lbs[o], bb = lbs[o + 1];
                float v0 = accl[mt][nb][0] + ba, v1 = accl[mt][nb][1] + bb;
                float v2 = accl[mt][nb][2] + ba, v3 = accl[mt][nb][3] + bb;
                int nl = mt * 16 + r0;
                *(float2*)&g_x[(size_t)(n0 + nl) * DN + o] = make_float2(v0, v1);
                *(float2*)&g_x[(size_t)(n0 + nl + 8) * DN + o] = make_float2(v2, v3);
                u32 hp, lp;
                bsplit2(v0, v1, hp, lp);
                *(u32*)(smc + SY_A_HI + nl * YSTR + o * 2) = hp;
                *(u32*)(smc + SY_A_LO + nl * YSTR + o * 2) = lp;
                bsplit2(v2, v3, hp, lp);
                *(u32*)(smc + SY_A_HI + (nl + 8) * YSTR + o * 2) = hp;
                *(u32*)(smc + SY_A_LO + (nl + 8) * YSTR + o * 2) = lp;
            }
        }
    }
    __syncthreads();

    // ---- phase 2: ya/yb in two nq-passes (acc 32 regs/pass) ----
    int side = warp >> 2, og1 = warp & 3;
    int r0 = lane >> 2, cb = (lane & 3) * 2;
    float* dst = side == 0 ? g_ya : g_yb;
#pragma unroll
    for (int pass = 0; pass < 2; pass++) {
        float acc[2][4][4] = {};   // [mt][nb-in-pass][frag]
#pragma unroll
        for (int ks = 0; ks < 8; ks++) {
            int ka = ks * 16;
            u32 ah[2][4], al_[2][4];
            ldmA<YSTR>(ah[0], smb + SY_A_HI, 0, ka);
            ldmA<YSTR>(ah[1], smb + SY_A_HI, 16, ka);
            ldmA<YSTR>(al_[0], smb + SY_A_LO, 0, ka);
            ldmA<YSTR>(al_[1], smb + SY_A_LO, 16, ka);
            int fbase = ((((og1 * 2 + side) * 8 + ks) * 4) * 32 + lane) * 2;
#pragma unroll
            for (int nq = 0; nq < 2; nq++) {
                uint4 fh = g_f1[fbase + (pass * 2 + nq) * 64];
                uint4 fl = g_f1[fbase + (pass * 2 + nq) * 64 + 1];
#pragma unroll
                for (int mt = 0; mt < 2; mt++) {
                    mma16816(acc[mt][nq * 2], ah[mt], fh.x, fh.y);
                    mma16816(acc[mt][nq * 2], ah[mt], fl.x, fl.y);
                    mma16816(acc[mt][nq * 2], al_[mt], fh.x, fh.y);
                    mma16816(acc[mt][nq * 2 + 1], ah[mt], fh.z, fh.w);
                    mma16816(acc[mt][nq * 2 + 1], ah[mt], fl.z, fl.w);
                    mma16816(acc[mt][nq * 2 + 1], al_[mt], fh.z, fh.w);
                }
            }
        }
        // epilogue: store (ya += b1) for this pass's 32 outs
#pragma unroll
        for (int mt = 0; mt < 2; mt++) {
            int node = n0 + mt * 16 + r0;
#pragma unroll
            for (int nb = 0; nb < 4; nb++) {
                int o = og1 * 64 + (pass * 4 + nb) * 8 + cb;
                float ba = side == 0 ? b1s[o] : 0.0f;
                float bb = side == 0 ? b1s[o + 1] : 0.0f;
                *(float2*)&dst[(size_t)node * 256 + o] =
                    make_float2(acc[mt][nb][0] + ba, acc[mt][nb][1] + bb);
                *(float2*)&dst[(size_t)(node + 8) * 256 + o] =
                    make_float2(acc[mt][nb][2] + ba, acc[mt][nb][3] + bb);
            }
        }
    }
}

// ---------------------------------------------------------------------------
// Fused edge kernel: gather ya/yb -> silu -> GEMM2 (mma bf16 hi/lo) -> att
// -> scatter (red.global.v4).  64 edges/CTA, 8 warps = 2 eg x 4 og, 3 CTAs/SM.
// ---------------------------------------------------------------------------
__global__ __launch_bounds__(256, 3) void k_edge(
    const float* __restrict__ dist, const float* __restrict__ emask,
    const float* __restrict__ w1, const float* __restrict__ b2,
    const float* __restrict__ w3, const float* __restrict__ b3,
    const void* __restrict__ edges) {
    extern __shared__ char smc[];
    u32 smb = smem_u32(smc);
    float* smf = (float*)smc;
    int* rows = (int*)(smc + SB_ROWS);
    int* cols = (int*)(smc + SB_COLS);

    int tid = threadIdx.x, lane = tid & 31, warp = tid >> 5;
    int eg = warp & 1, og = warp >> 1;   // 2 edge-groups x 4 out-groups
    int Eb = eg * 32;
    int e0 = blockIdx.x * ET;

    // stage small vectors
    smf[SB_W1C / 4 + tid] = w1[tid * 257 + 256];
    if (tid < 128) {
        smf[SB_B2 / 4 + tid] = b2[tid];
        smf[SB_W3 / 4 + tid] = w3[tid];
    }
    if (tid < 64) {
        int e = e0 + tid;
        if (g_e64) {
            const long long* e64 = (const long long*)edges;
            rows[tid] = (int)e64[e];
            cols[tid] = (int)e64[EE + e];
        } else {
            const int* ei = (const int*)edges;
            rows[tid] = ei[e];
            cols[tid] = ei[EE + e];
        }
        float em = emask[e];
        smf[SB_EMS / 4 + tid] = em;
        smf[SB_DE / 4 + tid] = dist[e] * em;
    }
    __syncthreads();

    // ---- gather ya[row]+yb[col]+de*w1c -> silu -> h1 bf16 hi/lo tile ----
    {
        float4 wc0 = *(const float4*)(smf + SB_W1C / 4 + lane * 4);
        float4 wc1 = *(const float4*)(smf + SB_W1C / 4 + lane * 4 + 128);
#pragma unroll
        for (int i = 0; i < 8; i++) {
            int el = warp * 8 + i;
            const float* ya = &g_ya[(size_t)rows[el] * 256];
            const float* yb = &g_yb[(size_t)cols[el] * 256];
            float de = smf[SB_DE / 4 + el];
#pragma unroll
            for (int j = 0; j < 2; j++) {
                int o4 = lane * 4 + j * 128;
                float4 a4 = *(const float4*)(ya + o4);
                float4 b4 = *(const float4*)(yb + o4);
                float4 wc = j == 0 ? wc0 : wc1;
                float v0 = silu_(a4.x + b4.x + de * wc.x);
                float v1 = silu_(a4.y + b4.y + de * wc.y);
                float v2 = silu_(a4.z + b4.z + de * wc.z);
                float v3 = silu_(a4.w + b4.w + de * wc.w);
                u32 hp0, lp0, hp1, lp1;
                bsplit2(v0, v1, hp0, lp0);
                bsplit2(v2, v3, hp1, lp1);
                *(u64*)(smc + SB_A_HI + el * ASTR + o4 * 2) = (u64)hp0 | ((u64)hp1 << 32);
                *(u64*)(smc + SB_A_LO + el * ASTR + o4 * 2) = (u64)lp0 | ((u64)lp1 << 32);
            }
        }
    }
    __syncthreads();

    // ---- GEMM2: D2[64e x 128o], warp slice 32e x 32o, K=256 ----
    float acc2[2][4][4] = {};
#pragma unroll
    for (int ks = 0; ks < 16; ks++) {
        int ka = ks * 16;
        u32 ah[2][4], al_[2][4];
        ldmA<ASTR>(ah[0], smb + SB_A_HI, Eb, ka);
        ldmA<ASTR>(ah[1], smb + SB_A_HI, Eb + 16, ka);
        ldmA<ASTR>(al_[0], smb + SB_A_LO, Eb, ka);
        ldmA<ASTR>(al_[1], smb + SB_A_LO, Eb + 16, ka);
        int fbase = (((og * 16 + ks) * 2) * 32 + lane) * 2;
#pragma unroll
        for (int nq = 0; nq < 2; nq++) {
            uint4 fh = g_f2[fbase + nq * 64];
            uint4 fl = g_f2[fbase + nq * 64 + 1];
#pragma unroll
            for (int mt = 0; mt < 2; mt++) {
                mma16816(acc2[mt][nq * 2], ah[mt], fh.x, fh.y);
                mma16816(acc2[mt][nq * 2], ah[mt], fl.x, fl.y);
                mma16816(acc2[mt][nq * 2], al_[mt], fh.x, fh.y);
                mma16816(acc2[mt][nq * 2 + 1], ah[mt], fh.z, fh.w);
                mma16816(acc2[mt][nq * 2 + 1], ah[mt], fl.z, fl.w);
                mma16816(acc2[mt][nq * 2 + 1], al_[mt], fh.z, fh.w);
            }
        }
    }

    // ---- epilogue2: att partials, cross-og combine ----
    {
        int r0 = lane >> 2, cb = (lane & 3) * 2;
        float p[2][2] = {};
#pragma unroll
        for (int mt = 0; mt < 2; mt++)
#pragma unroll
            for (int nb = 0; nb < 4; nb++) {
                int o = og * 32 + nb * 8 + cb;
                float b2a = smf[SB_B2 / 4 + o], b2b = smf[SB_B2 / 4 + o + 1];
                float w3a = smf[SB_W3 / 4 + o], w3b = smf[SB_W3 / 4 + o + 1];
                p[mt][0] += silu_(acc2[mt][nb][0] + b2a) * w3a + silu_(acc2[mt][nb][1] + b2b) * w3b;
                p[mt][1] += silu_(acc2[mt][nb][2] + b2a) * w3a + silu_(acc2[mt][nb][3] + b2b) * w3b;
            }
#pragma unroll
        for (int off = 1; off <= 2; off <<= 1)
#pragma unroll
            for (int mt = 0; mt < 2; mt++) {
                p[mt][0] += __shfl_xor_sync(0xffffffffu, p[mt][0], off);
                p[mt][1] += __shfl_xor_sync(0xffffffffu, p[mt][1], off);
            }
        if ((lane & 3) == 0) {
#pragma unroll
            for (int mt = 0; mt < 2; mt++) {
                int e = Eb + mt * 16 + r0;
                smf[SB_PART / 4 + og * 64 + e] = p[mt][0];
                smf[SB_PART / 4 + og * 64 + e + 8] = p[mt][1];
            }
        }
    }
    __syncthreads();
    if (tid < 64) {
        float z = smf[SB_PART / 4 + tid] + smf[SB_PART / 4 + 64 + tid] +
                  smf[SB_PART / 4 + 128 + tid] + smf[SB_PART / 4 + 192 + tid] + b3[0];
        smf[SB_ATT / 4 + tid] = sigm(z) * smf[SB_EMS / 4 + tid];
    }
    __syncthreads();

    // ---- scatter: g_out[row] += x_col * att  (vector reduction, no return) ----
#pragma unroll
    for (int i = 0; i < 8; i++) {
        int el = warp * 8 + i;
        float a = smf[SB_ATT / 4 + el];
        const float4 v = *(const float4*)&g_x[(size_t)cols[el] * DN + lane * 4];
        float* dst = &g_out[(size_t)rows[el] * DN + lane * 4];
        asm volatile("red.global.add.v4.f32 [%0], {%1, %2, %3, %4};"
                     :: "l"(dst), "f"(v.x * a), "f"(v.y * a), "f"(v.z * a), "f"(v.w * a)
                     : "memory");
    }
}

// ---------------------------------------------------------------------------
// k_node (mma): node_mlp + residual + final LN + silu.  32 nodes/CTA.
// ---------------------------------------------------------------------------
__global__ __launch_bounds__(256, 3) void k_node(
    const float* __restrict__ b1, const float* __restrict__ g1,
    const float* __restrict__ bb1, const float* __restrict__ b2,
    const float* __restrict__ g2, const float* __restrict__ bb2,
    float* __restrict__ out) {
    extern __shared__ char smc[];
    u32 smb = smem_u32(smc);
    float* mid = (float*)(smc + SN_MID);
    float* b1s = (float*)(smc + SN_B1);
    float* b2s = (float*)(smc + SN_B2);
    float* g1s = (float*)(smc + SN_G1);
    float* bb1s = (float*)(smc + SN_BB1);
    float* g2s = (float*)(smc + SN_G2);
    float* bb2s = (float*)(smc + SN_BB2);
    int tid = threadIdx.x, lane = tid & 31, warp = tid >> 5;
    int n0 = blockIdx.x * 32;

    if (tid < 128) {
        b1s[tid] = b1[tid]; b2s[tid] = b2[tid];
        g1s[tid] = g1[tid]; bb1s[tid] = bb1[tid];
        g2s[tid] = g2[tid]; bb2s[tid] = bb2[tid];
    }
    // load input (g_out / NORM_FACTOR), bsplit -> A
#pragma unroll
    for (int i = 0; i < 4; i++) {
        int el = warp * 4 + i;
        float4 v = *(const float4*)&g_out[(size_t)(n0 + el) * DN + lane * 4];
        v.x *= 0.01f; v.y *= 0.01f; v.z *= 0.01f; v.w *= 0.01f;
        u32 hp0, lp0, hp1, lp1;
        bsplit2(v.x, v.y, hp0, lp0);
        bsplit2(v.z, v.w, hp1, lp1);
        *(u64*)(smc + SN_A_HI + el * YSTR + lane * 8) = (u64)hp0 | ((u64)hp1 << 32);
        *(u64*)(smc + SN_A_LO + el * YSTR + lane * 8) = (u64)lp0 | ((u64)lp1 << 32);
    }
    __syncthreads();

    int r0 = lane >> 2, cb = (lane & 3) * 2;

    // ---- GEMM1 (nm_w1): warp -> outs [warp*16, +16) ----
    {
        float acc[2][2][4] = {};
#pragma unroll
        for (int ks = 0; ks < 8; ks++) {
            int ka = ks * 16;
            u32 ah[2][4], al_[2][4];
            ldmA<YSTR>(ah[0], smb + SN_A_HI, 0, ka);
            ldmA<YSTR>(ah[1], smb + SN_A_HI, 16, ka);
            ldmA<YSTR>(al_[0], smb + SN_A_LO, 0, ka);
            ldmA<YSTR>(al_[1], smb + SN_A_LO, 16, ka);
            int fbase = ((warp * 8 + ks) * 32 + lane) * 2;
            uint4 fh = g_fn1[fbase];
            uint4 fl = g_fn1[fbase + 1];
#pragma unroll
            for (int mt = 0; mt < 2; mt++) {
                mma16816(acc[mt][0], ah[mt], fh.x, fh.y);
                mma16816(acc[mt][0], ah[mt], fl.x, fl.y);
                mma16816(acc[mt][0], al_[mt], fh.x, fh.y);
                mma16816(acc[mt][1], ah[mt], fh.z, fh.w);
                mma16816(acc[mt][1], ah[mt], fl.z, fl.w);
                mma16816(acc[mt][1], al_[mt], fh.z, fh.w);
            }
        }
#pragma unroll
        for (int mt = 0; mt < 2; mt++)
#pragma unroll
            for (int nb = 0; nb < 2; nb++) {
                int o = warp * 16 + nb * 8 + cb;
                float ba = b1s[o], bb = b1s[o + 1];
                int nl = mt * 16 + r0;
                *(float2*)&mid[nl * 132 + o] = make_float2(acc[mt][nb][0] + ba, acc[mt][nb][1] + bb);
                *(float2*)&mid[(nl + 8) * 132 + o] = make_float2(acc[mt][nb][2] + ba, acc[mt][nb][3] + bb);
            }
    }
    __syncthreads();

    // ---- LN1 + silu -> A (bf16 hi/lo) ----
#pragma unroll
    for (int i = 0; i < 4; i++) {
        int nl = warp * 4 + i;
        float v[4], s1 = 0.f, s2 = 0.f;
#pragma unroll
        for (int j = 0; j < 4; j++) {
            v[j] = mid[nl * 132 + lane + 32 * j];
            s1 += v[j]; s2 += v[j] * v[j];
        }
#pragma unroll
        for (int off = 16; off > 0; off >>= 1) {
            s1 += __shfl_xor_sync(0xffffffffu, s1, off);
            s2 += __shfl_xor_sync(0xffffffffu, s2, off);
        }
        float mean = s1 * (1.0f / 128.0f);
        float var = s2 * (1.0f / 128.0f) - mean * mean;
        float inv = rsqrtf(var + 1e-5f);
#pragma unroll
        for (int j = 0; j < 4; j++) {
            int o = lane + 32 * j;
            float y = silu_((v[j] - mean) * inv * g1s[o] + bb1s[o]);
            u16 hh, ll;
            bsplit(y, hh, ll);
            *(u16*)(smc + SN_A_HI + nl * YSTR + o * 2) = hh;
            *(u16*)(smc + SN_A_LO + nl * YSTR + o * 2) = ll;
        }
    }
    __syncthreads();

    // ---- GEMM2 (nm_w2) ----
    {
        float acc[2][2][4] = {};
#pragma unroll
        for (int ks = 0; ks < 8; ks++) {
            int ka = ks * 16;
            u32 ah[2][4], al_[2][4];
            ldmA<YSTR>(ah[0], smb + SN_A_HI, 0, ka);
            ldmA<YSTR>(ah[1], smb + SN_A_HI, 16, ka);
            ldmA<YSTR>(al_[0], smb + SN_A_LO, 0, ka);
            ldmA<YSTR>(al_[1], smb + SN_A_LO, 16, ka);
            int fbase = ((warp * 8 + ks) * 32 + lane) * 2;
            uint4 fh = g_fn2[fbase];
            uint4 fl = g_fn2[fbase + 1];
#pragma unroll
            for (int mt = 0; mt < 2; mt++) {
                mma16816(acc[mt][0], ah[mt], fh.x, fh.y);
                mma16816(acc[mt][0], ah[mt], fl.x, fl.y);
                mma16816(acc[mt][0], al_[mt], fh.x, fh.y);
                mma16816(acc[mt][1], ah[mt], fh.z, fh.w);
                mma16816(acc[mt][1], ah[mt], fl.z, fl.w);
                mma16816(acc[mt][1], al_[mt], fh.z, fh.w);
            }
        }
#pragma unroll
        for (int mt = 0; mt < 2; mt++)
#pragma unroll
            for (int nb = 0; nb < 2; nb++) {
                int o = warp * 16 + nb * 8 + cb;
                float ba = b2s[o], bb = b2s[o + 1];
                int nl = mt * 16 + r0;
                *(float2*)&mid[nl * 132 + o] = make_float2(acc[mt][nb][0] + ba, acc[mt][nb][1] + bb);
                *(float2*)&mid[(nl + 8) * 132 + o] = make_float2(acc[mt][nb][2] + ba, acc[mt][nb][3] + bb);
            }
    }
    __syncthreads();

    // ---- + residual, LN2, silu, store ----
#pragma unroll
    for (int i = 0; i < 4; i++) {
        int nl = warp * 4 + i;
        float v[4], s1 = 0.f, s2 = 0.f;
#pragma unroll
        for (int j = 0; j < 4; j++) {
            int o = lane + 32 * j;
            v[j] = mid[nl * 132 + o] + g_x[(size_t)(n0 + nl) * DN + o];
            s1 += v[j]; s2 += v[j] * v[j];
        }
#pragma unroll
        for (int off = 16; off > 0; off >>= 1) {
            s1 += __shfl_xor_sync(0xffffffffu, s1, off);
            s2 += __shfl_xor_sync(0xffffffffu, s2, off);
        }
        float mean = s1 * (1.0f / 128.0f);
        float var = s2 * (1.0f / 128.0f) - mean * mean;
        float inv = rsqrtf(var + 1e-5f);
#pragma unroll
        for (int j = 0; j < 4; j++) {
            int o = lane + 32 * j;
            float y = (v[j] - mean) * inv * g2s[o] + bb2s[o];
            out[(size_t)(n0 + nl) * DN + o] = silu_(y);
        }
    }
}

// ---------------------------------------------------------------------------
extern "C" void kernel_launch(void* const* d_in, const int* in_sizes, int n_in,
                              void* d_out, int out_size) {
    const float* h = (const float*)d_in[0];
    const float* distances = (const float*)d_in[1];
    const float* edge_mask = (const float*)d_in[3];
    const float* lin_w = (const float*)d_in[4];
    const float* lin_b = (const float*)d_in[5];
    const float* att_w1 = (const float*)d_in[6];
    const float* att_b1 = (const float*)d_in[7];
    const float* att_w2 = (const float*)d_in[8];
    const float* att_b2 = (const float*)d_in[9];
    const float* att_w3 = (const float*)d_in[10];
    const float* att_b3 = (const float*)d_in[11];
    const float* nm_w1 = (const float*)d_in[12];
    const float* nm_b1 = (const float*)d_in[13];
    const float* nm_ln_g = (const float*)d_in[14];
    const float* nm_ln_b = (const float*)d_in[15];
    const float* nm_w2 = (const float*)d_in[16];
    const float* nm_b2 = (const float*)d_in[17];
    const float* ln_g = (const float*)d_in[18];
    const float* ln_b = (const float*)d_in[19];
    const void* edges = d_in[20];

    cudaFuncSetAttribute(k_xy, cudaFuncAttributeMaxDynamicSharedMemorySize, SMEM_Y);
    cudaFuncSetAttribute(k_edge, cudaFuncAttributeMaxDynamicSharedMemorySize, SMEM_EDGE);
    cudaFuncSetAttribute(k_node, cudaFuncAttributeMaxDynamicSharedMemorySize, SMEM_N);

    k_prep<<<72, 256>>>(att_w1, att_w2, lin_w, nm_w1, nm_w2, edges);
    k_zero4<<<(NN * DN / 4 + 255) / 256, 256>>>();
    k_xy<<<625, 256, SMEM_Y>>>(h, lin_b, att_b1);
    k_edge<<<NCTA, 256, SMEM_EDGE>>>(distances, edge_mask, att_w1, att_b2,
                                     att_w3, att_b3, edges);
    k_node<<<625, 256, SMEM_N>>>(nm_b1, nm_ln_g, nm_ln_b,
                                 nm_b2, ln_g, ln_b, (float*)d_out);
}

// round 12
// speedup vs baseline: 13.5278x; 1.5461x over previous
#include <cuda_runtime.h>
#include <cuda_bf16.h>

typedef unsigned int u32;
typedef unsigned long long u64;
typedef unsigned short u16;

#define DN 128
#define NN 20000
#define EE 640000
#define ET 64                   // edges per CTA
#define NCTA (EE / ET)          // 10000
#define ASTR 528                // h1 row stride bytes (256 halves + pad)
#define YSTR 272                // x row stride bytes (136 halves)

// ---------------- device globals (no runtime alloc) ----------------
__device__ float g_x[NN * DN];
__device__ float g_out[NN * DN];
__device__ float g_ya[NN * 256];   // x@W1a^T + b1
__device__ float g_yb[NN * 256];   // x@W1b^T
__device__ int g_e64;
// pre-packed B fragments in per-lane mma order
__device__ uint4 g_f1[16384];   // W1 bf16 hi/lo: [og4][side2][ks8][nq4][lane32][hi/lo]
__device__ uint4 g_fh2[4096];   // W2 fp16 single: [og4][ks16][nq2][lane32]
__device__ uint4 g_fl[4096];    // lin_w bf16 hi/lo: [og8][ks8][lane32][hi/lo]
__device__ uint4 g_fn1[4096];   // nm_w1 bf16 hi/lo
__device__ uint4 g_fn2[4096];   // nm_w2 bf16 hi/lo

// ---------------- k_edge smem layout (bytes) ----------------
#define SB_ROWS 0
#define SB_COLS 256
#define SB_DE   512
#define SB_EMS  768
#define SB_ATT  1024
#define SB_PART 1280
#define SB_B2   2304
#define SB_W3   2816
#define SB_W1C  3328
#define SB_A    4352            // 64 x 528 = 33792 (fp16 h1 tile)
#define SMEM_EDGE 38144

// ---------------- k_xy smem layout ----------------
#define SY_A_HI 0               // 32 x 272 = 8704
#define SY_A_LO 8704
#define SY_B1   17408           // 256 f
#define SY_LB   18432           // 128 f
#define SMEM_Y  18944

// ---------------- k_node smem layout ----------------
#define SN_A_HI 0               // 32 x 272 = 8704
#define SN_A_LO 8704
#define SN_MID  17408           // 32 x 132 f = 16896
#define SN_B1   34304           // 128 f
#define SN_B2   34816
#define SN_G1   35328
#define SN_BB1  35840
#define SN_G2   36352
#define SN_BB2  36864
#define SMEM_N  37376

__device__ __forceinline__ u32 smem_u32(const void* p) {
    u32 a;
    asm("{ .reg .u64 t; cvta.to.shared.u64 t, %1; cvt.u32.u64 %0, t; }" : "=r"(a) : "l"(p));
    return a;
}
__device__ __forceinline__ float sigm(float v) {
    return __fdividef(1.0f, 1.0f + __expf(-v));
}
__device__ __forceinline__ float silu_(float v) { return v * sigm(v); }

__device__ __forceinline__ void bsplit(float v, u16& h, u16& l) {
    __nv_bfloat16 hb = __float2bfloat16(v);
    __nv_bfloat16 lb = __float2bfloat16(v - __bfloat162float(hb));
    h = __bfloat16_as_ushort(hb);
    l = __bfloat16_as_ushort(lb);
}
// pack-pair bf16 split
__device__ __forceinline__ void bsplit2(float v0, float v1, u32& hp, u32& lp) {
    asm("cvt.rn.bf16x2.f32 %0, %1, %2;" : "=r"(hp) : "f"(v1), "f"(v0));
    float h0 = __uint_as_float(hp << 16);
    float h1 = __uint_as_float(hp & 0xffff0000u);
    asm("cvt.rn.bf16x2.f32 %0, %1, %2;" : "=r"(lp) : "f"(v1 - h1), "f"(v0 - h0));
}
// fp16 pair pack (v0 in low half)
__device__ __forceinline__ u32 hpack2(float v0, float v1) {
    u32 r;
    asm("cvt.rn.f16x2.f32 %0, %1, %2;" : "=r"(r) : "f"(v1), "f"(v0));
    return r;
}

// ldmatrix m16k16 (A, row-major, stride S bytes)
template <int S>
__device__ __forceinline__ void ldmA(u32 r[4], u32 base, int row0, int kh) {
    int lane = threadIdx.x & 31;
    int quad = lane >> 3;
    u32 addr = base + (u32)(row0 + (lane & 7) + (quad & 1) * 8) * S +
               (u32)kh * 2 + (u32)(quad >> 1) * 16;
    asm volatile("ldmatrix.sync.aligned.m8n8.x4.shared.b16 {%0,%1,%2,%3}, [%4];"
                 : "=r"(r[0]), "=r"(r[1]), "=r"(r[2]), "=r"(r[3]) : "r"(addr));
}
__device__ __forceinline__ void mma16816(float d[4], const u32 a[4], u32 b0, u32 b1) {
    asm volatile("mma.sync.aligned.m16n8k16.row.col.f32.bf16.bf16.f32 "
                 "{%0,%1,%2,%3}, {%4,%5,%6,%7}, {%8,%9}, {%0,%1,%2,%3};"
                 : "+f"(d[0]), "+f"(d[1]), "+f"(d[2]), "+f"(d[3])
                 : "r"(a[0]), "r"(a[1]), "r"(a[2]), "r"(a[3]), "r"(b0), "r"(b1));
}
__device__ __forceinline__ void mmaf16(float d[4], const u32 a[4], u32 b0, u32 b1) {
    asm volatile("mma.sync.aligned.m16n8k16.row.col.f32.f16.f16.f32 "
                 "{%0,%1,%2,%3}, {%4,%5,%6,%7}, {%8,%9}, {%0,%1,%2,%3};"
                 : "+f"(d[0]), "+f"(d[1]), "+f"(d[2]), "+f"(d[3])
                 : "r"(a[0]), "r"(a[1]), "r"(a[2]), "r"(a[3]), "r"(b0), "r"(b1));
}

// pack a 128x128 K-major fp32 weight into bf16 hi/lo frag pairs
__device__ __forceinline__ void pack128(const float* __restrict__ w, uint4* tab, int j) {
    int lane = j & 31, ks = (j >> 5) & 7, og = (j >> 8) & 7;
    int nb0 = og * 16 + (lane >> 2);
    int kb = ks * 16 + (lane & 3) * 2;
    u32 wh[4], wl[4];
#pragma unroll
    for (int nb = 0; nb < 2; nb++)
#pragma unroll
        for (int r = 0; r < 2; r++) {
            const float* p = &w[(nb0 + nb * 8) * 128 + kb + r * 8];
            u16 h0, l0, h1, l1;
            bsplit(p[0], h0, l0);
            bsplit(p[1], h1, l1);
            wh[nb * 2 + r] = (u32)h0 | ((u32)h1 << 16);
            wl[nb * 2 + r] = (u32)l0 | ((u32)l1 << 16);
        }
    tab[j * 2] = make_uint4(wh[0], wh[1], wh[2], wh[3]);
    tab[j * 2 + 1] = make_uint4(wl[0], wl[1], wl[2], wl[3]);
}

// ---------------------------------------------------------------------------
// k_prep: pack weight fragment tables. 18432 items -> grid 72 x 256.
// ---------------------------------------------------------------------------
__global__ void k_prep(const float* __restrict__ w1, const float* __restrict__ w2,
                       const float* __restrict__ lw, const float* __restrict__ nw1,
                       const float* __restrict__ nw2, const void* __restrict__ edges) {
    int idx = blockIdx.x * 256 + threadIdx.x;
    if (idx < 8192) {       // W1 bf16 hi/lo frags [256 out][257 k]
        int lane = idx & 31, nq = (idx >> 5) & 3, ks = (idx >> 7) & 7;
        int side = (idx >> 10) & 1, og = (idx >> 11) & 3;
        int nb0 = og * 64 + nq * 16 + (lane >> 2);
        int kb = side * 128 + ks * 16 + (lane & 3) * 2;
        u32 wh[4], wl[4];
#pragma unroll
        for (int nb = 0; nb < 2; nb++)
#pragma unroll
            for (int r = 0; r < 2; r++) {
                const float* p = &w1[(nb0 + nb * 8) * 257 + kb + r * 8];
                u16 h0, l0, h1, l1;
                bsplit(p[0], h0, l0);
                bsplit(p[1], h1, l1);
                wh[nb * 2 + r] = (u32)h0 | ((u32)h1 << 16);
                wl[nb * 2 + r] = (u32)l0 | ((u32)l1 << 16);
            }
        g_f1[idx * 2] = make_uint4(wh[0], wh[1], wh[2], wh[3]);
        g_f1[idx * 2 + 1] = make_uint4(wl[0], wl[1], wl[2], wl[3]);
    } else if (idx < 12288) {  // W2 fp16 single frags [128 out][256 k]
        int j = idx - 8192;
        int lane = j & 31, nq = (j >> 5) & 1, ks = (j >> 6) & 15, og = (j >> 10) & 3;
        int nb0 = og * 32 + nq * 16 + (lane >> 2);
        int kb = ks * 16 + (lane & 3) * 2;
        u32 wf[4];
#pragma unroll
        for (int nb = 0; nb < 2; nb++)
#pragma unroll
            for (int r = 0; r < 2; r++) {
                const float* p = &w2[(nb0 + nb * 8) * 256 + kb + r * 8];
                wf[nb * 2 + r] = hpack2(p[0], p[1]);
            }
        g_fh2[j] = make_uint4(wf[0], wf[1], wf[2], wf[3]);
    } else if (idx < 14336) {  // lin_w frags
        pack128(lw, g_fl, idx - 12288);
    } else if (idx < 16384) {  // nm_w1 frags
        pack128(nw1, g_fn1, idx - 14336);
    } else {                   // nm_w2 frags
        pack128(nw2, g_fn2, idx - 16384);
    }
    if (idx == 0) {
        const int* e32 = (const int*)edges;
        int nz = 0;
        for (int i = 0; i < 16; i++) nz |= e32[2 * i + 1];
        g_e64 = (nz == 0) ? 1 : 0;
    }
}

__global__ void k_zero4() {
    int i = blockIdx.x * 256 + threadIdx.x;
    if (i < NN * DN / 4)
        *(float4*)&g_out[i * 4] = make_float4(0.f, 0.f, 0.f, 0.f);
}

// ---------------------------------------------------------------------------
// k_xy: fused  x = h@lin_w^T + lin_b ;  ya = x@W1a^T + b1 ;  yb = x@W1b^T.
// 32 nodes/CTA, 2 CTAs/SM. (bf16 hi/lo split — accuracy anchor)
// ---------------------------------------------------------------------------
__global__ __launch_bounds__(256, 2) void k_xy(const float* __restrict__ h,
                                               const float* __restrict__ lb,
                                               const float* __restrict__ b1) {
    extern __shared__ char smc[];
    u32 smb = smem_u32(smc);
    float* b1s = (float*)(smc + SY_B1);
    float* lbs = (float*)(smc + SY_LB);
    int tid = threadIdx.x, lane = tid & 31, warp = tid >> 5;
    int n0 = blockIdx.x * 32;

    b1s[tid] = b1[tid];
    if (tid < 128) lbs[tid] = lb[tid];
#pragma unroll
    for (int i = 0; i < 4; i++) {
        int el = warp * 4 + i;
        const float4 v = *(const float4*)&h[(size_t)(n0 + el) * DN + lane * 4];
        u32 hp0, lp0, hp1, lp1;
        bsplit2(v.x, v.y, hp0, lp0);
        bsplit2(v.z, v.w, hp1, lp1);
        *(u64*)(smc + SY_A_HI + el * YSTR + lane * 8) = (u64)hp0 | ((u64)hp1 << 32);
        *(u64*)(smc + SY_A_LO + el * YSTR + lane * 8) = (u64)lp0 | ((u64)lp1 << 32);
    }
    __syncthreads();

    // ---- phase 1: x = h@lin_w^T + lin_b ----
    {
        float accl[2][2][4] = {};
#pragma unroll
        for (int ks = 0; ks < 8; ks++) {
            int ka = ks * 16;
            u32 ah[2][4], al_[2][4];
            ldmA<YSTR>(ah[0], smb + SY_A_HI, 0, ka);
            ldmA<YSTR>(ah[1], smb + SY_A_HI, 16, ka);
            ldmA<YSTR>(al_[0], smb + SY_A_LO, 0, ka);
            ldmA<YSTR>(al_[1], smb + SY_A_LO, 16, ka);
            int fbase = ((warp * 8 + ks) * 32 + lane) * 2;
            uint4 fh = g_fl[fbase];
            uint4 fl = g_fl[fbase + 1];
#pragma unroll
            for (int mt = 0; mt < 2; mt++) {
                mma16816(accl[mt][0], ah[mt], fh.x, fh.y);
                mma16816(accl[mt][0], ah[mt], fl.x, fl.y);
                mma16816(accl[mt][0], al_[mt], fh.x, fh.y);
                mma16816(accl[mt][1], ah[mt], fh.z, fh.w);
                mma16816(accl[mt][1], ah[mt], fl.z, fl.w);
                mma16816(accl[mt][1], al_[mt], fh.z, fh.w);
            }
        }
        __syncthreads();
        int r0 = lane >> 2, cb = (lane & 3) * 2;
#pragma unroll
        for (int mt = 0; mt < 2; mt++) {
#pragma unroll
            for (int nb = 0; nb < 2; nb++) {
                int o = warp * 16 + nb * 8 + cb;
                float ba = lbs[o], bb = lbs[o + 1];
                float v0 = accl[mt][nb][0] + ba, v1 = accl[mt][nb][1] + bb;
                float v2 = accl[mt][nb][2] + ba, v3 = accl[mt][nb][3] + bb;
                int nl = mt * 16 + r0;
                *(float2*)&g_x[(size_t)(n0 + nl) * DN + o] = make_float2(v0, v1);
                *(float2*)&g_x[(size_t)(n0 + nl + 8) * DN + o] = make_float2(v2, v3);
                u32 hp, lp;
                bsplit2(v0, v1, hp, lp);
                *(u32*)(smc + SY_A_HI + nl * YSTR + o * 2) = hp;
                *(u32*)(smc + SY_A_LO + nl * YSTR + o * 2) = lp;
                bsplit2(v2, v3, hp, lp);
                *(u32*)(smc + SY_A_HI + (nl + 8) * YSTR + o * 2) = hp;
                *(u32*)(smc + SY_A_LO + (nl + 8) * YSTR + o * 2) = lp;
            }
        }
    }
    __syncthreads();

    // ---- phase 2: ya/yb in two nq-passes ----
    int side = warp >> 2, og1 = warp & 3;
    int r0 = lane >> 2, cb = (lane & 3) * 2;
    float* dst = side == 0 ? g_ya : g_yb;
#pragma unroll
    for (int pass = 0; pass < 2; pass++) {
        float acc[2][4][4] = {};
#pragma unroll
        for (int ks = 0; ks < 8; ks++) {
            int ka = ks * 16;
            u32 ah[2][4], al_[2][4];
            ldmA<YSTR>(ah[0], smb + SY_A_HI, 0, ka);
            ldmA<YSTR>(ah[1], smb + SY_A_HI, 16, ka);
            ldmA<YSTR>(al_[0], smb + SY_A_LO, 0, ka);
            ldmA<YSTR>(al_[1], smb + SY_A_LO, 16, ka);
            int fbase = ((((og1 * 2 + side) * 8 + ks) * 4) * 32 + lane) * 2;
#pragma unroll
            for (int nq = 0; nq < 2; nq++) {
                uint4 fh = g_f1[fbase + (pass * 2 + nq) * 64];
                uint4 fl = g_f1[fbase + (pass * 2 + nq) * 64 + 1];
#pragma unroll
                for (int mt = 0; mt < 2; mt++) {
                    mma16816(acc[mt][nq * 2], ah[mt], fh.x, fh.y);
                    mma16816(acc[mt][nq * 2], ah[mt], fl.x, fl.y);
                    mma16816(acc[mt][nq * 2], al_[mt], fh.x, fh.y);
                    mma16816(acc[mt][nq * 2 + 1], ah[mt], fh.z, fh.w);
                    mma16816(acc[mt][nq * 2 + 1], ah[mt], fl.z, fl.w);
                    mma16816(acc[mt][nq * 2 + 1], al_[mt], fh.z, fh.w);
                }
            }
        }
#pragma unroll
        for (int mt = 0; mt < 2; mt++) {
            int node = n0 + mt * 16 + r0;
#pragma unroll
            for (int nb = 0; nb < 4; nb++) {
                int o = og1 * 64 + (pass * 4 + nb) * 8 + cb;
                float ba = side == 0 ? b1s[o] : 0.0f;
                float bb = side == 0 ? b1s[o + 1] : 0.0f;
                *(float2*)&dst[(size_t)node * 256 + o] =
                    make_float2(acc[mt][nb][0] + ba, acc[mt][nb][1] + bb);
                *(float2*)&dst[(size_t)(node + 8) * 256 + o] =
                    make_float2(acc[mt][nb][2] + ba, acc[mt][nb][3] + bb);
            }
        }
    }
}

// ---------------------------------------------------------------------------
// Fused edge kernel: gather ya/yb -> silu -> GEMM2 (single fp16 mma) -> att
// -> scatter (red.global.v4).  64 edges/CTA, 8 warps = 2 eg x 4 og, 4 CTAs/SM.
// ---------------------------------------------------------------------------
__global__ __launch_bounds__(256, 4) void k_edge(
    const float* __restrict__ dist, const float* __restrict__ emask,
    const float* __restrict__ w1, const float* __restrict__ b2,
    const float* __restrict__ w3, const float* __restrict__ b3,
    const void* __restrict__ edges) {
    extern __shared__ char smc[];
    u32 smb = smem_u32(smc);
    float* smf = (float*)smc;
    int* rows = (int*)(smc + SB_ROWS);
    int* cols = (int*)(smc + SB_COLS);

    int tid = threadIdx.x, lane = tid & 31, warp = tid >> 5;
    int eg = warp & 1, og = warp >> 1;   // 2 edge-groups x 4 out-groups
    int Eb = eg * 32;
    int e0 = blockIdx.x * ET;

    smf[SB_W1C / 4 + tid] = w1[tid * 257 + 256];
    if (tid < 128) {
        smf[SB_B2 / 4 + tid] = b2[tid];
        smf[SB_W3 / 4 + tid] = w3[tid];
    }
    if (tid < 64) {
        int e = e0 + tid;
        if (g_e64) {
            const long long* e64 = (const long long*)edges;
            rows[tid] = (int)e64[e];
            cols[tid] = (int)e64[EE + e];
        } else {
            const int* ei = (const int*)edges;
            rows[tid] = ei[e];
            cols[tid] = ei[EE + e];
        }
        float em = emask[e];
        smf[SB_EMS / 4 + tid] = em;
        smf[SB_DE / 4 + tid] = dist[e] * em;
    }
    __syncthreads();

    // ---- gather ya[row]+yb[col]+de*w1c -> silu -> h1 fp16 tile ----
    {
        float4 wc0 = *(const float4*)(smf + SB_W1C / 4 + lane * 4);
        float4 wc1 = *(const float4*)(smf + SB_W1C / 4 + lane * 4 + 128);
#pragma unroll
        for (int i = 0; i < 8; i++) {
            int el = warp * 8 + i;
            const float* ya = &g_ya[(size_t)rows[el] * 256];
            const float* yb = &g_yb[(size_t)cols[el] * 256];
            float de = smf[SB_DE / 4 + el];
#pragma unroll
            for (int j = 0; j < 2; j++) {
                int o4 = lane * 4 + j * 128;
                float4 a4 = *(const float4*)(ya + o4);
                float4 b4 = *(const float4*)(yb + o4);
                float4 wc = j == 0 ? wc0 : wc1;
                float v0 = silu_(a4.x + b4.x + de * wc.x);
                float v1 = silu_(a4.y + b4.y + de * wc.y);
                float v2 = silu_(a4.z + b4.z + de * wc.z);
                float v3 = silu_(a4.w + b4.w + de * wc.w);
                u32 p01 = hpack2(v0, v1);
                u32 p23 = hpack2(v2, v3);
                *(u64*)(smc + SB_A + el * ASTR + o4 * 2) = (u64)p01 | ((u64)p23 << 32);
            }
        }
    }
    __syncthreads();

    // ---- GEMM2 (fp16): D2[64e x 128o], warp slice 32e x 32o, K=256 ----
    float acc2[2][4][4] = {};
#pragma unroll
    for (int ks = 0; ks < 16; ks++) {
        int ka = ks * 16;
        u32 ah[2][4];
        ldmA<ASTR>(ah[0], smb + SB_A, Eb, ka);
        ldmA<ASTR>(ah[1], smb + SB_A, Eb + 16, ka);
        int fbase = ((og * 16 + ks) * 2) * 32 + lane;
#pragma unroll
        for (int nq = 0; nq < 2; nq++) {
            uint4 f = g_fh2[fbase + nq * 32];
#pragma unroll
            for (int mt = 0; mt < 2; mt++) {
                mmaf16(acc2[mt][nq * 2], ah[mt], f.x, f.y);
                mmaf16(acc2[mt][nq * 2 + 1], ah[mt], f.z, f.w);
            }
        }
    }

    // ---- epilogue2: att partials, cross-og combine ----
    {
        int r0 = lane >> 2, cb = (lane & 3) * 2;
        float p[2][2] = {};
#pragma unroll
        for (int mt = 0; mt < 2; mt++)
#pragma unroll
            for (int nb = 0; nb < 4; nb++) {
                int o = og * 32 + nb * 8 + cb;
                float b2a = smf[SB_B2 / 4 + o], b2b = smf[SB_B2 / 4 + o + 1];
                float w3a = smf[SB_W3 / 4 + o], w3b = smf[SB_W3 / 4 + o + 1];
                p[mt][0] += silu_(acc2[mt][nb][0] + b2a) * w3a + silu_(acc2[mt][nb][1] + b2b) * w3b;
                p[mt][1] += silu_(acc2[mt][nb][2] + b2a) * w3a + silu_(acc2[mt][nb][3] + b2b) * w3b;
            }
#pragma unroll
        for (int off = 1; off <= 2; off <<= 1)
#pragma unroll
            for (int mt = 0; mt < 2; mt++) {
                p[mt][0] += __shfl_xor_sync(0xffffffffu, p[mt][0], off);
                p[mt][1] += __shfl_xor_sync(0xffffffffu, p[mt][1], off);
            }
        if ((lane & 3) == 0) {
#pragma unroll
            for (int mt = 0; mt < 2; mt++) {
                int e = Eb + mt * 16 + r0;
                smf[SB_PART / 4 + og * 64 + e] = p[mt][0];
                smf[SB_PART / 4 + og * 64 + e + 8] = p[mt][1];
            }
        }
    }
    __syncthreads();
    if (tid < 64) {
        float z = smf[SB_PART / 4 + tid] + smf[SB_PART / 4 + 64 + tid] +
                  smf[SB_PART / 4 + 128 + tid] + smf[SB_PART / 4 + 192 + tid] + b3[0];
        smf[SB_ATT / 4 + tid] = sigm(z) * smf[SB_EMS / 4 + tid];
    }
    __syncthreads();

    // ---- scatter: g_out[row] += x_col * att ----
#pragma unroll
    for (int i = 0; i < 8; i++) {
        int el = warp * 8 + i;
        float a = smf[SB_ATT / 4 + el];
        const float4 v = *(const float4*)&g_x[(size_t)cols[el] * DN + lane * 4];
        float* dst = &g_out[(size_t)rows[el] * DN + lane * 4];
        asm volatile("red.global.add.v4.f32 [%0], {%1, %2, %3, %4};"
                     :: "l"(dst), "f"(v.x * a), "f"(v.y * a), "f"(v.z * a), "f"(v.w * a)
                     : "memory");
    }
}

// ---------------------------------------------------------------------------
// k_node (mma): node_mlp + residual + final LN + silu.  32 nodes/CTA.
// ---------------------------------------------------------------------------
__global__ __launch_bounds__(256, 3) void k_node(
    const float* __restrict__ b1, const float* __restrict__ g1,
    const float* __restrict__ bb1, const float* __restrict__ b2,
    const float* __restrict__ g2, const float* __restrict__ bb2,
    float* __restrict__ out) {
    extern __shared__ char smc[];
    u32 smb = smem_u32(smc);
    float* mid = (float*)(smc + SN_MID);
    float* b1s = (float*)(smc + SN_B1);
    float* b2s = (float*)(smc + SN_B2);
    float* g1s = (float*)(smc + SN_G1);
    float* bb1s = (float*)(smc + SN_BB1);
    float* g2s = (float*)(smc + SN_G2);
    float* bb2s = (float*)(smc + SN_BB2);
    int tid = threadIdx.x, lane = tid & 31, warp = tid >> 5;
    int n0 = blockIdx.x * 32;

    if (tid < 128) {
        b1s[tid] = b1[tid]; b2s[tid] = b2[tid];
        g1s[tid] = g1[tid]; bb1s[tid] = bb1[tid];
        g2s[tid] = g2[tid]; bb2s[tid] = bb2[tid];
    }
#pragma unroll
    for (int i = 0; i < 4; i++) {
        int el = warp * 4 + i;
        float4 v = *(const float4*)&g_out[(size_t)(n0 + el) * DN + lane * 4];
        v.x *= 0.01f; v.y *= 0.01f; v.z *= 0.01f; v.w *= 0.01f;
        u32 hp0, lp0, hp1, lp1;
        bsplit2(v.x, v.y, hp0, lp0);
        bsplit2(v.z, v.w, hp1, lp1);
        *(u64*)(smc + SN_A_HI + el * YSTR + lane * 8) = (u64)hp0 | ((u64)hp1 << 32);
        *(u64*)(smc + SN_A_LO + el * YSTR + lane * 8) = (u64)lp0 | ((u64)lp1 << 32);
    }
    __syncthreads();

    int r0 = lane >> 2, cb = (lane & 3) * 2;

    // ---- GEMM1 (nm_w1) ----
    {
        float acc[2][2][4] = {};
#pragma unroll
        for (int ks = 0; ks < 8; ks++) {
            int ka = ks * 16;
            u32 ah[2][4], al_[2][4];
            ldmA<YSTR>(ah[0], smb + SN_A_HI, 0, ka);
            ldmA<YSTR>(ah[1], smb + SN_A_HI, 16, ka);
            ldmA<YSTR>(al_[0], smb + SN_A_LO, 0, ka);
            ldmA<YSTR>(al_[1], smb + SN_A_LO, 16, ka);
            int fbase = ((warp * 8 + ks) * 32 + lane) * 2;
            uint4 fh = g_fn1[fbase];
            uint4 fl = g_fn1[fbase + 1];
#pragma unroll
            for (int mt = 0; mt < 2; mt++) {
                mma16816(acc[mt][0], ah[mt], fh.x, fh.y);
                mma16816(acc[mt][0], ah[mt], fl.x, fl.y);
                mma16816(acc[mt][0], al_[mt], fh.x, fh.y);
                mma16816(acc[mt][1], ah[mt], fh.z, fh.w);
                mma16816(acc[mt][1], ah[mt], fl.z, fl.w);
                mma16816(acc[mt][1], al_[mt], fh.z, fh.w);
            }
        }
#pragma unroll
        for (int mt = 0; mt < 2; mt++)
#pragma unroll
            for (int nb = 0; nb < 2; nb++) {
                int o = warp * 16 + nb * 8 + cb;
                float ba = b1s[o], bb = b1s[o + 1];
                int nl = mt * 16 + r0;
                *(float2*)&mid[nl * 132 + o] = make_float2(acc[mt][nb][0] + ba, acc[mt][nb][1] + bb);
                *(float2*)&mid[(nl + 8) * 132 + o] = make_float2(acc[mt][nb][2] + ba, acc[mt][nb][3] + bb);
            }
    }
    __syncthreads();

    // ---- LN1 + silu -> A ----
#pragma unroll
    for (int i = 0; i < 4; i++) {
        int nl = warp * 4 + i;
        float v[4], s1 = 0.f, s2 = 0.f;
#pragma unroll
        for (int j = 0; j < 4; j++) {
            v[j] = mid[nl * 132 + lane + 32 * j];
            s1 += v[j]; s2 += v[j] * v[j];
        }
#pragma unroll
        for (int off = 16; off > 0; off >>= 1) {
            s1 += __shfl_xor_sync(0xffffffffu, s1, off);
            s2 += __shfl_xor_sync(0xffffffffu, s2, off);
        }
        float mean = s1 * (1.0f / 128.0f);
        float var = s2 * (1.0f / 128.0f) - mean * mean;
        float inv = rsqrtf(var + 1e-5f);
#pragma unroll
        for (int j = 0; j < 4; j++) {
            int o = lane + 32 * j;
            float y = silu_((v[j] - mean) * inv * g1s[o] + bb1s[o]);
            u16 hh, ll;
            bsplit(y, hh, ll);
            *(u16*)(smc + SN_A_HI + nl * YSTR + o * 2) = hh;
            *(u16*)(smc + SN_A_LO + nl * YSTR + o * 2) = ll;
        }
    }
    __syncthreads();

    // ---- GEMM2 (nm_w2) ----
    {
        float acc[2][2][4] = {};
#pragma unroll
        for (int ks = 0; ks < 8; ks++) {
            int ka = ks * 16;
            u32 ah[2][4], al_[2][4];
            ldmA<YSTR>(ah[0], smb + SN_A_HI, 0, ka);
            ldmA<YSTR>(ah[1], smb + SN_A_HI, 16, ka);
            ldmA<YSTR>(al_[0], smb + SN_A_LO, 0, ka);
            ldmA<YSTR>(al_[1], smb + SN_A_LO, 16, ka);
            int fbase = ((warp * 8 + ks) * 32 + lane) * 2;
            uint4 fh = g_fn2[fbase];
            uint4 fl = g_fn2[fbase + 1];
#pragma unroll
            for (int mt = 0; mt < 2; mt++) {
                mma16816(acc[mt][0], ah[mt], fh.x, fh.y);
                mma16816(acc[mt][0], ah[mt], fl.x, fl.y);
                mma16816(acc[mt][0], al_[mt], fh.x, fh.y);
                mma16816(acc[mt][1], ah[mt], fh.z, fh.w);
                mma16816(acc[mt][1], ah[mt], fl.z, fl.w);
                mma16816(acc[mt][1], al_[mt], fh.z, fh.w);
            }
        }
#pragma unroll
        for (int mt = 0; mt < 2; mt++)
#pragma unroll
            for (int nb = 0; nb < 2; nb++) {
                int o = warp * 16 + nb * 8 + cb;
                float ba = b2s[o], bb = b2s[o + 1];
                int nl = mt * 16 + r0;
                *(float2*)&mid[nl * 132 + o] = make_float2(acc[mt][nb][0] + ba, acc[mt][nb][1] + bb);
                *(float2*)&mid[(nl + 8) * 132 + o] = make_float2(acc[mt][nb][2] + ba, acc[mt][nb][3] + bb);
            }
    }
    __syncthreads();

    // ---- + residual, LN2, silu, store ----
#pragma unroll
    for (int i = 0; i < 4; i++) {
        int nl = warp * 4 + i;
        float v[4], s1 = 0.f, s2 = 0.f;
#pragma unroll
        for (int j = 0; j < 4; j++) {
            int o = lane + 32 * j;
            v[j] = mid[nl * 132 + o] + g_x[(size_t)(n0 + nl) * DN + o];
            s1 += v[j]; s2 += v[j] * v[j];
        }
#pragma unroll
        for (int off = 16; off > 0; off >>= 1) {
            s1 += __shfl_xor_sync(0xffffffffu, s1, off);
            s2 += __shfl_xor_sync(0xffffffffu, s2, off);
        }
        float mean = s1 * (1.0f / 128.0f);
        float var = s2 * (1.0f / 128.0f) - mean * mean;
        float inv = rsqrtf(var + 1e-5f);
#pragma unroll
        for (int j = 0; j < 4; j++) {
            int o = lane + 32 * j;
            float y = (v[j] - mean) * inv * g2s[o] + bb2s[o];
            out[(size_t)(n0 + nl) * DN + o] = silu_(y);
        }
    }
}

// ---------------------------------------------------------------------------
extern "C" void kernel_launch(void* const* d_in, const int* in_sizes, int n_in,
                              void* d_out, int out_size) {
    const float* h = (const float*)d_in[0];
    const float* distances = (const float*)d_in[1];
    const float* edge_mask = (const float*)d_in[3];
    const float* lin_w = (const float*)d_in[4];
    const float* lin_b = (const float*)d_in[5];
    const float* att_w1 = (const float*)d_in[6];
    const float* att_b1 = (const float*)d_in[7];
    const float* att_w2 = (const float*)d_in[8];
    const float* att_b2 = (const float*)d_in[9];
    const float* att_w3 = (const float*)d_in[10];
    const float* att_b3 = (const float*)d_in[11];
    const float* nm_w1 = (const float*)d_in[12];
    const float* nm_b1 = (const float*)d_in[13];
    const float* nm_ln_g = (const float*)d_in[14];
    const float* nm_ln_b = (const float*)d_in[15];
    const float* nm_w2 = (const float*)d_in[16];
    const float* nm_b2 = (const float*)d_in[17];
    const float* ln_g = (const float*)d_in[18];
    const float* ln_b = (const float*)d_in[19];
    const void* edges = d_in[20];

    cudaFuncSetAttribute(k_xy, cudaFuncAttributeMaxDynamicSharedMemorySize, SMEM_Y);
    cudaFuncSetAttribute(k_edge, cudaFuncAttributeMaxDynamicSharedMemorySize, SMEM_EDGE);
    cudaFuncSetAttribute(k_node, cudaFuncAttributeMaxDynamicSharedMemorySize, SMEM_N);

    k_prep<<<72, 256>>>(att_w1, att_w2, lin_w, nm_w1, nm_w2, edges);
    k_zero4<<<(NN * DN / 4 + 255) / 256, 256>>>();
    k_xy<<<625, 256, SMEM_Y>>>(h, lin_b, att_b1);
    k_edge<<<NCTA, 256, SMEM_EDGE>>>(distances, edge_mask, att_w1, att_b2,
                                     att_w3, att_b3, edges);
    k_node<<<625, 256, SMEM_N>>>(nm_b1, nm_ln_g, nm_ln_b,
                                 nm_b2, ln_g, ln_b, (float*)d_out);
}

// round 13
// speedup vs baseline: 15.1758x; 1.1218x over previous
#include <cuda_runtime.h>
#include <cuda_bf16.h>
#include <cuda_fp16.h>

typedef unsigned int u32;
typedef unsigned long long u64;
typedef unsigned short u16;

#define DN 128
#define NN 20000
#define EE 640000
#define ET 64                   // edges per CTA
#define NCTA (EE / ET)          // 10000
#define ASTR 528                // h1 row stride bytes (256 halves + pad)
#define YSTR 272                // x row stride bytes (136 halves)

// ---------------- device globals (no runtime alloc) ----------------
__device__ float g_x[NN * DN];
__device__ float g_out[NN * DN];
__device__ u32 g_yah[NN * 128];    // (x@W1a^T + b1) as fp16 pairs
__device__ u32 g_ybh[NN * 128];    // (x@W1b^T) as fp16 pairs
__device__ int g_e64;
// pre-packed B fragments in per-lane mma order
__device__ uint4 g_f1[16384];   // W1 bf16 hi/lo: [og4][side2][ks8][nq4][lane32][hi/lo]
__device__ uint4 g_fh2[4096];   // W2 fp16 single: [og4][ks16][nq2][lane32]
__device__ uint4 g_fl[4096];    // lin_w bf16 hi/lo: [og8][ks8][lane32][hi/lo]
__device__ uint4 g_fn1[4096];   // nm_w1 bf16 hi/lo
__device__ uint4 g_fn2[4096];   // nm_w2 bf16 hi/lo

// ---------------- k_edge smem layout (bytes) ----------------
#define SB_ROWS 0
#define SB_COLS 256
#define SB_DE   512
#define SB_EMS  768
#define SB_ATT  1024
#define SB_PART 1280
#define SB_B2   2304
#define SB_W3   2816
#define SB_W1C  3328
#define SB_A    4352            // 64 x 528 = 33792 (fp16 h1 tile)
#define SMEM_EDGE 38144

// ---------------- k_xy smem layout ----------------
#define SY_A_HI 0               // 32 x 272 = 8704
#define SY_A_LO 8704
#define SY_B1   17408           // 256 f
#define SY_LB   18432           // 128 f
#define SMEM_Y  18944

// ---------------- k_node smem layout ----------------
#define SN_A_HI 0               // 32 x 272 = 8704
#define SN_A_LO 8704
#define SN_MID  17408           // 32 x 132 f = 16896
#define SN_B1   34304           // 128 f
#define SN_B2   34816
#define SN_G1   35328
#define SN_BB1  35840
#define SN_G2   36352
#define SN_BB2  36864
#define SMEM_N  37376

__device__ __forceinline__ u32 smem_u32(const void* p) {
    u32 a;
    asm("{ .reg .u64 t; cvta.to.shared.u64 t, %1; cvt.u32.u64 %0, t; }" : "=r"(a) : "l"(p));
    return a;
}
// accurate sigmoid (output path): MUFU.EX2 + MUFU.RCP
__device__ __forceinline__ float sigm(float v) {
    return __fdividef(1.0f, 1.0f + __expf(-v));
}
__device__ __forceinline__ float silu_(float v) { return v * sigm(v); }
// fast sigmoid (attenuated paths): single MUFU.TANH
__device__ __forceinline__ float tanhap(float x) {
    float r; asm("tanh.approx.f32 %0, %1;" : "=f"(r) : "f"(x)); return r;
}
__device__ __forceinline__ float sigm_f(float v) { return fmaf(tanhap(v * 0.5f), 0.5f, 0.5f); }
__device__ __forceinline__ float silu_f(float v) { return v * sigm_f(v); }

__device__ __forceinline__ void bsplit(float v, u16& h, u16& l) {
    __nv_bfloat16 hb = __float2bfloat16(v);
    __nv_bfloat16 lb = __float2bfloat16(v - __bfloat162float(hb));
    h = __bfloat16_as_ushort(hb);
    l = __bfloat16_as_ushort(lb);
}
__device__ __forceinline__ void bsplit2(float v0, float v1, u32& hp, u32& lp) {
    asm("cvt.rn.bf16x2.f32 %0, %1, %2;" : "=r"(hp) : "f"(v1), "f"(v0));
    float h0 = __uint_as_float(hp << 16);
    float h1 = __uint_as_float(hp & 0xffff0000u);
    asm("cvt.rn.bf16x2.f32 %0, %1, %2;" : "=r"(lp) : "f"(v1 - h1), "f"(v0 - h0));
}
// fp16 pair pack (v0 in low half)
__device__ __forceinline__ u32 hpack2(float v0, float v1) {
    u32 r;
    asm("cvt.rn.f16x2.f32 %0, %1, %2;" : "=r"(r) : "f"(v1), "f"(v0));
    return r;
}
__device__ __forceinline__ float2 hunpack2(u32 p) {
    return __half22float2(*(const __half2*)&p);
}

// ldmatrix m16k16 (A, row-major, stride S bytes)
template <int S>
__device__ __forceinline__ void ldmA(u32 r[4], u32 base, int row0, int kh) {
    int lane = threadIdx.x & 31;
    int quad = lane >> 3;
    u32 addr = base + (u32)(row0 + (lane & 7) + (quad & 1) * 8) * S +
               (u32)kh * 2 + (u32)(quad >> 1) * 16;
    asm volatile("ldmatrix.sync.aligned.m8n8.x4.shared.b16 {%0,%1,%2,%3}, [%4];"
                 : "=r"(r[0]), "=r"(r[1]), "=r"(r[2]), "=r"(r[3]) : "r"(addr));
}
__device__ __forceinline__ void mma16816(float d[4], const u32 a[4], u32 b0, u32 b1) {
    asm volatile("mma.sync.aligned.m16n8k16.row.col.f32.bf16.bf16.f32 "
                 "{%0,%1,%2,%3}, {%4,%5,%6,%7}, {%8,%9}, {%0,%1,%2,%3};"
                 : "+f"(d[0]), "+f"(d[1]), "+f"(d[2]), "+f"(d[3])
                 : "r"(a[0]), "r"(a[1]), "r"(a[2]), "r"(a[3]), "r"(b0), "r"(b1));
}
__device__ __forceinline__ void mmaf16(float d[4], const u32 a[4], u32 b0, u32 b1) {
    asm volatile("mma.sync.aligned.m16n8k16.row.col.f32.f16.f16.f32 "
                 "{%0,%1,%2,%3}, {%4,%5,%6,%7}, {%8,%9}, {%0,%1,%2,%3};"
                 : "+f"(d[0]), "+f"(d[1]), "+f"(d[2]), "+f"(d[3])
                 : "r"(a[0]), "r"(a[1]), "r"(a[2]), "r"(a[3]), "r"(b0), "r"(b1));
}

// pack a 128x128 K-major fp32 weight into bf16 hi/lo frag pairs
__device__ __forceinline__ void pack128(const float* __restrict__ w, uint4* tab, int j) {
    int lane = j & 31, ks = (j >> 5) & 7, og = (j >> 8) & 7;
    int nb0 = og * 16 + (lane >> 2);
    int kb = ks * 16 + (lane & 3) * 2;
    u32 wh[4], wl[4];
#pragma unroll
    for (int nb = 0; nb < 2; nb++)
#pragma unroll
        for (int r = 0; r < 2; r++) {
            const float* p = &w[(nb0 + nb * 8) * 128 + kb + r * 8];
            u16 h0, l0, h1, l1;
            bsplit(p[0], h0, l0);
            bsplit(p[1], h1, l1);
            wh[nb * 2 + r] = (u32)h0 | ((u32)h1 << 16);
            wl[nb * 2 + r] = (u32)l0 | ((u32)l1 << 16);
        }
    tab[j * 2] = make_uint4(wh[0], wh[1], wh[2], wh[3]);
    tab[j * 2 + 1] = make_uint4(wl[0], wl[1], wl[2], wl[3]);
}

// ---------------------------------------------------------------------------
// k_prep: pack weight fragment tables. grid 72 x 256.
// ---------------------------------------------------------------------------
__global__ void k_prep(const float* __restrict__ w1, const float* __restrict__ w2,
                       const float* __restrict__ lw, const float* __restrict__ nw1,
                       const float* __restrict__ nw2, const void* __restrict__ edges) {
    int idx = blockIdx.x * 256 + threadIdx.x;
    if (idx < 8192) {       // W1 bf16 hi/lo frags [256 out][257 k]
        int lane = idx & 31, nq = (idx >> 5) & 3, ks = (idx >> 7) & 7;
        int side = (idx >> 10) & 1, og = (idx >> 11) & 3;
        int nb0 = og * 64 + nq * 16 + (lane >> 2);
        int kb = side * 128 + ks * 16 + (lane & 3) * 2;
        u32 wh[4], wl[4];
#pragma unroll
        for (int nb = 0; nb < 2; nb++)
#pragma unroll
            for (int r = 0; r < 2; r++) {
                const float* p = &w1[(nb0 + nb * 8) * 257 + kb + r * 8];
                u16 h0, l0, h1, l1;
                bsplit(p[0], h0, l0);
                bsplit(p[1], h1, l1);
                wh[nb * 2 + r] = (u32)h0 | ((u32)h1 << 16);
                wl[nb * 2 + r] = (u32)l0 | ((u32)l1 << 16);
            }
        g_f1[idx * 2] = make_uint4(wh[0], wh[1], wh[2], wh[3]);
        g_f1[idx * 2 + 1] = make_uint4(wl[0], wl[1], wl[2], wl[3]);
    } else if (idx < 12288) {  // W2 fp16 single frags [128 out][256 k]
        int j = idx - 8192;
        int lane = j & 31, nq = (j >> 5) & 1, ks = (j >> 6) & 15, og = (j >> 10) & 3;
        int nb0 = og * 32 + nq * 16 + (lane >> 2);
        int kb = ks * 16 + (lane & 3) * 2;
        u32 wf[4];
#pragma unroll
        for (int nb = 0; nb < 2; nb++)
#pragma unroll
            for (int r = 0; r < 2; r++) {
                const float* p = &w2[(nb0 + nb * 8) * 256 + kb + r * 8];
                wf[nb * 2 + r] = hpack2(p[0], p[1]);
            }
        g_fh2[j] = make_uint4(wf[0], wf[1], wf[2], wf[3]);
    } else if (idx < 14336) {  // lin_w frags
        pack128(lw, g_fl, idx - 12288);
    } else if (idx < 16384) {  // nm_w1 frags
        pack128(nw1, g_fn1, idx - 14336);
    } else {                   // nm_w2 frags
        pack128(nw2, g_fn2, idx - 16384);
    }
    if (idx == 0) {
        const int* e32 = (const int*)edges;
        int nz = 0;
        for (int i = 0; i < 16; i++) nz |= e32[2 * i + 1];
        g_e64 = (nz == 0) ? 1 : 0;
    }
}

__global__ void k_zero4() {
    int i = blockIdx.x * 256 + threadIdx.x;
    if (i < NN * DN / 4)
        *(float4*)&g_out[i * 4] = make_float4(0.f, 0.f, 0.f, 0.f);
}

// ---------------------------------------------------------------------------
// k_xy: fused  x = h@lin_w^T + lin_b ;  ya/yb stored as fp16 pairs.
// 32 nodes/CTA, 2 CTAs/SM.
// ---------------------------------------------------------------------------
__global__ __launch_bounds__(256, 2) void k_xy(const float* __restrict__ h,
                                               const float* __restrict__ lb,
                                               const float* __restrict__ b1) {
    extern __shared__ char smc[];
    u32 smb = smem_u32(smc);
    float* b1s = (float*)(smc + SY_B1);
    float* lbs = (float*)(smc + SY_LB);
    int tid = threadIdx.x, lane = tid & 31, warp = tid >> 5;
    int n0 = blockIdx.x * 32;

    b1s[tid] = b1[tid];
    if (tid < 128) lbs[tid] = lb[tid];
#pragma unroll
    for (int i = 0; i < 4; i++) {
        int el = warp * 4 + i;
        const float4 v = *(const float4*)&h[(size_t)(n0 + el) * DN + lane * 4];
        u32 hp0, lp0, hp1, lp1;
        bsplit2(v.x, v.y, hp0, lp0);
        bsplit2(v.z, v.w, hp1, lp1);
        *(u64*)(smc + SY_A_HI + el * YSTR + lane * 8) = (u64)hp0 | ((u64)hp1 << 32);
        *(u64*)(smc + SY_A_LO + el * YSTR + lane * 8) = (u64)lp0 | ((u64)lp1 << 32);
    }
    __syncthreads();

    // ---- phase 1: x = h@lin_w^T + lin_b ----
    {
        float accl[2][2][4] = {};
#pragma unroll
        for (int ks = 0; ks < 8; ks++) {
            int ka = ks * 16;
            u32 ah[2][4], al_[2][4];
            ldmA<YSTR>(ah[0], smb + SY_A_HI, 0, ka);
            ldmA<YSTR>(ah[1], smb + SY_A_HI, 16, ka);
            ldmA<YSTR>(al_[0], smb + SY_A_LO, 0, ka);
            ldmA<YSTR>(al_[1], smb + SY_A_LO, 16, ka);
            int fbase = ((warp * 8 + ks) * 32 + lane) * 2;
            uint4 fh = g_fl[fbase];
            uint4 fl = g_fl[fbase + 1];
#pragma unroll
            for (int mt = 0; mt < 2; mt++) {
                mma16816(accl[mt][0], ah[mt], fh.x, fh.y);
                mma16816(accl[mt][0], ah[mt], fl.x, fl.y);
                mma16816(accl[mt][0], al_[mt], fh.x, fh.y);
                mma16816(accl[mt][1], ah[mt], fh.z, fh.w);
                mma16816(accl[mt][1], ah[mt], fl.z, fl.w);
                mma16816(accl[mt][1], al_[mt], fh.z, fh.w);
            }
        }
        __syncthreads();
        int r0 = lane >> 2, cb = (lane & 3) * 2;
#pragma unroll
        for (int mt = 0; mt < 2; mt++) {
#pragma unroll
            for (int nb = 0; nb < 2; nb++) {
                int o = warp * 16 + nb * 8 + cb;
                float ba = lbs[o], bb = lbs[o + 1];
                float v0 = accl[mt][nb][0] + ba, v1 = accl[mt][nb][1] + bb;
                float v2 = accl[mt][nb][2] + ba, v3 = accl[mt][nb][3] + bb;
                int nl = mt * 16 + r0;
                *(float2*)&g_x[(size_t)(n0 + nl) * DN + o] = make_float2(v0, v1);
                *(float2*)&g_x[(size_t)(n0 + nl + 8) * DN + o] = make_float2(v2, v3);
                u32 hp, lp;
                bsplit2(v0, v1, hp, lp);
                *(u32*)(smc + SY_A_HI + nl * YSTR + o * 2) = hp;
                *(u32*)(smc + SY_A_LO + nl * YSTR + o * 2) = lp;
                bsplit2(v2, v3, hp, lp);
                *(u32*)(smc + SY_A_HI + (nl + 8) * YSTR + o * 2) = hp;
                *(u32*)(smc + SY_A_LO + (nl + 8) * YSTR + o * 2) = lp;
            }
        }
    }
    __syncthreads();

    // ---- phase 2: ya/yb in two nq-passes, fp16 output ----
    int side = warp >> 2, og1 = warp & 3;
    int r0 = lane >> 2, cb = (lane & 3) * 2;
    u32* dsth = side == 0 ? g_yah : g_ybh;
#pragma unroll
    for (int pass = 0; pass < 2; pass++) {
        float acc[2][4][4] = {};
#pragma unroll
        for (int ks = 0; ks < 8; ks++) {
            int ka = ks * 16;
            u32 ah[2][4], al_[2][4];
            ldmA<YSTR>(ah[0], smb + SY_A_HI, 0, ka);
            ldmA<YSTR>(ah[1], smb + SY_A_HI, 16, ka);
            ldmA<YSTR>(al_[0], smb + SY_A_LO, 0, ka);
            ldmA<YSTR>(al_[1], smb + SY_A_LO, 16, ka);
            int fbase = ((((og1 * 2 + side) * 8 + ks) * 4) * 32 + lane) * 2;
#pragma unroll
            for (int nq = 0; nq < 2; nq++) {
                uint4 fh = g_f1[fbase + (pass * 2 + nq) * 64];
                uint4 fl = g_f1[fbase + (pass * 2 + nq) * 64 + 1];
#pragma unroll
                for (int mt = 0; mt < 2; mt++) {
                    mma16816(acc[mt][nq * 2], ah[mt], fh.x, fh.y);
                    mma16816(acc[mt][nq * 2], ah[mt], fl.x, fl.y);
                    mma16816(acc[mt][nq * 2], al_[mt], fh.x, fh.y);
                    mma16816(acc[mt][nq * 2 + 1], ah[mt], fh.z, fh.w);
                    mma16816(acc[mt][nq * 2 + 1], ah[mt], fl.z, fl.w);
                    mma16816(acc[mt][nq * 2 + 1], al_[mt], fh.z, fh.w);
                }
            }
        }
#pragma unroll
        for (int mt = 0; mt < 2; mt++) {
            int node = n0 + mt * 16 + r0;
#pragma unroll
            for (int nb = 0; nb < 4; nb++) {
                int o = og1 * 64 + (pass * 4 + nb) * 8 + cb;
                float ba = side == 0 ? b1s[o] : 0.0f;
                float bb = side == 0 ? b1s[o + 1] : 0.0f;
                dsth[(size_t)node * 128 + (o >> 1)] =
                    hpack2(acc[mt][nb][0] + ba, acc[mt][nb][1] + bb);
                dsth[(size_t)(node + 8) * 128 + (o >> 1)] =
                    hpack2(acc[mt][nb][2] + ba, acc[mt][nb][3] + bb);
            }
        }
    }
}

// ---------------------------------------------------------------------------
// Fused edge kernel: gather fp16 ya/yb -> silu -> GEMM2 (fp16 mma) -> att
// -> scatter (red.global.v4).  64 edges/CTA, 8 warps = 2 eg x 4 og, 4 CTAs/SM.
// ---------------------------------------------------------------------------
__global__ __launch_bounds__(256, 4) void k_edge(
    const float* __restrict__ dist, const float* __restrict__ emask,
    const float* __restrict__ w1, const float* __restrict__ b2,
    const float* __restrict__ w3, const float* __restrict__ b3,
    const void* __restrict__ edges) {
    extern __shared__ char smc[];
    u32 smb = smem_u32(smc);
    float* smf = (float*)smc;
    int* rows = (int*)(smc + SB_ROWS);
    int* cols = (int*)(smc + SB_COLS);

    int tid = threadIdx.x, lane = tid & 31, warp = tid >> 5;
    int eg = warp & 1, og = warp >> 1;
    int Eb = eg * 32;
    int e0 = blockIdx.x * ET;

    smf[SB_W1C / 4 + tid] = w1[tid * 257 + 256];
    if (tid < 128) {
        smf[SB_B2 / 4 + tid] = b2[tid];
        smf[SB_W3 / 4 + tid] = w3[tid];
    }
    if (tid < 64) {
        int e = e0 + tid;
        if (g_e64) {
            const long long* e64 = (const long long*)edges;
            rows[tid] = (int)e64[e];
            cols[tid] = (int)e64[EE + e];
        } else {
            const int* ei = (const int*)edges;
            rows[tid] = ei[e];
            cols[tid] = ei[EE + e];
        }
        float em = emask[e];
        smf[SB_EMS / 4 + tid] = em;
        smf[SB_DE / 4 + tid] = dist[e] * em;
    }
    __syncthreads();

    // ---- gather fp16 ya[row]+yb[col]+de*w1c -> silu_f -> h1 fp16 tile ----
    {
        float4 wc0 = *(const float4*)(smf + SB_W1C / 4 + lane * 4);
        float4 wc1 = *(const float4*)(smf + SB_W1C / 4 + lane * 4 + 128);
#pragma unroll
        for (int i = 0; i < 8; i++) {
            int el = warp * 8 + i;
            const u32* ya = &g_yah[(size_t)rows[el] * 128];
            const u32* yb = &g_ybh[(size_t)cols[el] * 128];
            float de = smf[SB_DE / 4 + el];
#pragma unroll
            for (int j = 0; j < 2; j++) {
                int yo = lane * 2 + j * 64;
                uint2 pa = *(const uint2*)(ya + yo);
                uint2 pb = *(const uint2*)(yb + yo);
                float2 a0 = hunpack2(pa.x), a1 = hunpack2(pa.y);
                float2 b0 = hunpack2(pb.x), b1_ = hunpack2(pb.y);
                float4 wc = j == 0 ? wc0 : wc1;
                float v0 = silu_f(a0.x + b0.x + de * wc.x);
                float v1 = silu_f(a0.y + b0.y + de * wc.y);
                float v2 = silu_f(a1.x + b1_.x + de * wc.z);
                float v3 = silu_f(a1.y + b1_.y + de * wc.w);
                u32 p01 = hpack2(v0, v1);
                u32 p23 = hpack2(v2, v3);
                *(u64*)(smc + SB_A + el * ASTR + (lane * 4 + j * 128) * 2) =
                    (u64)p01 | ((u64)p23 << 32);
            }
        }
    }
    __syncthreads();

    // ---- GEMM2 (fp16): D2[64e x 128o], warp slice 32e x 32o, K=256 ----
    float acc2[2][4][4] = {};
#pragma unroll
    for (int ks = 0; ks < 16; ks++) {
        int ka = ks * 16;
        u32 ah[2][4];
        ldmA<ASTR>(ah[0], smb + SB_A, Eb, ka);
        ldmA<ASTR>(ah[1], smb + SB_A, Eb + 16, ka);
        int fbase = ((og * 16 + ks) * 2) * 32 + lane;
#pragma unroll
        for (int nq = 0; nq < 2; nq++) {
            uint4 f = g_fh2[fbase + nq * 32];
#pragma unroll
            for (int mt = 0; mt < 2; mt++) {
                mmaf16(acc2[mt][nq * 2], ah[mt], f.x, f.y);
                mmaf16(acc2[mt][nq * 2 + 1], ah[mt], f.z, f.w);
            }
        }
    }

    // ---- epilogue2: att partials (silu_f), cross-og combine ----
    {
        int r0 = lane >> 2, cb = (lane & 3) * 2;
        float p[2][2] = {};
#pragma unroll
        for (int mt = 0; mt < 2; mt++)
#pragma unroll
            for (int nb = 0; nb < 4; nb++) {
                int o = og * 32 + nb * 8 + cb;
                float b2a = smf[SB_B2 / 4 + o], b2b = smf[SB_B2 / 4 + o + 1];
                float w3a = smf[SB_W3 / 4 + o], w3b = smf[SB_W3 / 4 + o + 1];
                p[mt][0] += silu_f(acc2[mt][nb][0] + b2a) * w3a + silu_f(acc2[mt][nb][1] + b2b) * w3b;
                p[mt][1] += silu_f(acc2[mt][nb][2] + b2a) * w3a + silu_f(acc2[mt][nb][3] + b2b) * w3b;
            }
#pragma unroll
        for (int off = 1; off <= 2; off <<= 1)
#pragma unroll
            for (int mt = 0; mt < 2; mt++) {
                p[mt][0] += __shfl_xor_sync(0xffffffffu, p[mt][0], off);
                p[mt][1] += __shfl_xor_sync(0xffffffffu, p[mt][1], off);
            }
        if ((lane & 3) == 0) {
#pragma unroll
            for (int mt = 0; mt < 2; mt++) {
                int e = Eb + mt * 16 + r0;
                smf[SB_PART / 4 + og * 64 + e] = p[mt][0];
                smf[SB_PART / 4 + og * 64 + e + 8] = p[mt][1];
            }
        }
    }
    __syncthreads();
    if (tid < 64) {
        float z = smf[SB_PART / 4 + tid] + smf[SB_PART / 4 + 64 + tid] +
                  smf[SB_PART / 4 + 128 + tid] + smf[SB_PART / 4 + 192 + tid] + b3[0];
        smf[SB_ATT / 4 + tid] = sigm(z) * smf[SB_EMS / 4 + tid];  // accurate sigmoid
    }
    __syncthreads();

    // ---- scatter: g_out[row] += x_col * att ----
#pragma unroll
    for (int i = 0; i < 8; i++) {
        int el = warp * 8 + i;
        float a = smf[SB_ATT / 4 + el];
        const float4 v = *(const float4*)&g_x[(size_t)cols[el] * DN + lane * 4];
        float* dst = &g_out[(size_t)rows[el] * DN + lane * 4];
        asm volatile("red.global.add.v4.f32 [%0], {%1, %2, %3, %4};"
                     :: "l"(dst), "f"(v.x * a), "f"(v.y * a), "f"(v.z * a), "f"(v.w * a)
                     : "memory");
    }
}

// ---------------------------------------------------------------------------
// k_node (mma): node_mlp + residual + final LN + silu.  32 nodes/CTA.
// ---------------------------------------------------------------------------
__global__ __launch_bounds__(256, 3) void k_node(
    const float* __restrict__ b1, const float* __restrict__ g1,
    const float* __restrict__ bb1, const float* __restrict__ b2,
    const float* __restrict__ g2, const float* __restrict__ bb2,
    float* __restrict__ out) {
    extern __shared__ char smc[];
    u32 smb = smem_u32(smc);
    float* mid = (float*)(smc + SN_MID);
    float* b1s = (float*)(smc + SN_B1);
    float* b2s = (float*)(smc + SN_B2);
    float* g1s = (float*)(smc + SN_G1);
    float* bb1s = (float*)(smc + SN_BB1);
    float* g2s = (float*)(smc + SN_G2);
    float* bb2s = (float*)(smc + SN_BB2);
    int tid = threadIdx.x, lane = tid & 31, warp = tid >> 5;
    int n0 = blockIdx.x * 32;

    if (tid < 128) {
        b1s[tid] = b1[tid]; b2s[tid] = b2[tid];
        g1s[tid] = g1[tid]; bb1s[tid] = bb1[tid];
        g2s[tid] = g2[tid]; bb2s[tid] = bb2[tid];
    }
#pragma unroll
    for (int i = 0; i < 4; i++) {
        int el = warp * 4 + i;
        float4 v = *(const float4*)&g_out[(size_t)(n0 + el) * DN + lane * 4];
        v.x *= 0.01f; v.y *= 0.01f; v.z *= 0.01f; v.w *= 0.01f;
        u32 hp0, lp0, hp1, lp1;
        bsplit2(v.x, v.y, hp0, lp0);
        bsplit2(v.z, v.w, hp1, lp1);
        *(u64*)(smc + SN_A_HI + el * YSTR + lane * 8) = (u64)hp0 | ((u64)hp1 << 32);
        *(u64*)(smc + SN_A_LO + el * YSTR + lane * 8) = (u64)lp0 | ((u64)lp1 << 32);
    }
    __syncthreads();

    int r0 = lane >> 2, cb = (lane & 3) * 2;

    // ---- GEMM1 (nm_w1) ----
    {
        float acc[2][2][4] = {};
#pragma unroll
        for (int ks = 0; ks < 8; ks++) {
            int ka = ks * 16;
            u32 ah[2][4], al_[2][4];
            ldmA<YSTR>(ah[0], smb + SN_A_HI, 0, ka);
            ldmA<YSTR>(ah[1], smb + SN_A_HI, 16, ka);
            ldmA<YSTR>(al_[0], smb + SN_A_LO, 0, ka);
            ldmA<YSTR>(al_[1], smb + SN_A_LO, 16, ka);
            int fbase = ((warp * 8 + ks) * 32 + lane) * 2;
            uint4 fh = g_fn1[fbase];
            uint4 fl = g_fn1[fbase + 1];
#pragma unroll
            for (int mt = 0; mt < 2; mt++) {
                mma16816(acc[mt][0], ah[mt], fh.x, fh.y);
                mma16816(acc[mt][0], ah[mt], fl.x, fl.y);
                mma16816(acc[mt][0], al_[mt], fh.x, fh.y);
                mma16816(acc[mt][1], ah[mt], fh.z, fh.w);
                mma16816(acc[mt][1], ah[mt], fl.z, fl.w);
                mma16816(acc[mt][1], al_[mt], fh.z, fh.w);
            }
        }
#pragma unroll
        for (int mt = 0; mt < 2; mt++)
#pragma unroll
            for (int nb = 0; nb < 2; nb++) {
                int o = warp * 16 + nb * 8 + cb;
                float ba = b1s[o], bb = b1s[o + 1];
                int nl = mt * 16 + r0;
                *(float2*)&mid[nl * 132 + o] = make_float2(acc[mt][nb][0] + ba, acc[mt][nb][1] + bb);
                *(float2*)&mid[(nl + 8) * 132 + o] = make_float2(acc[mt][nb][2] + ba, acc[mt][nb][3] + bb);
            }
    }
    __syncthreads();

    // ---- LN1 + silu_f -> A ----
#pragma unroll
    for (int i = 0; i < 4; i++) {
        int nl = warp * 4 + i;
        float v[4], s1 = 0.f, s2 = 0.f;
#pragma unroll
        for (int j = 0; j < 4; j++) {
            v[j] = mid[nl * 132 + lane + 32 * j];
            s1 += v[j]; s2 += v[j] * v[j];
        }
#pragma unroll
        for (int off = 16; off > 0; off >>= 1) {
            s1 += __shfl_xor_sync(0xffffffffu, s1, off);
            s2 += __shfl_xor_sync(0xffffffffu, s2, off);
        }
        float mean = s1 * (1.0f / 128.0f);
        float var = s2 * (1.0f / 128.0f) - mean * mean;
        float inv = rsqrtf(var + 1e-5f);
#pragma unroll
        for (int j = 0; j < 4; j++) {
            int o = lane + 32 * j;
            float y = silu_f((v[j] - mean) * inv * g1s[o] + bb1s[o]);
            u16 hh, ll;
            bsplit(y, hh, ll);
            *(u16*)(smc + SN_A_HI + nl * YSTR + o * 2) = hh;
            *(u16*)(smc + SN_A_LO + nl * YSTR + o * 2) = ll;
        }
    }
    __syncthreads();

    // ---- GEMM2 (nm_w2) ----
    {
        float acc[2][2][4] = {};
#pragma unroll
        for (int ks = 0; ks < 8; ks++) {
            int ka = ks * 16;
            u32 ah[2][4], al_[2][4];
            ldmA<YSTR>(ah[0], smb + SN_A_HI, 0, ka);
            ldmA<YSTR>(ah[1], smb + SN_A_HI, 16, ka);
            ldmA<YSTR>(al_[0], smb + SN_A_LO, 0, ka);
            ldmA<YSTR>(al_[1], smb + SN_A_LO, 16, ka);
            int fbase = ((warp * 8 + ks) * 32 + lane) * 2;
            uint4 fh = g_fn2[fbase];
            uint4 fl = g_fn2[fbase + 1];
#pragma unroll
            for (int mt = 0; mt < 2; mt++) {
                mma16816(acc[mt][0], ah[mt], fh.x, fh.y);
                mma16816(acc[mt][0], ah[mt], fl.x, fl.y);
                mma16816(acc[mt][0], al_[mt], fh.x, fh.y);
                mma16816(acc[mt][1], ah[mt], fh.z, fh.w);
                mma16816(acc[mt][1], ah[mt], fl.z, fl.w);
                mma16816(acc[mt][1], al_[mt], fh.z, fh.w);
            }
        }
#pragma unroll
        for (int mt = 0; mt < 2; mt++)
#pragma unroll
            for (int nb = 0; nb < 2; nb++) {
                int o = warp * 16 + nb * 8 + cb;
                float ba = b2s[o], bb = b2s[o + 1];
                int nl = mt * 16 + r0;
                *(float2*)&mid[nl * 132 + o] = make_float2(acc[mt][nb][0] + ba, acc[mt][nb][1] + bb);
                *(float2*)&mid[(nl + 8) * 132 + o] = make_float2(acc[mt][nb][2] + ba, acc[mt][nb][3] + bb);
            }
    }
    __syncthreads();

    // ---- + residual, LN2, silu (accurate), store ----
#pragma unroll
    for (int i = 0; i < 4; i++) {
        int nl = warp * 4 + i;
        float v[4], s1 = 0.f, s2 = 0.f;
#pragma unroll
        for (int j = 0; j < 4; j++) {
            int o = lane + 32 * j;
            v[j] = mid[nl * 132 + o] + g_x[(size_t)(n0 + nl) * DN + o];
            s1 += v[j]; s2 += v[j] * v[j];
        }
#pragma unroll
        for (int off = 16; off > 0; off >>= 1) {
            s1 += __shfl_xor_sync(0xffffffffu, s1, off);
            s2 += __shfl_xor_sync(0xffffffffu, s2, off);
        }
        float mean = s1 * (1.0f / 128.0f);
        float var = s2 * (1.0f / 128.0f) - mean * mean;
        float inv = rsqrtf(var + 1e-5f);
#pragma unroll
        for (int j = 0; j < 4; j++) {
            int o = lane + 32 * j;
            float y = (v[j] - mean) * inv * g2s[o] + bb2s[o];
            out[(size_t)(n0 + nl) * DN + o] = silu_(y);
        }
    }
}

// ---------------------------------------------------------------------------
extern "C" void kernel_launch(void* const* d_in, const int* in_sizes, int n_in,
                              void* d_out, int out_size) {
    const float* h = (const float*)d_in[0];
    const float* distances = (const float*)d_in[1];
    const float* edge_mask = (const float*)d_in[3];
    const float* lin_w = (const float*)d_in[4];
    const float* lin_b = (const float*)d_in[5];
    const float* att_w1 = (const float*)d_in[6];
    const float* att_b1 = (const float*)d_in[7];
    const float* att_w2 = (const float*)d_in[8];
    const float* att_b2 = (const float*)d_in[9];
    const float* att_w3 = (const float*)d_in[10];
    const float* att_b3 = (const float*)d_in[11];
    const float* nm_w1 = (const float*)d_in[12];
    const float* nm_b1 = (const float*)d_in[13];
    const float* nm_ln_g = (const float*)d_in[14];
    const float* nm_ln_b = (const float*)d_in[15];
    const float* nm_w2 = (const float*)d_in[16];
    const float* nm_b2 = (const float*)d_in[17];
    const float* ln_g = (const float*)d_in[18];
    const float* ln_b = (const float*)d_in[19];
    const void* edges = d_in[20];

    cudaFuncSetAttribute(k_xy, cudaFuncAttributeMaxDynamicSharedMemorySize, SMEM_Y);
    cudaFuncSetAttribute(k_edge, cudaFuncAttributeMaxDynamicSharedMemorySize, SMEM_EDGE);
    cudaFuncSetAttribute(k_node, cudaFuncAttributeMaxDynamicSharedMemorySize, SMEM_N);

    k_prep<<<72, 256>>>(att_w1, att_w2, lin_w, nm_w1, nm_w2, edges);
    k_zero4<<<(NN * DN / 4 + 255) / 256, 256>>>();
    k_xy<<<625, 256, SMEM_Y>>>(h, lin_b, att_b1);
    k_edge<<<NCTA, 256, SMEM_EDGE>>>(distances, edge_mask, att_w1, att_b2,
                                     att_w3, att_b3, edges);
    k_node<<<625, 256, SMEM_N>>>(nm_b1, nm_ln_g, nm_ln_b,
                                 nm_b2, ln_g, ln_b, (float*)d_out);
}

// round 14
// speedup vs baseline: 15.9050x; 1.0481x over previous
#include <cuda_runtime.h>
#include <cuda_bf16.h>
#include <cuda_fp16.h>

typedef unsigned int u32;
typedef unsigned long long u64;
typedef unsigned short u16;

#define DN 128
#define NN 20000
#define EE 640000
#define ET 64                   // edges per CTA
#define NCTA (EE / ET)          // 10000
#define ASTR 528                // h1 row stride bytes (256 halves + pad)
#define YSTR 272                // x row stride bytes (136 halves)

// ---------------- device globals (no runtime alloc) ----------------
__device__ float g_x[NN * DN];
__device__ float g_out[NN * DN];
__device__ u32 g_yah[NN * 128];    // (x@W1a^T + b1) as fp16 pairs
__device__ u32 g_ybh[NN * 128];    // (x@W1b^T) as fp16 pairs
__device__ int g_e64;
// pre-packed B fragments in per-lane mma order
__device__ uint4 g_fh1[8192];   // W1 fp16 single: [og4][side2][ks8][nq4][lane32]
__device__ uint4 g_fh2[4096];   // W2 fp16 single: [og4][ks16][nq2][lane32]
__device__ uint4 g_fl[4096];    // lin_w bf16 hi/lo: [og8][ks8][lane32][hi/lo]
__device__ uint4 g_fn1[4096];   // nm_w1 bf16 hi/lo
__device__ uint4 g_fn2[4096];   // nm_w2 bf16 hi/lo

// ---------------- k_edge smem layout (bytes) ----------------
#define SB_ROWS 0
#define SB_COLS 256
#define SB_DE   512
#define SB_EMS  768
#define SB_ATT  1024
#define SB_PART 1280
#define SB_B2   2304
#define SB_W3   2816
#define SB_W1C  3328
#define SB_A    4352            // 64 x 528 = 33792 (fp16 h1 tile)
#define SMEM_EDGE 38144

// ---------------- k_xy smem layout ----------------
#define SY_A_HI 0               // 32 x 272 = 8704 (bf16 hi / later fp16 x)
#define SY_A_LO 8704
#define SY_B1   17408           // 256 f
#define SY_LB   18432           // 128 f
#define SMEM_Y  18944

// ---------------- k_node smem layout ----------------
#define SN_A_HI 0               // 32 x 272 = 8704
#define SN_A_LO 8704
#define SN_MID  17408           // 32 x 132 f = 16896
#define SN_B1   34304           // 128 f
#define SN_B2   34816
#define SN_G1   35328
#define SN_BB1  35840
#define SN_G2   36352
#define SN_BB2  36864
#define SMEM_N  37376

__device__ __forceinline__ u32 smem_u32(const void* p) {
    u32 a;
    asm("{ .reg .u64 t; cvta.to.shared.u64 t, %1; cvt.u32.u64 %0, t; }" : "=r"(a) : "l"(p));
    return a;
}
// accurate sigmoid (output path)
__device__ __forceinline__ float sigm(float v) {
    return __fdividef(1.0f, 1.0f + __expf(-v));
}
__device__ __forceinline__ float silu_(float v) { return v * sigm(v); }
// fast fp32 sigmoid (attenuated scalar paths)
__device__ __forceinline__ float tanhap(float x) {
    float r; asm("tanh.approx.f32 %0, %1;" : "=f"(r) : "f"(x)); return r;
}
__device__ __forceinline__ float sigm_f(float v) { return fmaf(tanhap(v * 0.5f), 0.5f, 0.5f); }
__device__ __forceinline__ float silu_f(float v) { return v * sigm_f(v); }

// half2 helpers (attenuated h1 path)
__device__ __forceinline__ u32 hadd2_(u32 a, u32 b) {
    u32 r; asm("add.rn.f16x2 %0, %1, %2;" : "=r"(r) : "r"(a), "r"(b)); return r;
}
__device__ __forceinline__ u32 hfma2_(u32 a, u32 b, u32 c) {
    u32 r; asm("fma.rn.f16x2 %0, %1, %2, %3;" : "=r"(r) : "r"(a), "r"(b), "r"(c)); return r;
}
__device__ __forceinline__ u32 silu_h2(u32 v) {
    const u32 h05 = 0x38003800u;   // half2(0.5, 0.5)
    u32 t, s;
    asm("mul.rn.f16x2 %0, %1, %2;" : "=r"(t) : "r"(v), "r"(h05));
    asm("tanh.approx.f16x2 %0, %1;" : "=r"(t) : "r"(t));
    asm("fma.rn.f16x2 %0, %1, %2, %3;" : "=r"(s) : "r"(t), "r"(h05), "r"(h05));
    asm("mul.rn.f16x2 %0, %1, %2;" : "=r"(s) : "r"(s), "r"(v));
    return s;
}

__device__ __forceinline__ void bsplit(float v, u16& h, u16& l) {
    __nv_bfloat16 hb = __float2bfloat16(v);
    __nv_bfloat16 lb = __float2bfloat16(v - __bfloat162float(hb));
    h = __bfloat16_as_ushort(hb);
    l = __bfloat16_as_ushort(lb);
}
__device__ __forceinline__ void bsplit2(float v0, float v1, u32& hp, u32& lp) {
    asm("cvt.rn.bf16x2.f32 %0, %1, %2;" : "=r"(hp) : "f"(v1), "f"(v0));
    float h0 = __uint_as_float(hp << 16);
    float h1 = __uint_as_float(hp & 0xffff0000u);
    asm("cvt.rn.bf16x2.f32 %0, %1, %2;" : "=r"(lp) : "f"(v1 - h1), "f"(v0 - h0));
}
__device__ __forceinline__ u32 hpack2(float v0, float v1) {
    u32 r;
    asm("cvt.rn.f16x2.f32 %0, %1, %2;" : "=r"(r) : "f"(v1), "f"(v0));
    return r;
}

// ldmatrix m16k16 (A, row-major, stride S bytes)
template <int S>
__device__ __forceinline__ void ldmA(u32 r[4], u32 base, int row0, int kh) {
    int lane = threadIdx.x & 31;
    int quad = lane >> 3;
    u32 addr = base + (u32)(row0 + (lane & 7) + (quad & 1) * 8) * S +
               (u32)kh * 2 + (u32)(quad >> 1) * 16;
    asm volatile("ldmatrix.sync.aligned.m8n8.x4.shared.b16 {%0,%1,%2,%3}, [%4];"
                 : "=r"(r[0]), "=r"(r[1]), "=r"(r[2]), "=r"(r[3]) : "r"(addr));
}
__device__ __forceinline__ void mma16816(float d[4], const u32 a[4], u32 b0, u32 b1) {
    asm volatile("mma.sync.aligned.m16n8k16.row.col.f32.bf16.bf16.f32 "
                 "{%0,%1,%2,%3}, {%4,%5,%6,%7}, {%8,%9}, {%0,%1,%2,%3};"
                 : "+f"(d[0]), "+f"(d[1]), "+f"(d[2]), "+f"(d[3])
                 : "r"(a[0]), "r"(a[1]), "r"(a[2]), "r"(a[3]), "r"(b0), "r"(b1));
}
__device__ __forceinline__ void mmaf16(float d[4], const u32 a[4], u32 b0, u32 b1) {
    asm volatile("mma.sync.aligned.m16n8k16.row.col.f32.f16.f16.f32 "
                 "{%0,%1,%2,%3}, {%4,%5,%6,%7}, {%8,%9}, {%0,%1,%2,%3};"
                 : "+f"(d[0]), "+f"(d[1]), "+f"(d[2]), "+f"(d[3])
                 : "r"(a[0]), "r"(a[1]), "r"(a[2]), "r"(a[3]), "r"(b0), "r"(b1));
}

// pack a 128x128 K-major fp32 weight into bf16 hi/lo frag pairs
__device__ __forceinline__ void pack128(const float* __restrict__ w, uint4* tab, int j) {
    int lane = j & 31, ks = (j >> 5) & 7, og = (j >> 8) & 7;
    int nb0 = og * 16 + (lane >> 2);
    int kb = ks * 16 + (lane & 3) * 2;
    u32 wh[4], wl[4];
#pragma unroll
    for (int nb = 0; nb < 2; nb++)
#pragma unroll
        for (int r = 0; r < 2; r++) {
            const float* p = &w[(nb0 + nb * 8) * 128 + kb + r * 8];
            u16 h0, l0, h1, l1;
            bsplit(p[0], h0, l0);
            bsplit(p[1], h1, l1);
            wh[nb * 2 + r] = (u32)h0 | ((u32)h1 << 16);
            wl[nb * 2 + r] = (u32)l0 | ((u32)l1 << 16);
        }
    tab[j * 2] = make_uint4(wh[0], wh[1], wh[2], wh[3]);
    tab[j * 2 + 1] = make_uint4(wl[0], wl[1], wl[2], wl[3]);
}

// ---------------------------------------------------------------------------
// k_prep: pack weight fragment tables. grid 72 x 256.
// ---------------------------------------------------------------------------
__global__ void k_prep(const float* __restrict__ w1, const float* __restrict__ w2,
                       const float* __restrict__ lw, const float* __restrict__ nw1,
                       const float* __restrict__ nw2, const void* __restrict__ edges) {
    int idx = blockIdx.x * 256 + threadIdx.x;
    if (idx < 8192) {       // W1 fp16 single frags [256 out][257 k]
        int lane = idx & 31, nq = (idx >> 5) & 3, ks = (idx >> 7) & 7;
        int side = (idx >> 10) & 1, og = (idx >> 11) & 3;
        int nb0 = og * 64 + nq * 16 + (lane >> 2);
        int kb = side * 128 + ks * 16 + (lane & 3) * 2;
        u32 wf[4];
#pragma unroll
        for (int nb = 0; nb < 2; nb++)
#pragma unroll
            for (int r = 0; r < 2; r++) {
                const float* p = &w1[(nb0 + nb * 8) * 257 + kb + r * 8];
                wf[nb * 2 + r] = hpack2(p[0], p[1]);
            }
        g_fh1[idx] = make_uint4(wf[0], wf[1], wf[2], wf[3]);
    } else if (idx < 12288) {  // W2 fp16 single frags [128 out][256 k]
        int j = idx - 8192;
        int lane = j & 31, nq = (j >> 5) & 1, ks = (j >> 6) & 15, og = (j >> 10) & 3;
        int nb0 = og * 32 + nq * 16 + (lane >> 2);
        int kb = ks * 16 + (lane & 3) * 2;
        u32 wf[4];
#pragma unroll
        for (int nb = 0; nb < 2; nb++)
#pragma unroll
            for (int r = 0; r < 2; r++) {
                const float* p = &w2[(nb0 + nb * 8) * 256 + kb + r * 8];
                wf[nb * 2 + r] = hpack2(p[0], p[1]);
            }
        g_fh2[j] = make_uint4(wf[0], wf[1], wf[2], wf[3]);
    } else if (idx < 14336) {  // lin_w frags
        pack128(lw, g_fl, idx - 12288);
    } else if (idx < 16384) {  // nm_w1 frags
        pack128(nw1, g_fn1, idx - 14336);
    } else {                   // nm_w2 frags
        pack128(nw2, g_fn2, idx - 16384);
    }
    if (idx == 0) {
        const int* e32 = (const int*)edges;
        int nz = 0;
        for (int i = 0; i < 16; i++) nz |= e32[2 * i + 1];
        g_e64 = (nz == 0) ? 1 : 0;
    }
}

__global__ void k_zero4() {
    int i = blockIdx.x * 256 + threadIdx.x;
    if (i < NN * DN / 4)
        *(float4*)&g_out[i * 4] = make_float4(0.f, 0.f, 0.f, 0.f);
}

// ---------------------------------------------------------------------------
// k_xy: phase1 x = h@lin_w^T + lin_b (bf16 split, output path);
//       phase2 ya/yb = x@W1^T (single fp16 — feeds attenuated att path).
// 32 nodes/CTA, 2 CTAs/SM.
// ---------------------------------------------------------------------------
__global__ __launch_bounds__(256, 2) void k_xy(const float* __restrict__ h,
                                               const float* __restrict__ lb,
                                               const float* __restrict__ b1) {
    extern __shared__ char smc[];
    u32 smb = smem_u32(smc);
    float* b1s = (float*)(smc + SY_B1);
    float* lbs = (float*)(smc + SY_LB);
    int tid = threadIdx.x, lane = tid & 31, warp = tid >> 5;
    int n0 = blockIdx.x * 32;

    b1s[tid] = b1[tid];
    if (tid < 128) lbs[tid] = lb[tid];
#pragma unroll
    for (int i = 0; i < 4; i++) {
        int el = warp * 4 + i;
        const float4 v = *(const float4*)&h[(size_t)(n0 + el) * DN + lane * 4];
        u32 hp0, lp0, hp1, lp1;
        bsplit2(v.x, v.y, hp0, lp0);
        bsplit2(v.z, v.w, hp1, lp1);
        *(u64*)(smc + SY_A_HI + el * YSTR + lane * 8) = (u64)hp0 | ((u64)hp1 << 32);
        *(u64*)(smc + SY_A_LO + el * YSTR + lane * 8) = (u64)lp0 | ((u64)lp1 << 32);
    }
    __syncthreads();

    // ---- phase 1: x = h@lin_w^T + lin_b (bf16 hi/lo split) ----
    {
        float accl[2][2][4] = {};
#pragma unroll
        for (int ks = 0; ks < 8; ks++) {
            int ka = ks * 16;
            u32 ah[2][4], al_[2][4];
            ldmA<YSTR>(ah[0], smb + SY_A_HI, 0, ka);
            ldmA<YSTR>(ah[1], smb + SY_A_HI, 16, ka);
            ldmA<YSTR>(al_[0], smb + SY_A_LO, 0, ka);
            ldmA<YSTR>(al_[1], smb + SY_A_LO, 16, ka);
            int fbase = ((warp * 8 + ks) * 32 + lane) * 2;
            uint4 fh = g_fl[fbase];
            uint4 fl = g_fl[fbase + 1];
#pragma unroll
            for (int mt = 0; mt < 2; mt++) {
                mma16816(accl[mt][0], ah[mt], fh.x, fh.y);
                mma16816(accl[mt][0], ah[mt], fl.x, fl.y);
                mma16816(accl[mt][0], al_[mt], fh.x, fh.y);
                mma16816(accl[mt][1], ah[mt], fh.z, fh.w);
                mma16816(accl[mt][1], ah[mt], fl.z, fl.w);
                mma16816(accl[mt][1], al_[mt], fh.z, fh.w);
            }
        }
        __syncthreads();   // done reading h tile; overlay fp16 x tile
        int r0 = lane >> 2, cb = (lane & 3) * 2;
#pragma unroll
        for (int mt = 0; mt < 2; mt++) {
#pragma unroll
            for (int nb = 0; nb < 2; nb++) {
                int o = warp * 16 + nb * 8 + cb;
                float ba = lbs[o], bb = lbs[o + 1];
                float v0 = accl[mt][nb][0] + ba, v1 = accl[mt][nb][1] + bb;
                float v2 = accl[mt][nb][2] + ba, v3 = accl[mt][nb][3] + bb;
                int nl = mt * 16 + r0;
                *(float2*)&g_x[(size_t)(n0 + nl) * DN + o] = make_float2(v0, v1);
                *(float2*)&g_x[(size_t)(n0 + nl + 8) * DN + o] = make_float2(v2, v3);
                *(u32*)(smc + SY_A_HI + nl * YSTR + o * 2) = hpack2(v0, v1);
                *(u32*)(smc + SY_A_HI + (nl + 8) * YSTR + o * 2) = hpack2(v2, v3);
            }
        }
    }
    __syncthreads();

    // ---- phase 2: ya/yb single fp16 mma ----
    int side = warp >> 2, og1 = warp & 3;
    int r0 = lane >> 2, cb = (lane & 3) * 2;
    u32* dsth = side == 0 ? g_yah : g_ybh;
    float acc[2][8][4] = {};
#pragma unroll
    for (int ks = 0; ks < 8; ks++) {
        int ka = ks * 16;
        u32 ah[2][4];
        ldmA<YSTR>(ah[0], smb + SY_A_HI, 0, ka);
        ldmA<YSTR>(ah[1], smb + SY_A_HI, 16, ka);
        int fbase = (((og1 * 2 + side) * 8 + ks) * 4) * 32 + lane;
#pragma unroll
        for (int nq = 0; nq < 4; nq++) {
            uint4 f = g_fh1[fbase + nq * 32];
#pragma unroll
            for (int mt = 0; mt < 2; mt++) {
                mmaf16(acc[mt][nq * 2], ah[mt], f.x, f.y);
                mmaf16(acc[mt][nq * 2 + 1], ah[mt], f.z, f.w);
            }
        }
    }
#pragma unroll
    for (int mt = 0; mt < 2; mt++) {
        int node = n0 + mt * 16 + r0;
#pragma unroll
        for (int nb = 0; nb < 8; nb++) {
            int o = og1 * 64 + nb * 8 + cb;
            float ba = side == 0 ? b1s[o] : 0.0f;
            float bb = side == 0 ? b1s[o + 1] : 0.0f;
            dsth[(size_t)node * 128 + (o >> 1)] =
                hpack2(acc[mt][nb][0] + ba, acc[mt][nb][1] + bb);
            dsth[(size_t)(node + 8) * 128 + (o >> 1)] =
                hpack2(acc[mt][nb][2] + ba, acc[mt][nb][3] + bb);
        }
    }
}

// ---------------------------------------------------------------------------
// Fused edge kernel: half2 gather+silu -> GEMM2 (fp16 mma) -> att
// -> scatter (red.global.v4).  64 edges/CTA, 8 warps = 2 eg x 4 og, 4 CTAs/SM.
// ---------------------------------------------------------------------------
__global__ __launch_bounds__(256, 4) void k_edge(
    const float* __restrict__ dist, const float* __restrict__ emask,
    const float* __restrict__ w1, const float* __restrict__ b2,
    const float* __restrict__ w3, const float* __restrict__ b3,
    const void* __restrict__ edges) {
    extern __shared__ char smc[];
    u32 smb = smem_u32(smc);
    float* smf = (float*)smc;
    int* rows = (int*)(smc + SB_ROWS);
    int* cols = (int*)(smc + SB_COLS);

    int tid = threadIdx.x, lane = tid & 31, warp = tid >> 5;
    int eg = warp & 1, og = warp >> 1;
    int Eb = eg * 32;
    int e0 = blockIdx.x * ET;

    smf[SB_W1C / 4 + tid] = w1[tid * 257 + 256];
    if (tid < 128) {
        smf[SB_B2 / 4 + tid] = b2[tid];
        smf[SB_W3 / 4 + tid] = w3[tid];
    }
    if (tid < 64) {
        int e = e0 + tid;
        if (g_e64) {
            const long long* e64 = (const long long*)edges;
            rows[tid] = (int)e64[e];
            cols[tid] = (int)e64[EE + e];
        } else {
            const int* ei = (const int*)edges;
            rows[tid] = ei[e];
            cols[tid] = ei[EE + e];
        }
        float em = emask[e];
        smf[SB_EMS / 4 + tid] = em;
        smf[SB_DE / 4 + tid] = dist[e] * em;
    }
    __syncthreads();

    // ---- gather fp16 ya[row]+yb[col]+de*w1c -> silu (all f16x2) ----
    {
        float4 wc0 = *(const float4*)(smf + SB_W1C / 4 + lane * 4);
        float4 wc1 = *(const float4*)(smf + SB_W1C / 4 + lane * 4 + 128);
        u32 wch[4];
        wch[0] = hpack2(wc0.x, wc0.y);
        wch[1] = hpack2(wc0.z, wc0.w);
        wch[2] = hpack2(wc1.x, wc1.y);
        wch[3] = hpack2(wc1.z, wc1.w);
#pragma unroll
        for (int i = 0; i < 8; i++) {
            int el = warp * 8 + i;
            const u32* ya = &g_yah[(size_t)rows[el] * 128];
            const u32* yb = &g_ybh[(size_t)cols[el] * 128];
            u32 de2 = hpack2(smf[SB_DE / 4 + el], smf[SB_DE / 4 + el]);
#pragma unroll
            for (int j = 0; j < 2; j++) {
                int yo = lane * 2 + j * 64;
                uint2 pa = *(const uint2*)(ya + yo);
                uint2 pb = *(const uint2*)(yb + yo);
                u32 s0 = hfma2_(de2, wch[j * 2], hadd2_(pa.x, pb.x));
                u32 s1 = hfma2_(de2, wch[j * 2 + 1], hadd2_(pa.y, pb.y));
                s0 = silu_h2(s0);
                s1 = silu_h2(s1);
                *(u64*)(smc + SB_A + el * ASTR + (lane * 4 + j * 128) * 2) =
                    (u64)s0 | ((u64)s1 << 32);
            }
        }
    }
    __syncthreads();

    // ---- GEMM2 (fp16): D2[64e x 128o], warp slice 32e x 32o, K=256 ----
    float acc2[2][4][4] = {};
#pragma unroll
    for (int ks = 0; ks < 16; ks++) {
        int ka = ks * 16;
        u32 ah[2][4];
        ldmA<ASTR>(ah[0], smb + SB_A, Eb, ka);
        ldmA<ASTR>(ah[1], smb + SB_A, Eb + 16, ka);
        int fbase = ((og * 16 + ks) * 2) * 32 + lane;
#pragma unroll
        for (int nq = 0; nq < 2; nq++) {
            uint4 f = g_fh2[fbase + nq * 32];
#pragma unroll
            for (int mt = 0; mt < 2; mt++) {
                mmaf16(acc2[mt][nq * 2], ah[mt], f.x, f.y);
                mmaf16(acc2[mt][nq * 2 + 1], ah[mt], f.z, f.w);
            }
        }
    }

    // ---- epilogue2: att partials (silu_f), cross-og combine ----
    {
        int r0 = lane >> 2, cb = (lane & 3) * 2;
        float p[2][2] = {};
#pragma unroll
        for (int mt = 0; mt < 2; mt++)
#pragma unroll
            for (int nb = 0; nb < 4; nb++) {
                int o = og * 32 + nb * 8 + cb;
                float b2a = smf[SB_B2 / 4 + o], b2b = smf[SB_B2 / 4 + o + 1];
                float w3a = smf[SB_W3 / 4 + o], w3b = smf[SB_W3 / 4 + o + 1];
                p[mt][0] += silu_f(acc2[mt][nb][0] + b2a) * w3a + silu_f(acc2[mt][nb][1] + b2b) * w3b;
                p[mt][1] += silu_f(acc2[mt][nb][2] + b2a) * w3a + silu_f(acc2[mt][nb][3] + b2b) * w3b;
            }
#pragma unroll
        for (int off = 1; off <= 2; off <<= 1)
#pragma unroll
            for (int mt = 0; mt < 2; mt++) {
                p[mt][0] += __shfl_xor_sync(0xffffffffu, p[mt][0], off);
                p[mt][1] += __shfl_xor_sync(0xffffffffu, p[mt][1], off);
            }
        if ((lane & 3) == 0) {
#pragma unroll
            for (int mt = 0; mt < 2; mt++) {
                int e = Eb + mt * 16 + r0;
                smf[SB_PART / 4 + og * 64 + e] = p[mt][0];
                smf[SB_PART / 4 + og * 64 + e + 8] = p[mt][1];
            }
        }
    }
    __syncthreads();
    if (tid < 64) {
        float z = smf[SB_PART / 4 + tid] + smf[SB_PART / 4 + 64 + tid] +
                  smf[SB_PART / 4 + 128 + tid] + smf[SB_PART / 4 + 192 + tid] + b3[0];
        smf[SB_ATT / 4 + tid] = sigm(z) * smf[SB_EMS / 4 + tid];  // accurate sigmoid
    }
    __syncthreads();

    // ---- scatter: g_out[row] += x_col * att ----
#pragma unroll
    for (int i = 0; i < 8; i++) {
        int el = warp * 8 + i;
        float a = smf[SB_ATT / 4 + el];
        const float4 v = *(const float4*)&g_x[(size_t)cols[el] * DN + lane * 4];
        float* dst = &g_out[(size_t)rows[el] * DN + lane * 4];
        asm volatile("red.global.add.v4.f32 [%0], {%1, %2, %3, %4};"
                     :: "l"(dst), "f"(v.x * a), "f"(v.y * a), "f"(v.z * a), "f"(v.w * a)
                     : "memory");
    }
}

// ---------------------------------------------------------------------------
// k_node (mma, split-bf16 — output path): node_mlp + residual + LN + silu.
// ---------------------------------------------------------------------------
__global__ __launch_bounds__(256, 3) void k_node(
    const float* __restrict__ b1, const float* __restrict__ g1,
    const float* __restrict__ bb1, const float* __restrict__ b2,
    const float* __restrict__ g2, const float* __restrict__ bb2,
    float* __restrict__ out) {
    extern __shared__ char smc[];
    u32 smb = smem_u32(smc);
    float* mid = (float*)(smc + SN_MID);
    float* b1s = (float*)(smc + SN_B1);
    float* b2s = (float*)(smc + SN_B2);
    float* g1s = (float*)(smc + SN_G1);
    float* bb1s = (float*)(smc + SN_BB1);
    float* g2s = (float*)(smc + SN_G2);
    float* bb2s = (float*)(smc + SN_BB2);
    int tid = threadIdx.x, lane = tid & 31, warp = tid >> 5;
    int n0 = blockIdx.x * 32;

    if (tid < 128) {
        b1s[tid] = b1[tid]; b2s[tid] = b2[tid];
        g1s[tid] = g1[tid]; bb1s[tid] = bb1[tid];
        g2s[tid] = g2[tid]; bb2s[tid] = bb2[tid];
    }
#pragma unroll
    for (int i = 0; i < 4; i++) {
        int el = warp * 4 + i;
        float4 v = *(const float4*)&g_out[(size_t)(n0 + el) * DN + lane * 4];
        v.x *= 0.01f; v.y *= 0.01f; v.z *= 0.01f; v.w *= 0.01f;
        u32 hp0, lp0, hp1, lp1;
        bsplit2(v.x, v.y, hp0, lp0);
        bsplit2(v.z, v.w, hp1, lp1);
        *(u64*)(smc + SN_A_HI + el * YSTR + lane * 8) = (u64)hp0 | ((u64)hp1 << 32);
        *(u64*)(smc + SN_A_LO + el * YSTR + lane * 8) = (u64)lp0 | ((u64)lp1 << 32);
    }
    __syncthreads();

    int r0 = lane >> 2, cb = (lane & 3) * 2;

    // ---- GEMM1 (nm_w1) ----
    {
        float acc[2][2][4] = {};
#pragma unroll
        for (int ks = 0; ks < 8; ks++) {
            int ka = ks * 16;
            u32 ah[2][4], al_[2][4];
            ldmA<YSTR>(ah[0], smb + SN_A_HI, 0, ka);
            ldmA<YSTR>(ah[1], smb + SN_A_HI, 16, ka);
            ldmA<YSTR>(al_[0], smb + SN_A_LO, 0, ka);
            ldmA<YSTR>(al_[1], smb + SN_A_LO, 16, ka);
            int fbase = ((warp * 8 + ks) * 32 + lane) * 2;
            uint4 fh = g_fn1[fbase];
            uint4 fl = g_fn1[fbase + 1];
#pragma unroll
            for (int mt = 0; mt < 2; mt++) {
                mma16816(acc[mt][0], ah[mt], fh.x, fh.y);
                mma16816(acc[mt][0], ah[mt], fl.x, fl.y);
                mma16816(acc[mt][0], al_[mt], fh.x, fh.y);
                mma16816(acc[mt][1], ah[mt], fh.z, fh.w);
                mma16816(acc[mt][1], ah[mt], fl.z, fl.w);
                mma16816(acc[mt][1], al_[mt], fh.z, fh.w);
            }
        }
#pragma unroll
        for (int mt = 0; mt < 2; mt++)
#pragma unroll
            for (int nb = 0; nb < 2; nb++) {
                int o = warp * 16 + nb * 8 + cb;
                float ba = b1s[o], bb = b1s[o + 1];
                int nl = mt * 16 + r0;
                *(float2*)&mid[nl * 132 + o] = make_float2(acc[mt][nb][0] + ba, acc[mt][nb][1] + bb);
                *(float2*)&mid[(nl + 8) * 132 + o] = make_float2(acc[mt][nb][2] + ba, acc[mt][nb][3] + bb);
            }
    }
    __syncthreads();

    // ---- LN1 + silu_f -> A ----
#pragma unroll
    for (int i = 0; i < 4; i++) {
        int nl = warp * 4 + i;
        float v[4], s1 = 0.f, s2 = 0.f;
#pragma unroll
        for (int j = 0; j < 4; j++) {
            v[j] = mid[nl * 132 + lane + 32 * j];
            s1 += v[j]; s2 += v[j] * v[j];
        }
#pragma unroll
        for (int off = 16; off > 0; off >>= 1) {
            s1 += __shfl_xor_sync(0xffffffffu, s1, off);
            s2 += __shfl_xor_sync(0xffffffffu, s2, off);
        }
        float mean = s1 * (1.0f / 128.0f);
        float var = s2 * (1.0f / 128.0f) - mean * mean;
        float inv = rsqrtf(var + 1e-5f);
#pragma unroll
        for (int j = 0; j < 4; j++) {
            int o = lane + 32 * j;
            float y = silu_f((v[j] - mean) * inv * g1s[o] + bb1s[o]);
            u16 hh, ll;
            bsplit(y, hh, ll);
            *(u16*)(smc + SN_A_HI + nl * YSTR + o * 2) = hh;
            *(u16*)(smc + SN_A_LO + nl * YSTR + o * 2) = ll;
        }
    }
    __syncthreads();

    // ---- GEMM2 (nm_w2) ----
    {
        float acc[2][2][4] = {};
#pragma unroll
        for (int ks = 0; ks < 8; ks++) {
            int ka = ks * 16;
            u32 ah[2][4], al_[2][4];
            ldmA<YSTR>(ah[0], smb + SN_A_HI, 0, ka);
            ldmA<YSTR>(ah[1], smb + SN_A_HI, 16, ka);
            ldmA<YSTR>(al_[0], smb + SN_A_LO, 0, ka);
            ldmA<YSTR>(al_[1], smb + SN_A_LO, 16, ka);
            int fbase = ((warp * 8 + ks) * 32 + lane) * 2;
            uint4 fh = g_fn2[fbase];
            uint4 fl = g_fn2[fbase + 1];
#pragma unroll
            for (int mt = 0; mt < 2; mt++) {
                mma16816(acc[mt][0], ah[mt], fh.x, fh.y);
                mma16816(acc[mt][0], ah[mt], fl.x, fl.y);
                mma16816(acc[mt][0], al_[mt], fh.x, fh.y);
                mma16816(acc[mt][1], ah[mt], fh.z, fh.w);
                mma16816(acc[mt][1], ah[mt], fl.z, fl.w);
                mma16816(acc[mt][1], al_[mt], fh.z, fh.w);
            }
        }
#pragma unroll
        for (int mt = 0; mt < 2; mt++)
#pragma unroll
            for (int nb = 0; nb < 2; nb++) {
                int o = warp * 16 + nb * 8 + cb;
                float ba = b2s[o], bb = b2s[o + 1];
                int nl = mt * 16 + r0;
                *(float2*)&mid[nl * 132 + o] = make_float2(acc[mt][nb][0] + ba, acc[mt][nb][1] + bb);
                *(float2*)&mid[(nl + 8) * 132 + o] = make_float2(acc[mt][nb][2] + ba, acc[mt][nb][3] + bb);
            }
    }
    __syncthreads();

    // ---- + residual, LN2, silu (accurate), store ----
#pragma unroll
    for (int i = 0; i < 4; i++) {
        int nl = warp * 4 + i;
        float v[4], s1 = 0.f, s2 = 0.f;
#pragma unroll
        for (int j = 0; j < 4; j++) {
            int o = lane + 32 * j;
            v[j] = mid[nl * 132 + o] + g_x[(size_t)(n0 + nl) * DN + o];
            s1 += v[j]; s2 += v[j] * v[j];
        }
#pragma unroll
        for (int off = 16; off > 0; off >>= 1) {
            s1 += __shfl_xor_sync(0xffffffffu, s1, off);
            s2 += __shfl_xor_sync(0xffffffffu, s2, off);
        }
        float mean = s1 * (1.0f / 128.0f);
        float var = s2 * (1.0f / 128.0f) - mean * mean;
        float inv = rsqrtf(var + 1e-5f);
#pragma unroll
        for (int j = 0; j < 4; j++) {
            int o = lane + 32 * j;
            float y = (v[j] - mean) * inv * g2s[o] + bb2s[o];
            out[(size_t)(n0 + nl) * DN + o] = silu_(y);
        }
    }
}

// ---------------------------------------------------------------------------
extern "C" void kernel_launch(void* const* d_in, const int* in_sizes, int n_in,
                              void* d_out, int out_size) {
    const float* h = (const float*)d_in[0];
    const float* distances = (const float*)d_in[1];
    const float* edge_mask = (const float*)d_in[3];
    const float* lin_w = (const float*)d_in[4];
    const float* lin_b = (const float*)d_in[5];
    const float* att_w1 = (const float*)d_in[6];
    const float* att_b1 = (const float*)d_in[7];
    const float* att_w2 = (const float*)d_in[8];
    const float* att_b2 = (const float*)d_in[9];
    const float* att_w3 = (const float*)d_in[10];
    const float* att_b3 = (const float*)d_in[11];
    const float* nm_w1 = (const float*)d_in[12];
    const float* nm_b1 = (const float*)d_in[13];
    const float* nm_ln_g = (const float*)d_in[14];
    const float* nm_ln_b = (const float*)d_in[15];
    const float* nm_w2 = (const float*)d_in[16];
    const float* nm_b2 = (const float*)d_in[17];
    const float* ln_g = (const float*)d_in[18];
    const float* ln_b = (const float*)d_in[19];
    const void* edges = d_in[20];

    cudaFuncSetAttribute(k_xy, cudaFuncAttributeMaxDynamicSharedMemorySize, SMEM_Y);
    cudaFuncSetAttribute(k_edge, cudaFuncAttributeMaxDynamicSharedMemorySize, SMEM_EDGE);
    cudaFuncSetAttribute(k_node, cudaFuncAttributeMaxDynamicSharedMemorySize, SMEM_N);

    k_prep<<<72, 256>>>(att_w1, att_w2, lin_w, nm_w1, nm_w2, edges);
    k_zero4<<<(NN * DN / 4 + 255) / 256, 256>>>();
    k_xy<<<625, 256, SMEM_Y>>>(h, lin_b, att_b1);
    k_edge<<<NCTA, 256, SMEM_EDGE>>>(distances, edge_mask, att_w1, att_b2,
                                     att_w3, att_b3, edges);
    k_node<<<625, 256, SMEM_N>>>(nm_b1, nm_ln_g, nm_ln_b,
                                 nm_b2, ln_g, ln_b, (float*)d_out);
}